// round 1
// baseline (speedup 1.0000x reference)
#include <cuda_runtime.h>
#include <math.h>

#define HID   2048
#define NHEAD 16
#define DH    128
#define HARM  64
#define BATCH 2
#define SEQ   2048
#define NROWS (BATCH*SEQ)   // 4096

// ---------------- device scratch (no allocations allowed) ----------------
__device__ float g_w[4][HID*HARM];        // amp*cos(phase) for q,k,v,o   (2MB)
__device__ float g_res[3][NROWS*HARM];    // resonances q,k,v             (3MB)
__device__ float g_q[NROWS*HID];          // 32MB
__device__ float g_k[NROWS*HID];          // 32MB
__device__ float g_v[NROWS*HID];          // 32MB
__device__ float g_ao[NROWS*HID];         // attention output, (b,s,d)    (32MB)
__device__ float g_reso[NROWS*HARM];      // resonance of attention out   (1MB)

// ---------------- shared tiled GEMM:  C = A @ B^T ----------------
// A: (M x K) row-major, B: (N x K) row-major, C tile (64x64) at (bm,bn), row stride ldc.
// block = 256 threads (16x16), 4x4 microtile, Ktile = 16.
__device__ __forceinline__ void gemm64x64(const float* __restrict__ A,
                                          const float* __restrict__ B,
                                          float* __restrict__ C,
                                          int K, int ldc, int bm, int bn)
{
    __shared__ float As[64][17];
    __shared__ float Bs[64][17];
    const int tid = threadIdx.x;
    const int tx = tid & 15;
    const int ty = tid >> 4;

    float acc[4][4] = {};
    const float* Ab = A + (size_t)bm * 64 * K;
    const float* Bb = B + (size_t)bn * 64 * K;

    for (int kt = 0; kt < K; kt += 16) {
        #pragma unroll
        for (int p = 0; p < 4; p++) {
            int r = (tid >> 4) + p * 16;
            int c = tid & 15;
            As[r][c] = Ab[r * K + kt + c];
            Bs[r][c] = Bb[r * K + kt + c];
        }
        __syncthreads();
        #pragma unroll
        for (int k = 0; k < 16; k++) {
            float a[4], b[4];
            #pragma unroll
            for (int i = 0; i < 4; i++) a[i] = As[ty * 4 + i][k];
            #pragma unroll
            for (int j = 0; j < 4; j++) b[j] = Bs[tx * 4 + j][k];
            #pragma unroll
            for (int i = 0; i < 4; i++)
                #pragma unroll
                for (int j = 0; j < 4; j++)
                    acc[i][j] += a[i] * b[j];
        }
        __syncthreads();
    }

    #pragma unroll
    for (int i = 0; i < 4; i++)
        #pragma unroll
        for (int j = 0; j < 4; j++)
            C[(size_t)(bm * 64 + ty * 4 + i) * ldc + bn * 64 + tx * 4 + j] = acc[i][j];
}

// ---------------- kernels ----------------

// w = amp * cos(phase) for all four projections
__global__ void k_compute_w(const float* __restrict__ pq, const float* __restrict__ aq,
                            const float* __restrict__ pk, const float* __restrict__ ak,
                            const float* __restrict__ pv, const float* __restrict__ av,
                            const float* __restrict__ po, const float* __restrict__ ao)
{
    int i = blockIdx.x * blockDim.x + threadIdx.x;
    if (i < HID * HARM) {
        g_w[0][i] = aq[i] * cosf(pq[i]);
        g_w[1][i] = ak[i] * cosf(pk[i]);
        g_w[2][i] = av[i] * cosf(pv[i]);
        g_w[3][i] = ao[i] * cosf(po[i]);
    }
}

// res_z = X @ basis_z^T    (4096 x 64), grid (64, 1, 3)
__global__ __launch_bounds__(256) void k_resonance(const float* __restrict__ X,
                                                   const float* __restrict__ b0,
                                                   const float* __restrict__ b1,
                                                   const float* __restrict__ b2)
{
    const float* B = (blockIdx.z == 0) ? b0 : (blockIdx.z == 1) ? b1 : b2;
    gemm64x64(X, B, g_res[blockIdx.z], HID, HARM, blockIdx.x, 0);
}

// q/k/v = res_z @ w_z^T    (4096 x 2048), grid (64, 32, 3)
__global__ __launch_bounds__(256) void k_expand_qkv()
{
    int z = blockIdx.z;
    float* C = (z == 0) ? g_q : (z == 1) ? g_k : g_v;
    gemm64x64(g_res[z], g_w[z], C, HARM, HID, blockIdx.x, blockIdx.y);
}

// res_o = AO @ basis_o^T   grid (64, 1, 1)
__global__ __launch_bounds__(256) void k_resonance_o(const float* __restrict__ basis_o)
{
    gemm64x64(g_ao, basis_o, g_reso, HID, HARM, blockIdx.x, 0);
}

// out = res_o @ w_o^T      grid (64, 32, 1)
__global__ __launch_bounds__(256) void k_expand_o(float* __restrict__ out)
{
    gemm64x64(g_reso, g_w[3], out, HARM, HID, blockIdx.x, blockIdx.y);
}

// ---------------- flash attention (fp32, online softmax) ----------------
// grid: (SEQ/64, NHEAD, BATCH), 256 threads (16x16).
// Bq=Bk=64, Dh=128. S fragment 4x4 per thread, O fragment 4x8 per thread.
#define ATTN_SMEM_FLOATS (3 * 64 * 129 + 64 * 65)
#define ATTN_SMEM_BYTES  (ATTN_SMEM_FLOATS * 4)

__global__ __launch_bounds__(256, 1) void k_attn()
{
    extern __shared__ float sm[];
    float* Qs = sm;                 // [64][129]
    float* Ks = Qs + 64 * 129;      // [64][129]
    float* Vs = Ks + 64 * 129;      // [64][129]
    float* Ps = Vs + 64 * 129;      // [64][65]

    const int tid = threadIdx.x;
    const int tx = tid & 15;
    const int ty = tid >> 4;
    const int qt = blockIdx.x;
    const int h  = blockIdx.y;
    const int b  = blockIdx.z;

    const float scale = 0.08838834764831844f;  // 1/sqrt(128)
    const int qrow0 = b * SEQ + qt * 64;

    const float* Qg = g_q + (size_t)qrow0 * HID + h * DH;
    const float* Kg = g_k + (size_t)(b * SEQ) * HID + h * DH;
    const float* Vg = g_v + (size_t)(b * SEQ) * HID + h * DH;

    // Load Q tile (scaled) once
    for (int i = tid; i < 64 * DH; i += 256) {
        int r = i >> 7, c = i & 127;
        Qs[r * 129 + c] = Qg[r * HID + c] * scale;
    }

    float m_i[4], l_i[4], o[4][8];
    #pragma unroll
    for (int i = 0; i < 4; i++) {
        m_i[i] = -1e30f;
        l_i[i] = 0.0f;
        #pragma unroll
        for (int j = 0; j < 8; j++) o[i][j] = 0.0f;
    }

    for (int kt = 0; kt < SEQ / 64; kt++) {
        __syncthreads();  // protect Vs/Ps reads of previous iteration
        for (int i = tid; i < 64 * DH; i += 256) {
            int r = i >> 7, c = i & 127;
            Ks[r * 129 + c] = Kg[(kt * 64 + r) * HID + c];
            Vs[r * 129 + c] = Vg[(kt * 64 + r) * HID + c];
        }
        __syncthreads();

        // ---- S = Q @ K^T (64x64 tile), 4x4 per thread ----
        float acc[4][4] = {};
        const float* q0 = Qs + (ty * 4 + 0) * 129;
        const float* q1 = Qs + (ty * 4 + 1) * 129;
        const float* q2 = Qs + (ty * 4 + 2) * 129;
        const float* q3 = Qs + (ty * 4 + 3) * 129;
        const float* k0 = Ks + (tx * 4 + 0) * 129;
        const float* k1 = Ks + (tx * 4 + 1) * 129;
        const float* k2 = Ks + (tx * 4 + 2) * 129;
        const float* k3 = Ks + (tx * 4 + 3) * 129;
        #pragma unroll 8
        for (int k = 0; k < 128; k++) {
            float a0 = q0[k], a1 = q1[k], a2 = q2[k], a3 = q3[k];
            float b0 = k0[k], b1 = k1[k], b2 = k2[k], b3 = k3[k];
            acc[0][0] += a0 * b0; acc[0][1] += a0 * b1; acc[0][2] += a0 * b2; acc[0][3] += a0 * b3;
            acc[1][0] += a1 * b0; acc[1][1] += a1 * b1; acc[1][2] += a1 * b2; acc[1][3] += a1 * b3;
            acc[2][0] += a2 * b0; acc[2][1] += a2 * b1; acc[2][2] += a2 * b2; acc[2][3] += a2 * b3;
            acc[3][0] += a3 * b0; acc[3][1] += a3 * b1; acc[3][2] += a3 * b2; acc[3][3] += a3 * b3;
        }

        // ---- online softmax over this 64-wide key tile ----
        #pragma unroll
        for (int i = 0; i < 4; i++) {
            float rm = fmaxf(fmaxf(acc[i][0], acc[i][1]), fmaxf(acc[i][2], acc[i][3]));
            rm = fmaxf(rm, __shfl_xor_sync(0xffffffffu, rm, 1));
            rm = fmaxf(rm, __shfl_xor_sync(0xffffffffu, rm, 2));
            rm = fmaxf(rm, __shfl_xor_sync(0xffffffffu, rm, 4));
            rm = fmaxf(rm, __shfl_xor_sync(0xffffffffu, rm, 8));
            float mn   = fmaxf(m_i[i], rm);
            float corr = __expf(m_i[i] - mn);
            m_i[i] = mn;

            float rs = 0.0f;
            #pragma unroll
            for (int j = 0; j < 4; j++) {
                float p = __expf(acc[i][j] - mn);
                Ps[(ty * 4 + i) * 65 + tx * 4 + j] = p;
                rs += p;
            }
            rs += __shfl_xor_sync(0xffffffffu, rs, 1);
            rs += __shfl_xor_sync(0xffffffffu, rs, 2);
            rs += __shfl_xor_sync(0xffffffffu, rs, 4);
            rs += __shfl_xor_sync(0xffffffffu, rs, 8);

            l_i[i] = l_i[i] * corr + rs;
            #pragma unroll
            for (int j = 0; j < 8; j++) o[i][j] *= corr;
        }
        __syncthreads();  // Ps complete before PV

        // ---- O += P @ V (64x128 tile), 4x8 per thread, cols = tx + 16*jj ----
        const float* p0 = Ps + (ty * 4 + 0) * 65;
        const float* p1 = Ps + (ty * 4 + 1) * 65;
        const float* p2 = Ps + (ty * 4 + 2) * 65;
        const float* p3 = Ps + (ty * 4 + 3) * 65;
        #pragma unroll 4
        for (int k = 0; k < 64; k++) {
            float pa = p0[k], pb = p1[k], pc = p2[k], pd = p3[k];
            const float* vrow = Vs + k * 129 + tx;
            #pragma unroll
            for (int jj = 0; jj < 8; jj++) {
                float vv = vrow[16 * jj];
                o[0][jj] += pa * vv;
                o[1][jj] += pb * vv;
                o[2][jj] += pc * vv;
                o[3][jj] += pd * vv;
            }
        }
    }

    // epilogue: normalize and store to (b, s, d) layout
    float* Og = g_ao + (size_t)qrow0 * HID + h * DH;
    #pragma unroll
    for (int i = 0; i < 4; i++) {
        float inv = 1.0f / l_i[i];
        #pragma unroll
        for (int jj = 0; jj < 8; jj++)
            Og[(ty * 4 + i) * HID + tx + 16 * jj] = o[i][jj] * inv;
    }
}

// ---------------- launch ----------------
extern "C" void kernel_launch(void* const* d_in, const int* in_sizes, int n_in,
                              void* d_out, int out_size)
{
    (void)in_sizes; (void)n_in; (void)out_size;
    const float* hs      = (const float*)d_in[0];
    const float* basis_q = (const float*)d_in[1];
    const float* phase_q = (const float*)d_in[2];
    const float* amp_q   = (const float*)d_in[3];
    const float* basis_k = (const float*)d_in[4];
    const float* phase_k = (const float*)d_in[5];
    const float* amp_k   = (const float*)d_in[6];
    const float* basis_v = (const float*)d_in[7];
    const float* phase_v = (const float*)d_in[8];
    const float* amp_v   = (const float*)d_in[9];
    const float* basis_o = (const float*)d_in[10];
    const float* phase_o = (const float*)d_in[11];
    const float* amp_o   = (const float*)d_in[12];
    float* out = (float*)d_out;

    cudaFuncSetAttribute(k_attn, cudaFuncAttributeMaxDynamicSharedMemorySize, ATTN_SMEM_BYTES);

    k_compute_w<<<(HID * HARM + 255) / 256, 256>>>(phase_q, amp_q, phase_k, amp_k,
                                                   phase_v, amp_v, phase_o, amp_o);
    k_resonance<<<dim3(NROWS / 64, 1, 3), 256>>>(hs, basis_q, basis_k, basis_v);
    k_expand_qkv<<<dim3(NROWS / 64, HID / 64, 3), 256>>>();
    k_attn<<<dim3(SEQ / 64, NHEAD, BATCH), 256, ATTN_SMEM_BYTES>>>();
    k_resonance_o<<<dim3(NROWS / 64, 1, 1), 256>>>(basis_o);
    k_expand_o<<<dim3(NROWS / 64, HID / 64, 1), 256>>>(out);
}

// round 2
// speedup vs baseline: 2.0550x; 2.0550x over previous
#include <cuda_runtime.h>
#include <math.h>

#define HID   2048
#define NHEAD 16
#define DH    128
#define HARM  64
#define BATCH 2
#define SEQ   2048
#define NROWS (BATCH*SEQ)   // 4096

typedef unsigned long long ull;

// ---------------- device scratch ----------------
__device__ float g_w[4][HID*HARM];       // amp*cos(phase) q,k,v,o  (2MB)
__device__ float g_res[3][NROWS*HARM];   // resonances q,k,v        (3MB)
__device__ float g_M[NHEAD*HARM*HARM];   // M_h = scale*Wq_h^T Wk_h (256KB), [h][a][c]
__device__ float g_Nt[HARM*NHEAD*HARM];  // Nt[c][h*64+a] = N_h[a][c] (256KB)
__device__ float g_U[NROWS*NHEAD*HARM];  // u = attn @ res_v, layout (b,s,h*64+a) (16MB)
__device__ float g_reso[NROWS*HARM];     // res_o (1MB)

// ---------------- f32x2 helpers ----------------
__device__ __forceinline__ ull ffma2(ull a, ull b, ull c) {
    ull d;
    asm("fma.rn.f32x2 %0, %1, %2, %3;" : "=l"(d) : "l"(a), "l"(b), "l"(c));
    return d;
}
__device__ __forceinline__ ull mul2(ull a, ull b) {
    ull d;
    asm("mul.rn.f32x2 %0, %1, %2;" : "=l"(d) : "l"(a), "l"(b));
    return d;
}
__device__ __forceinline__ ull dup2(float v) {
    ull r;
    asm("mov.b64 %0, {%1, %2};" : "=l"(r) : "f"(v), "f"(v));
    return r;
}
__device__ __forceinline__ float2 unpack2(ull v) {
    float2 f;
    asm("mov.b64 {%0, %1}, %2;" : "=f"(f.x), "=f"(f.y) : "l"(v));
    return f;
}

// ---------------- w = amp * cos(phase) ----------------
__global__ void k_compute_w(const float* __restrict__ pq, const float* __restrict__ aq,
                            const float* __restrict__ pk, const float* __restrict__ ak,
                            const float* __restrict__ pv, const float* __restrict__ av,
                            const float* __restrict__ po, const float* __restrict__ ao)
{
    int i = blockIdx.x * blockDim.x + threadIdx.x;
    if (i < HID * HARM) {
        g_w[0][i] = aq[i] * cosf(pq[i]);
        g_w[1][i] = ak[i] * cosf(pk[i]);
        g_w[2][i] = av[i] * cosf(pv[i]);
        g_w[3][i] = ao[i] * cosf(po[i]);
    }
}

// ---------------- prep: M_h and Nt ----------------
// z=0: g_M[h][a][c] = scale * sum_d wq[h*128+d][a] * wk[h*128+d][c]
// z=1: g_Nt[c][h*64+a] = sum_d wv[h*128+d][a] * basis_o[c][h*128+d]
__global__ __launch_bounds__(256) void k_prep(const float* __restrict__ basis_o)
{
    __shared__ float As[32][65];  // [d][a]
    __shared__ float Bs[32][65];  // [d][c]
    const int h = blockIdx.x;
    const int z = blockIdx.y;
    const int tid = threadIdx.x;
    const int tx = tid & 15;
    const int ty = tid >> 4;

    float acc[4][4] = {};
    for (int dc = 0; dc < 128; dc += 32) {
        __syncthreads();
        if (z == 0) {
            int d = tid >> 3, a0 = (tid & 7) * 8;
            #pragma unroll
            for (int j = 0; j < 8; j++) {
                As[d][a0 + j] = g_w[0][(h * 128 + dc + d) * 64 + a0 + j];
                Bs[d][a0 + j] = g_w[1][(h * 128 + dc + d) * 64 + a0 + j];
            }
        } else {
            int d = tid >> 3, a0 = (tid & 7) * 8;
            #pragma unroll
            for (int j = 0; j < 8; j++)
                As[d][a0 + j] = g_w[2][(h * 128 + dc + d) * 64 + a0 + j];
            int c = tid >> 2, d0 = (tid & 3) * 8;
            #pragma unroll
            for (int j = 0; j < 8; j++)
                Bs[d0 + j][c] = basis_o[c * 2048 + h * 128 + dc + d0 + j];
        }
        __syncthreads();
        #pragma unroll 8
        for (int d = 0; d < 32; d++) {
            float a[4], b[4];
            #pragma unroll
            for (int i = 0; i < 4; i++) a[i] = As[d][ty * 4 + i];
            #pragma unroll
            for (int j = 0; j < 4; j++) b[j] = Bs[d][tx * 4 + j];
            #pragma unroll
            for (int i = 0; i < 4; i++)
                #pragma unroll
                for (int j = 0; j < 4; j++)
                    acc[i][j] += a[i] * b[j];
        }
    }
    const float scale = 0.08838834764831845f;  // 1/sqrt(128)
    if (z == 0) {
        #pragma unroll
        for (int i = 0; i < 4; i++)
            #pragma unroll
            for (int j = 0; j < 4; j++)
                g_M[h * 4096 + (ty * 4 + i) * 64 + tx * 4 + j] = acc[i][j] * scale;
    } else {
        #pragma unroll
        for (int i = 0; i < 4; i++)
            #pragma unroll
            for (int j = 0; j < 4; j++)
                g_Nt[(tx * 4 + j) * 1024 + h * 64 + ty * 4 + i] = acc[i][j];
    }
}

// ---------------- generic f32x2 GEMM: C(128x64 tile) = A @ B^T ----------------
// A: (M x K) row-major lda, B: (N x K) row-major ldb, C row-major ldc.
// 256 threads, 8x4 microtile, Ktile=32.
__device__ __forceinline__ void gemmF2(const float* __restrict__ A,
                                       const float* __restrict__ B,
                                       float* __restrict__ C,
                                       int K, int lda, int ldb, int ldc)
{
    __shared__ float As[128 * 36];
    __shared__ float BsT[32 * 68];
    const int tid = threadIdx.x;
    const int tx = tid & 15;
    const int ty = tid >> 4;
    const float* Ab = A + (size_t)blockIdx.x * 128 * lda;
    const float* Bb = B + (size_t)blockIdx.y * 64 * ldb;

    ull acc[8][2] = {};
    for (int k0 = 0; k0 < K; k0 += 32) {
        __syncthreads();
        {
            int c = (tid & 7) * 4;
            #pragma unroll
            for (int p = 0; p < 4; p++) {
                int r = (tid >> 3) + p * 32;
                *(float4*)&As[r * 36 + c] = *(const float4*)&Ab[(size_t)r * lda + k0 + c];
            }
            int n = tid >> 2, kk0 = (tid & 3) * 8;
            #pragma unroll
            for (int j = 0; j < 8; j++)
                BsT[(kk0 + j) * 68 + n] = Bb[(size_t)n * ldb + k0 + kk0 + j];
        }
        __syncthreads();
        #pragma unroll 4
        for (int kk = 0; kk < 32; kk++) {
            float a[8];
            #pragma unroll
            for (int i = 0; i < 8; i++) a[i] = As[(ty * 8 + i) * 36 + kk];
            ull b0 = *(const ull*)&BsT[kk * 68 + tx * 4];
            ull b1 = *(const ull*)&BsT[kk * 68 + tx * 4 + 2];
            #pragma unroll
            for (int i = 0; i < 8; i++) {
                ull ad = dup2(a[i]);
                acc[i][0] = ffma2(ad, b0, acc[i][0]);
                acc[i][1] = ffma2(ad, b1, acc[i][1]);
            }
        }
    }
    #pragma unroll
    for (int i = 0; i < 8; i++) {
        float2 v0 = unpack2(acc[i][0]);
        float2 v1 = unpack2(acc[i][1]);
        size_t row = blockIdx.x * 128 + ty * 8 + i;
        *(float2*)&C[row * ldc + blockIdx.y * 64 + tx * 4] = v0;
        *(float2*)&C[row * ldc + blockIdx.y * 64 + tx * 4 + 2] = v1;
    }
}

// wrappers (device symbols can't be passed from host without symbol lookup)
__global__ __launch_bounds__(256) void k_res(const float* __restrict__ X,
                                             const float* __restrict__ b0,
                                             const float* __restrict__ b1,
                                             const float* __restrict__ b2)
{
    const float* B = (blockIdx.z == 0) ? b0 : (blockIdx.z == 1) ? b1 : b2;
    gemmF2(X, B, g_res[blockIdx.z], HID, HID, HID, HARM);
}
__global__ __launch_bounds__(256) void k_resO()
{
    gemmF2(g_U, g_Nt, g_reso, NHEAD * HARM, NHEAD * HARM, NHEAD * HARM, HARM);
}
__global__ __launch_bounds__(256) void k_out(float* __restrict__ out)
{
    gemmF2(g_reso, g_w[3], out, HARM, HARM, HARM, HID);
}

// ---------------- attention in rank-64 space ----------------
// per (qtile=128 rows, head, batch):
//   T = Rq_tile @ M_h            (128x64)
//   loop k-tiles (64): S = T @ Rk^T ; online softmax ; U += P @ Rv
//   write U/l to g_U (b,s,h*64+a)
#define AT_LD 68
#define ATTN_SMEM_BYTES ((128*AT_LD + 64*AT_LD + 64*AT_LD + 128*AT_LD) * 4)

__global__ __launch_bounds__(256, 2) void k_attn2()
{
    extern __shared__ float sm[];
    float* Ts  = sm;                   // [128][68]  T tile (row x feat)
    float* KsT = Ts + 128 * AT_LD;     // [64][68]   keys feature-major: [a][c]
    float* Vs  = KsT + 64 * AT_LD;     // [64][68]   values: [key][feat]
    float* Ps  = Vs + 64 * AT_LD;      // [128][68]  P (also staging for Rq)

    const int tid = threadIdx.x;
    const int tx = tid & 15;
    const int ty = tid >> 4;
    const int qt = blockIdx.x;
    const int h  = blockIdx.y;
    const int b  = blockIdx.z;
    const int qrow0 = b * SEQ + qt * 128;

    // ---- phase 0: stage Rq into Ps, M_h into KsT, compute T -> Ts ----
    {
        const float* Rq = g_res[0] + (size_t)qrow0 * HARM;
        int a4 = (tid & 15) * 4;
        #pragma unroll
        for (int p = 0; p < 8; p++) {
            int r = (tid >> 4) + p * 16;
            *(float4*)&Ps[r * AT_LD + a4] = *(const float4*)&Rq[r * 64 + a4];
        }
        const float* Mh = g_M + h * 4096;
        #pragma unroll
        for (int p = 0; p < 4; p++) {
            int a = (tid >> 4) + p * 16;
            *(float4*)&KsT[a * AT_LD + a4] = *(const float4*)&Mh[a * 64 + a4];
        }
    }
    __syncthreads();
    {
        ull t2[8][2] = {};
        #pragma unroll 4
        for (int a = 0; a < 64; a++) {
            float av[8];
            #pragma unroll
            for (int i = 0; i < 8; i++) av[i] = Ps[(ty * 8 + i) * AT_LD + a];
            ull b0 = *(const ull*)&KsT[a * AT_LD + tx * 4];
            ull b1 = *(const ull*)&KsT[a * AT_LD + tx * 4 + 2];
            #pragma unroll
            for (int i = 0; i < 8; i++) {
                ull ad = dup2(av[i]);
                t2[i][0] = ffma2(ad, b0, t2[i][0]);
                t2[i][1] = ffma2(ad, b1, t2[i][1]);
            }
        }
        #pragma unroll
        for (int i = 0; i < 8; i++) {
            float2 v0 = unpack2(t2[i][0]);
            float2 v1 = unpack2(t2[i][1]);
            *(float2*)&Ts[(ty * 8 + i) * AT_LD + tx * 4] = v0;
            *(float2*)&Ts[(ty * 8 + i) * AT_LD + tx * 4 + 2] = v1;
        }
    }

    float m_i[8], l_i[8];
    ull u2[8][2] = {};
    #pragma unroll
    for (int i = 0; i < 8; i++) { m_i[i] = -1e30f; l_i[i] = 0.0f; }

    const float* RkB = g_res[1] + (size_t)(b * SEQ) * HARM;
    const float* RvB = g_res[2] + (size_t)(b * SEQ) * HARM;

    for (int kt = 0; kt < SEQ / 64; kt++) {
        __syncthreads();  // everyone done with KsT/Vs/Ps from prior phase
        {
            const float* Rk = RkB + (size_t)(kt * 64) * HARM;
            const float* Rv = RvB + (size_t)(kt * 64) * HARM;
            int f4 = (tid & 15) * 4;
            #pragma unroll
            for (int p = 0; p < 4; p++) {
                int kk = (tid >> 4) + p * 16;
                *(float4*)&Vs[kk * AT_LD + f4] = *(const float4*)&Rv[kk * 64 + f4];
            }
            int kk = tid >> 2, f0 = (tid & 3) * 16;
            #pragma unroll
            for (int t = 0; t < 4; t++) {
                float4 v = *(const float4*)&Rk[kk * 64 + f0 + t * 4];
                KsT[(f0 + t * 4 + 0) * AT_LD + kk] = v.x;
                KsT[(f0 + t * 4 + 1) * AT_LD + kk] = v.y;
                KsT[(f0 + t * 4 + 2) * AT_LD + kk] = v.z;
                KsT[(f0 + t * 4 + 3) * AT_LD + kk] = v.w;
            }
        }
        __syncthreads();

        // ---- S = T @ Rk^T  (128x64), 8x4 per thread ----
        ull s2[8][2] = {};
        #pragma unroll 4
        for (int a = 0; a < 64; a++) {
            float av[8];
            #pragma unroll
            for (int i = 0; i < 8; i++) av[i] = Ts[(ty * 8 + i) * AT_LD + a];
            ull b0 = *(const ull*)&KsT[a * AT_LD + tx * 4];
            ull b1 = *(const ull*)&KsT[a * AT_LD + tx * 4 + 2];
            #pragma unroll
            for (int i = 0; i < 8; i++) {
                ull ad = dup2(av[i]);
                s2[i][0] = ffma2(ad, b0, s2[i][0]);
                s2[i][1] = ffma2(ad, b1, s2[i][1]);
            }
        }

        // ---- online softmax ----
        #pragma unroll
        for (int i = 0; i < 8; i++) {
            float2 p0 = unpack2(s2[i][0]);
            float2 p1 = unpack2(s2[i][1]);
            float rm = fmaxf(fmaxf(p0.x, p0.y), fmaxf(p1.x, p1.y));
            rm = fmaxf(rm, __shfl_xor_sync(0xffffffffu, rm, 1));
            rm = fmaxf(rm, __shfl_xor_sync(0xffffffffu, rm, 2));
            rm = fmaxf(rm, __shfl_xor_sync(0xffffffffu, rm, 4));
            rm = fmaxf(rm, __shfl_xor_sync(0xffffffffu, rm, 8));
            float mn   = fmaxf(m_i[i], rm);
            float corr = __expf(m_i[i] - mn);
            m_i[i] = mn;
            float e0 = __expf(p0.x - mn);
            float e1 = __expf(p0.y - mn);
            float e2 = __expf(p1.x - mn);
            float e3 = __expf(p1.y - mn);
            *(float2*)&Ps[(ty * 8 + i) * AT_LD + tx * 4]     = make_float2(e0, e1);
            *(float2*)&Ps[(ty * 8 + i) * AT_LD + tx * 4 + 2] = make_float2(e2, e3);
            float rs = (e0 + e1) + (e2 + e3);
            rs += __shfl_xor_sync(0xffffffffu, rs, 1);
            rs += __shfl_xor_sync(0xffffffffu, rs, 2);
            rs += __shfl_xor_sync(0xffffffffu, rs, 4);
            rs += __shfl_xor_sync(0xffffffffu, rs, 8);
            l_i[i] = l_i[i] * corr + rs;
            ull c2 = dup2(corr);
            u2[i][0] = mul2(u2[i][0], c2);
            u2[i][1] = mul2(u2[i][1], c2);
        }
        __syncthreads();  // Ps complete before PV

        // ---- U += P @ Rv  (128x64), 8x4 per thread ----
        #pragma unroll 4
        for (int kk = 0; kk < 64; kk++) {
            float pv[8];
            #pragma unroll
            for (int i = 0; i < 8; i++) pv[i] = Ps[(ty * 8 + i) * AT_LD + kk];
            ull v0 = *(const ull*)&Vs[kk * AT_LD + tx * 4];
            ull v1 = *(const ull*)&Vs[kk * AT_LD + tx * 4 + 2];
            #pragma unroll
            for (int i = 0; i < 8; i++) {
                ull pd = dup2(pv[i]);
                u2[i][0] = ffma2(pd, v0, u2[i][0]);
                u2[i][1] = ffma2(pd, v1, u2[i][1]);
            }
        }
    }

    // ---- epilogue: normalize, write U to (b,s,h*64+a) ----
    float* Ug = g_U + (size_t)qrow0 * (NHEAD * HARM) + h * HARM;
    #pragma unroll
    for (int i = 0; i < 8; i++) {
        ull iv = dup2(1.0f / l_i[i]);
        float2 o0 = unpack2(mul2(u2[i][0], iv));
        float2 o1 = unpack2(mul2(u2[i][1], iv));
        size_t row = (size_t)(ty * 8 + i) * (NHEAD * HARM);
        *(float2*)&Ug[row + tx * 4]     = o0;
        *(float2*)&Ug[row + tx * 4 + 2] = o1;
    }
}

// ---------------- launch ----------------
extern "C" void kernel_launch(void* const* d_in, const int* in_sizes, int n_in,
                              void* d_out, int out_size)
{
    (void)in_sizes; (void)n_in; (void)out_size;
    const float* hs      = (const float*)d_in[0];
    const float* basis_q = (const float*)d_in[1];
    const float* phase_q = (const float*)d_in[2];
    const float* amp_q   = (const float*)d_in[3];
    const float* basis_k = (const float*)d_in[4];
    const float* phase_k = (const float*)d_in[5];
    const float* amp_k   = (const float*)d_in[6];
    const float* basis_v = (const float*)d_in[7];
    const float* phase_v = (const float*)d_in[8];
    const float* amp_v   = (const float*)d_in[9];
    const float* basis_o = (const float*)d_in[10];
    const float* phase_o = (const float*)d_in[11];
    const float* amp_o   = (const float*)d_in[12];
    float* out = (float*)d_out;

    cudaFuncSetAttribute(k_attn2, cudaFuncAttributeMaxDynamicSharedMemorySize, ATTN_SMEM_BYTES);

    k_compute_w<<<(HID * HARM + 255) / 256, 256>>>(phase_q, amp_q, phase_k, amp_k,
                                                   phase_v, amp_v, phase_o, amp_o);
    k_prep<<<dim3(NHEAD, 2), 256>>>(basis_o);
    k_res<<<dim3(NROWS / 128, 1, 3), 256>>>(hs, basis_q, basis_k, basis_v);
    k_attn2<<<dim3(SEQ / 128, NHEAD, BATCH), 256, ATTN_SMEM_BYTES>>>();
    k_resO<<<dim3(NROWS / 128, 1), 256>>>();
    k_out<<<dim3(NROWS / 128, HID / 64), 256>>>(out);
}

// round 5
// speedup vs baseline: 2.0701x; 1.0073x over previous
#include <cuda_runtime.h>
#include <math.h>

#define HID   2048
#define NHEAD 16
#define DH    128
#define HARM  64
#define BATCH 2
#define SEQ   2048
#define NROWS (BATCH*SEQ)   // 4096

typedef unsigned long long ull;

// ---------------- device scratch ----------------
__device__ float g_w[4][HID*HARM];         // amp*cos(phase) q,k,v,o (2MB)
__device__ float g_res[3][NROWS*HARM];     // resonances q,k,v (3MB)
__device__ float g_resP[3][2][NROWS*HARM]; // split-K partials (6MB)
__device__ float g_M[NHEAD*HARM*HARM];     // M_h = log2e*scale*Wq_h^T Wk_h
__device__ float g_Nt[HARM*NHEAD*HARM];    // Nt[c][h*64+a] = N_h[a][c]
__device__ float g_U[NROWS*NHEAD*HARM];    // attn@res_v, (b,s,h*64+a) (16MB)
__device__ float g_reso[NROWS*HARM];       // res_o (1MB)
__device__ float g_resoP[4][NROWS*HARM];   // split-K partials (4MB)

// ---------------- f32x2 / misc helpers ----------------
__device__ __forceinline__ ull ffma2(ull a, ull b, ull c) {
    ull d; asm("fma.rn.f32x2 %0, %1, %2, %3;" : "=l"(d) : "l"(a), "l"(b), "l"(c)); return d;
}
__device__ __forceinline__ ull mul2(ull a, ull b) {
    ull d; asm("mul.rn.f32x2 %0, %1, %2;" : "=l"(d) : "l"(a), "l"(b)); return d;
}
__device__ __forceinline__ ull dup2(float v) {
    ull r; asm("mov.b64 %0, {%1, %2};" : "=l"(r) : "f"(v), "f"(v)); return r;
}
__device__ __forceinline__ float2 unpack2(ull v) {
    float2 f; asm("mov.b64 {%0, %1}, %2;" : "=f"(f.x), "=f"(f.y) : "l"(v)); return f;
}
__device__ __forceinline__ float ex2(float x) {
    float y; asm("ex2.approx.ftz.f32 %0, %1;" : "=f"(y) : "f"(x)); return y;
}

// ---------------- w = amp * cos(phase) ----------------
__global__ void k_compute_w(const float* __restrict__ pq, const float* __restrict__ aq,
                            const float* __restrict__ pk, const float* __restrict__ ak,
                            const float* __restrict__ pv, const float* __restrict__ av,
                            const float* __restrict__ po, const float* __restrict__ ao)
{
    int i = blockIdx.x * blockDim.x + threadIdx.x;
    if (i < HID * HARM) {
        g_w[0][i] = aq[i] * cosf(pq[i]);
        g_w[1][i] = ak[i] * cosf(pk[i]);
        g_w[2][i] = av[i] * cosf(pv[i]);
        g_w[3][i] = ao[i] * cosf(po[i]);
    }
}

// ---------------- prep: M_h (log2e folded) and Nt ----------------
__global__ __launch_bounds__(256) void k_prep(const float* __restrict__ basis_o)
{
    __shared__ float As[32][65];
    __shared__ float Bs[32][65];
    const int h = blockIdx.x;
    const int z = blockIdx.y;
    const int tid = threadIdx.x;
    const int tx = tid & 15;
    const int ty = tid >> 4;

    float acc[4][4] = {};
    for (int dc = 0; dc < 128; dc += 32) {
        __syncthreads();
        if (z == 0) {
            int d = tid >> 3, a0 = (tid & 7) * 8;
            #pragma unroll
            for (int j = 0; j < 8; j++) {
                As[d][a0 + j] = g_w[0][(h * 128 + dc + d) * 64 + a0 + j];
                Bs[d][a0 + j] = g_w[1][(h * 128 + dc + d) * 64 + a0 + j];
            }
        } else {
            int d = tid >> 3, a0 = (tid & 7) * 8;
            #pragma unroll
            for (int j = 0; j < 8; j++)
                As[d][a0 + j] = g_w[2][(h * 128 + dc + d) * 64 + a0 + j];
            int c = tid >> 2, d0 = (tid & 3) * 8;
            #pragma unroll
            for (int j = 0; j < 8; j++)
                Bs[d0 + j][c] = basis_o[c * 2048 + h * 128 + dc + d0 + j];
        }
        __syncthreads();
        #pragma unroll 8
        for (int d = 0; d < 32; d++) {
            float a[4], b[4];
            #pragma unroll
            for (int i = 0; i < 4; i++) a[i] = As[d][ty * 4 + i];
            #pragma unroll
            for (int j = 0; j < 4; j++) b[j] = Bs[d][tx * 4 + j];
            #pragma unroll
            for (int i = 0; i < 4; i++)
                #pragma unroll
                for (int j = 0; j < 4; j++)
                    acc[i][j] += a[i] * b[j];
        }
    }
    const float scale = 0.08838834764831845f * 1.4426950408889634f; // /sqrt(128) * log2e
    if (z == 0) {
        #pragma unroll
        for (int i = 0; i < 4; i++)
            #pragma unroll
            for (int j = 0; j < 4; j++)
                g_M[h * 4096 + (ty * 4 + i) * 64 + tx * 4 + j] = acc[i][j] * scale;
    } else {
        #pragma unroll
        for (int i = 0; i < 4; i++)
            #pragma unroll
            for (int j = 0; j < 4; j++)
                g_Nt[(tx * 4 + j) * 1024 + h * 64 + ty * 4 + i] = acc[i][j];
    }
}

// ---------------- 64x64-tile f32x2 GEMM partial: C = A @ B^T over Klen ----------------
__device__ __forceinline__ void gemm64F2(const float* __restrict__ A,
                                         const float* __restrict__ B,
                                         float* __restrict__ C,
                                         int Klen, int lda, int ldb)
{
    __shared__ float As[64 * 36];
    __shared__ float BsT[32 * 68];
    const int tid = threadIdx.x;
    const int tx = tid & 15;
    const int ty = tid >> 4;
    const float* Ab = A + (size_t)blockIdx.x * 64 * lda;

    ull acc[4][2] = {};
    for (int k0 = 0; k0 < Klen; k0 += 32) {
        __syncthreads();
        {
            int c = (tid & 7) * 4;
            int r = tid >> 3;
            *(float4*)&As[r * 36 + c]        = *(const float4*)&Ab[(size_t)r * lda + k0 + c];
            *(float4*)&As[(r + 32) * 36 + c] = *(const float4*)&Ab[(size_t)(r + 32) * lda + k0 + c];
            int n = tid >> 2, kk0 = (tid & 3) * 8;
            #pragma unroll
            for (int j = 0; j < 8; j++)
                BsT[(kk0 + j) * 68 + n] = B[(size_t)n * ldb + k0 + kk0 + j];
        }
        __syncthreads();
        #pragma unroll 4
        for (int kk = 0; kk < 32; kk++) {
            float a[4];
            #pragma unroll
            for (int i = 0; i < 4; i++) a[i] = As[(ty * 4 + i) * 36 + kk];
            ull b0 = *(const ull*)&BsT[kk * 68 + tx * 4];
            ull b1 = *(const ull*)&BsT[kk * 68 + tx * 4 + 2];
            #pragma unroll
            for (int i = 0; i < 4; i++) {
                ull ad = dup2(a[i]);
                acc[i][0] = ffma2(ad, b0, acc[i][0]);
                acc[i][1] = ffma2(ad, b1, acc[i][1]);
            }
        }
    }
    #pragma unroll
    for (int i = 0; i < 4; i++) {
        size_t row = blockIdx.x * 64 + ty * 4 + i;
        *(float2*)&C[row * 64 + tx * 4]     = unpack2(acc[i][0]);
        *(float2*)&C[row * 64 + tx * 4 + 2] = unpack2(acc[i][1]);
    }
}

// resonances: grid (64, 2, 3); split-K halves of K=2048
__global__ __launch_bounds__(256) void k_res_part(const float* __restrict__ X,
                                                  const float* __restrict__ b0,
                                                  const float* __restrict__ b1,
                                                  const float* __restrict__ b2)
{
    const int z = blockIdx.z, ks = blockIdx.y;
    const float* B = (z == 0) ? b0 : (z == 1) ? b1 : b2;
    gemm64F2(X + ks * 1024, B + ks * 1024, g_resP[z][ks], 1024, HID, HID);
}
__global__ void k_res_combine()
{
    int i = blockIdx.x * blockDim.x + threadIdx.x;  // float4 index
    const int N4 = NROWS * HARM / 4;
    if (i < 3 * N4) {
        int z = i / N4, r = i - z * N4;
        float4 a = ((const float4*)g_resP[z][0])[r];
        float4 b = ((const float4*)g_resP[z][1])[r];
        ((float4*)g_res[z])[r] = make_float4(a.x + b.x, a.y + b.y, a.z + b.z, a.w + b.w);
    }
}

// res_o partials: grid (64, 4); K=1024 split 4 ways
__global__ __launch_bounds__(256) void k_resO_part()
{
    const int ks = blockIdx.y;
    gemm64F2(g_U + ks * 256, g_Nt + ks * 256, g_resoP[ks], 256, NHEAD * HARM, NHEAD * HARM);
}
__global__ void k_resO_combine()
{
    int i = blockIdx.x * blockDim.x + threadIdx.x;
    const int N4 = NROWS * HARM / 4;
    if (i < N4) {
        float4 a = ((const float4*)g_resoP[0])[i];
        float4 b = ((const float4*)g_resoP[1])[i];
        float4 c = ((const float4*)g_resoP[2])[i];
        float4 d = ((const float4*)g_resoP[3])[i];
        ((float4*)g_reso)[i] = make_float4(a.x + b.x + c.x + d.x, a.y + b.y + c.y + d.y,
                                           a.z + b.z + c.z + d.z, a.w + b.w + c.w + d.w);
    }
}

// ---------------- 128x64-tile f32x2 GEMM (final output) ----------------
__device__ __forceinline__ void gemmF2(const float* __restrict__ A,
                                       const float* __restrict__ B,
                                       float* __restrict__ C,
                                       int K, int lda, int ldb, int ldc)
{
    __shared__ float As[128 * 36];
    __shared__ float BsT[32 * 68];
    const int tid = threadIdx.x;
    const int tx = tid & 15;
    const int ty = tid >> 4;
    const float* Ab = A + (size_t)blockIdx.x * 128 * lda;
    const float* Bb = B + (size_t)blockIdx.y * 64 * ldb;

    ull acc[8][2] = {};
    for (int k0 = 0; k0 < K; k0 += 32) {
        __syncthreads();
        {
            int c = (tid & 7) * 4;
            #pragma unroll
            for (int p = 0; p < 4; p++) {
                int r = (tid >> 3) + p * 32;
                *(float4*)&As[r * 36 + c] = *(const float4*)&Ab[(size_t)r * lda + k0 + c];
            }
            int n = tid >> 2, kk0 = (tid & 3) * 8;
            #pragma unroll
            for (int j = 0; j < 8; j++)
                BsT[(kk0 + j) * 68 + n] = Bb[(size_t)n * ldb + k0 + kk0 + j];
        }
        __syncthreads();
        #pragma unroll 4
        for (int kk = 0; kk < 32; kk++) {
            float a[8];
            #pragma unroll
            for (int i = 0; i < 8; i++) a[i] = As[(ty * 8 + i) * 36 + kk];
            ull b0 = *(const ull*)&BsT[kk * 68 + tx * 4];
            ull b1 = *(const ull*)&BsT[kk * 68 + tx * 4 + 2];
            #pragma unroll
            for (int i = 0; i < 8; i++) {
                ull ad = dup2(a[i]);
                acc[i][0] = ffma2(ad, b0, acc[i][0]);
                acc[i][1] = ffma2(ad, b1, acc[i][1]);
            }
        }
    }
    #pragma unroll
    for (int i = 0; i < 8; i++) {
        size_t row = blockIdx.x * 128 + ty * 8 + i;
        *(float2*)&C[row * ldc + blockIdx.y * 64 + tx * 4]     = unpack2(acc[i][0]);
        *(float2*)&C[row * ldc + blockIdx.y * 64 + tx * 4 + 2] = unpack2(acc[i][1]);
    }
}

__global__ __launch_bounds__(256) void k_out(float* __restrict__ out)
{
    gemmF2(g_reso, g_w[3], out, HARM, HARM, HARM, HID);
}

// ---------------- attention: rank-64, online softmax (log2 domain) ----------------
// Per tile: S = T@Rk^T (scores already in log2 units); per-row running max m;
// P = 2^(S-m); l per-thread partial rescaled by corr; U rescaled by corr.
// K/V global loads for tile t+1 are issued before the PV GEMM of tile t.
#define AT_LD 68
#define ATTN_SMEM_BYTES ((128*AT_LD + 64*AT_LD + 64*AT_LD + 128*AT_LD) * 4)

__global__ __launch_bounds__(256, 2) void k_attn3()
{
    extern __shared__ float sm[];
    float* Ts  = sm;                   // [128][68] T = Rq@M
    float* KsT = Ts + 128 * AT_LD;     // [64][68]  keys feature-major [a][kk]
    float* Vs  = KsT + 64 * AT_LD;     // [64][68]  values [kk][a]
    float* Ps  = Vs + 64 * AT_LD;      // [128][68] P (also stages Rq in phase 0)

    const int tid = threadIdx.x;
    const int tx = tid & 15;
    const int ty = tid >> 4;
    const int qt = blockIdx.x;
    const int h  = blockIdx.y;
    const int b  = blockIdx.z;
    const int qrow0 = b * SEQ + qt * 128;
    const int a4 = tx * 4;

    // ---- phase 0: stage Rq -> Ps, M_h -> KsT ----
    {
        const float* Rq = g_res[0] + (size_t)qrow0 * HARM;
        #pragma unroll
        for (int p = 0; p < 8; p++) {
            int r = ty + p * 16;
            *(float4*)&Ps[r * AT_LD + a4] = *(const float4*)&Rq[r * 64 + a4];
        }
        const float* Mh = g_M + h * 4096;
        #pragma unroll
        for (int p = 0; p < 4; p++) {
            int a = ty + p * 16;
            *(float4*)&KsT[a * AT_LD + a4] = *(const float4*)&Mh[a * 64 + a4];
        }
    }
    __syncthreads();

    const float* RkB = g_res[1] + (size_t)(b * SEQ) * HARM;
    const float* RvB = g_res[2] + (size_t)(b * SEQ) * HARM;
    const int kkL = tid >> 2;            // K staging: row this thread loads
    const int f0  = (tid & 3) * 16;      // feature group

    // prefetch tile 0 while T-GEMM runs
    float4 pk[4], pv[4];
    #pragma unroll
    for (int t = 0; t < 4; t++) pk[t] = *(const float4*)&RkB[kkL * 64 + f0 + t * 4];
    #pragma unroll
    for (int p = 0; p < 4; p++) pv[p] = *(const float4*)&RvB[(ty + p * 16) * 64 + a4];

    // ---- T = Rq @ M_h ----
    {
        ull t2[8][2] = {};
        #pragma unroll 4
        for (int a = 0; a < 64; a++) {
            float av[8];
            #pragma unroll
            for (int i = 0; i < 8; i++) av[i] = Ps[(ty * 8 + i) * AT_LD + a];
            ull b0 = *(const ull*)&KsT[a * AT_LD + tx * 4];
            ull b1 = *(const ull*)&KsT[a * AT_LD + tx * 4 + 2];
            #pragma unroll
            for (int i = 0; i < 8; i++) {
                ull ad = dup2(av[i]);
                t2[i][0] = ffma2(ad, b0, t2[i][0]);
                t2[i][1] = ffma2(ad, b1, t2[i][1]);
            }
        }
        #pragma unroll
        for (int i = 0; i < 8; i++) {
            *(float2*)&Ts[(ty * 8 + i) * AT_LD + tx * 4]     = unpack2(t2[i][0]);
            *(float2*)&Ts[(ty * 8 + i) * AT_LD + tx * 4 + 2] = unpack2(t2[i][1]);
        }
    }

    float m_i[8], l_i[8];
    ull u2[8][2] = {};
    #pragma unroll
    for (int i = 0; i < 8; i++) { m_i[i] = -1e30f; l_i[i] = 0.0f; }

    for (int kt = 0; kt < SEQ / 64; kt++) {
        __syncthreads();  // prior tile's readers of KsT/Vs/Ps (and phase-0 Ts write) done
        // ---- store staged K/V from registers ----
        #pragma unroll
        for (int t = 0; t < 4; t++) {
            KsT[(f0 + t * 4 + 0) * AT_LD + kkL] = pk[t].x;
            KsT[(f0 + t * 4 + 1) * AT_LD + kkL] = pk[t].y;
            KsT[(f0 + t * 4 + 2) * AT_LD + kkL] = pk[t].z;
            KsT[(f0 + t * 4 + 3) * AT_LD + kkL] = pk[t].w;
        }
        #pragma unroll
        for (int p = 0; p < 4; p++)
            *(float4*)&Vs[(ty + p * 16) * AT_LD + a4] = pv[p];
        __syncthreads();

        // ---- S = T @ Rk^T (log2-domain scores) ----
        ull s2[8][2] = {};
        #pragma unroll 4
        for (int a = 0; a < 64; a++) {
            float av[8];
            #pragma unroll
            for (int i = 0; i < 8; i++) av[i] = Ts[(ty * 8 + i) * AT_LD + a];
            ull b0 = *(const ull*)&KsT[a * AT_LD + tx * 4];
            ull b1 = *(const ull*)&KsT[a * AT_LD + tx * 4 + 2];
            #pragma unroll
            for (int i = 0; i < 8; i++) {
                ull ad = dup2(av[i]);
                s2[i][0] = ffma2(ad, b0, s2[i][0]);
                s2[i][1] = ffma2(ad, b1, s2[i][1]);
            }
        }

        // ---- online softmax: row max (shfl), rescale, P = 2^(S-m) ----
        #pragma unroll
        for (int i = 0; i < 8; i++) {
            float2 p0 = unpack2(s2[i][0]);
            float2 p1 = unpack2(s2[i][1]);
            float rm = fmaxf(fmaxf(p0.x, p0.y), fmaxf(p1.x, p1.y));
            rm = fmaxf(rm, __shfl_xor_sync(0xffffffffu, rm, 1));
            rm = fmaxf(rm, __shfl_xor_sync(0xffffffffu, rm, 2));
            rm = fmaxf(rm, __shfl_xor_sync(0xffffffffu, rm, 4));
            rm = fmaxf(rm, __shfl_xor_sync(0xffffffffu, rm, 8));
            float mn   = fmaxf(m_i[i], rm);
            float corr = ex2(m_i[i] - mn);     // 2^(old-new) in [0,1]
            m_i[i] = mn;
            float e0 = ex2(p0.x - mn);
            float e1 = ex2(p0.y - mn);
            float e2 = ex2(p1.x - mn);
            float e3 = ex2(p1.y - mn);
            *(float2*)&Ps[(ty * 8 + i) * AT_LD + tx * 4]     = make_float2(e0, e1);
            *(float2*)&Ps[(ty * 8 + i) * AT_LD + tx * 4 + 2] = make_float2(e2, e3);
            l_i[i] = l_i[i] * corr + ((e0 + e1) + (e2 + e3));  // per-thread partial
            ull c2 = dup2(corr);
            u2[i][0] = mul2(u2[i][0], c2);
            u2[i][1] = mul2(u2[i][1], c2);
        }
        __syncthreads();  // Ps complete before PV

        // ---- prefetch next tile (overlaps PV GEMM) ----
        if (kt + 1 < SEQ / 64) {
            const float* Rk = RkB + (size_t)((kt + 1) * 64) * HARM;
            const float* Rv = RvB + (size_t)((kt + 1) * 64) * HARM;
            #pragma unroll
            for (int t = 0; t < 4; t++) pk[t] = *(const float4*)&Rk[kkL * 64 + f0 + t * 4];
            #pragma unroll
            for (int p = 0; p < 4; p++) pv[p] = *(const float4*)&Rv[(ty + p * 16) * 64 + a4];
        }

        // ---- U += P @ Rv ----
        #pragma unroll 4
        for (int kk = 0; kk < 64; kk++) {
            float pvv[8];
            #pragma unroll
            for (int i = 0; i < 8; i++) pvv[i] = Ps[(ty * 8 + i) * AT_LD + kk];
            ull v0 = *(const ull*)&Vs[kk * AT_LD + tx * 4];
            ull v1 = *(const ull*)&Vs[kk * AT_LD + tx * 4 + 2];
            #pragma unroll
            for (int i = 0; i < 8; i++) {
                ull pd = dup2(pvv[i]);
                u2[i][0] = ffma2(pd, v0, u2[i][0]);
                u2[i][1] = ffma2(pd, v1, u2[i][1]);
            }
        }
    }

    // ---- epilogue: reduce l across 16 lanes, normalize, store ----
    float* Ug = g_U + (size_t)qrow0 * (NHEAD * HARM) + h * HARM;
    #pragma unroll
    for (int i = 0; i < 8; i++) {
        float lv = l_i[i];
        lv += __shfl_xor_sync(0xffffffffu, lv, 1);
        lv += __shfl_xor_sync(0xffffffffu, lv, 2);
        lv += __shfl_xor_sync(0xffffffffu, lv, 4);
        lv += __shfl_xor_sync(0xffffffffu, lv, 8);
        ull iv = dup2(1.0f / lv);
        size_t row = (size_t)(ty * 8 + i) * (NHEAD * HARM);
        *(float2*)&Ug[row + tx * 4]     = unpack2(mul2(u2[i][0], iv));
        *(float2*)&Ug[row + tx * 4 + 2] = unpack2(mul2(u2[i][1], iv));
    }
}

// ---------------- launch ----------------
extern "C" void kernel_launch(void* const* d_in, const int* in_sizes, int n_in,
                              void* d_out, int out_size)
{
    (void)in_sizes; (void)n_in; (void)out_size;
    const float* hs      = (const float*)d_in[0];
    const float* basis_q = (const float*)d_in[1];
    const float* phase_q = (const float*)d_in[2];
    const float* amp_q   = (const float*)d_in[3];
    const float* basis_k = (const float*)d_in[4];
    const float* phase_k = (const float*)d_in[5];
    const float* amp_k   = (const float*)d_in[6];
    const float* basis_v = (const float*)d_in[7];
    const float* phase_v = (const float*)d_in[8];
    const float* amp_v   = (const float*)d_in[9];
    const float* basis_o = (const float*)d_in[10];
    const float* phase_o = (const float*)d_in[11];
    const float* amp_o   = (const float*)d_in[12];
    float* out = (float*)d_out;

    cudaFuncSetAttribute(k_attn3, cudaFuncAttributeMaxDynamicSharedMemorySize, ATTN_SMEM_BYTES);

    k_compute_w<<<(HID * HARM + 255) / 256, 256>>>(phase_q, amp_q, phase_k, amp_k,
                                                   phase_v, amp_v, phase_o, amp_o);
    k_prep<<<dim3(NHEAD, 2), 256>>>(basis_o);
    k_res_part<<<dim3(NROWS / 64, 2, 3), 256>>>(hs, basis_q, basis_k, basis_v);
    k_res_combine<<<(3 * NROWS * HARM / 4 + 255) / 256, 256>>>();
    k_attn3<<<dim3(SEQ / 128, NHEAD, BATCH), 256, ATTN_SMEM_BYTES>>>();
    k_resO_part<<<dim3(NROWS / 64, 4), 256>>>();
    k_resO_combine<<<(NROWS * HARM / 4 + 255) / 256, 256>>>();
    k_out<<<dim3(NROWS / 128, HID / 64), 256>>>(out);
}

// round 6
// speedup vs baseline: 2.2197x; 1.0723x over previous
#include <cuda_runtime.h>
#include <math.h>

#define HID   2048
#define NHEAD 16
#define DH    128
#define HARM  64
#define BATCH 2
#define SEQ   2048
#define NROWS (BATCH*SEQ)   // 4096

typedef unsigned long long ull;

// ---------------- device scratch ----------------
__device__ float g_w[4][HID*HARM];         // amp*cos(phase) q,k,v,o (2MB)
__device__ float g_res[3][NROWS*HARM];     // resonances q,k,v (3MB)
__device__ float g_resP[3][2][NROWS*HARM]; // split-K partials (6MB)
__device__ float g_M[NHEAD*HARM*HARM];     // M_h = log2e*scale*Wq_h^T Wk_h
__device__ float g_Nt[HARM*NHEAD*HARM];    // Nt[c][h*64+a] = N_h[a][c]
__device__ float g_U[NROWS*NHEAD*HARM];    // attn@res_v, (b,s,h*64+a) (16MB)
__device__ float g_reso[NROWS*HARM];       // res_o (1MB)
__device__ float g_resoP[4][NROWS*HARM];   // split-K partials (4MB)

// ---------------- f32x2 / misc helpers ----------------
__device__ __forceinline__ ull ffma2(ull a, ull b, ull c) {
    ull d; asm("fma.rn.f32x2 %0, %1, %2, %3;" : "=l"(d) : "l"(a), "l"(b), "l"(c)); return d;
}
__device__ __forceinline__ ull mul2(ull a, ull b) {
    ull d; asm("mul.rn.f32x2 %0, %1, %2;" : "=l"(d) : "l"(a), "l"(b)); return d;
}
__device__ __forceinline__ ull dup2(float v) {
    ull r; asm("mov.b64 %0, {%1, %2};" : "=l"(r) : "f"(v), "f"(v)); return r;
}
__device__ __forceinline__ float2 unpack2(ull v) {
    float2 f; asm("mov.b64 {%0, %1}, %2;" : "=f"(f.x), "=f"(f.y) : "l"(v)); return f;
}
__device__ __forceinline__ float ex2(float x) {
    float y; asm("ex2.approx.ftz.f32 %0, %1;" : "=f"(y) : "f"(x)); return y;
}

// ---------------- w = amp * cos(phase) ----------------
__global__ void k_compute_w(const float* __restrict__ pq, const float* __restrict__ aq,
                            const float* __restrict__ pk, const float* __restrict__ ak,
                            const float* __restrict__ pv, const float* __restrict__ av,
                            const float* __restrict__ po, const float* __restrict__ ao)
{
    int i = blockIdx.x * blockDim.x + threadIdx.x;
    if (i < HID * HARM) {
        g_w[0][i] = aq[i] * cosf(pq[i]);
        g_w[1][i] = ak[i] * cosf(pk[i]);
        g_w[2][i] = av[i] * cosf(pv[i]);
        g_w[3][i] = ao[i] * cosf(po[i]);
    }
}

// ---------------- prep: M_h (log2e folded) and Nt ----------------
__global__ __launch_bounds__(256) void k_prep(const float* __restrict__ basis_o)
{
    __shared__ float As[32][65];
    __shared__ float Bs[32][65];
    const int h = blockIdx.x;
    const int z = blockIdx.y;
    const int tid = threadIdx.x;
    const int tx = tid & 15;
    const int ty = tid >> 4;

    float acc[4][4] = {};
    for (int dc = 0; dc < 128; dc += 32) {
        __syncthreads();
        if (z == 0) {
            int d = tid >> 3, a0 = (tid & 7) * 8;
            #pragma unroll
            for (int j = 0; j < 8; j++) {
                As[d][a0 + j] = g_w[0][(h * 128 + dc + d) * 64 + a0 + j];
                Bs[d][a0 + j] = g_w[1][(h * 128 + dc + d) * 64 + a0 + j];
            }
        } else {
            int d = tid >> 3, a0 = (tid & 7) * 8;
            #pragma unroll
            for (int j = 0; j < 8; j++)
                As[d][a0 + j] = g_w[2][(h * 128 + dc + d) * 64 + a0 + j];
            int c = tid >> 2, d0 = (tid & 3) * 8;
            #pragma unroll
            for (int j = 0; j < 8; j++)
                Bs[d0 + j][c] = basis_o[c * 2048 + h * 128 + dc + d0 + j];
        }
        __syncthreads();
        #pragma unroll 8
        for (int d = 0; d < 32; d++) {
            float a[4], b[4];
            #pragma unroll
            for (int i = 0; i < 4; i++) a[i] = As[d][ty * 4 + i];
            #pragma unroll
            for (int j = 0; j < 4; j++) b[j] = Bs[d][tx * 4 + j];
            #pragma unroll
            for (int i = 0; i < 4; i++)
                #pragma unroll
                for (int j = 0; j < 4; j++)
                    acc[i][j] += a[i] * b[j];
        }
    }
    const float scale = 0.08838834764831845f * 1.4426950408889634f; // /sqrt(128) * log2e
    if (z == 0) {
        #pragma unroll
        for (int i = 0; i < 4; i++)
            #pragma unroll
            for (int j = 0; j < 4; j++)
                g_M[h * 4096 + (ty * 4 + i) * 64 + tx * 4 + j] = acc[i][j] * scale;
    } else {
        #pragma unroll
        for (int i = 0; i < 4; i++)
            #pragma unroll
            for (int j = 0; j < 4; j++)
                g_Nt[(tx * 4 + j) * 1024 + h * 64 + ty * 4 + i] = acc[i][j];
    }
}

// ---------------- 64x64-tile f32x2 GEMM partial: C = A @ B^T over Klen ----------------
__device__ __forceinline__ void gemm64F2(const float* __restrict__ A,
                                         const float* __restrict__ B,
                                         float* __restrict__ C,
                                         int Klen, int lda, int ldb)
{
    __shared__ float As[64 * 36];
    __shared__ float BsT[32 * 68];
    const int tid = threadIdx.x;
    const int tx = tid & 15;
    const int ty = tid >> 4;
    const float* Ab = A + (size_t)blockIdx.x * 64 * lda;

    ull acc[4][2] = {};
    for (int k0 = 0; k0 < Klen; k0 += 32) {
        __syncthreads();
        {
            int c = (tid & 7) * 4;
            int r = tid >> 3;
            *(float4*)&As[r * 36 + c]        = *(const float4*)&Ab[(size_t)r * lda + k0 + c];
            *(float4*)&As[(r + 32) * 36 + c] = *(const float4*)&Ab[(size_t)(r + 32) * lda + k0 + c];
            int n = tid >> 2, kk0 = (tid & 3) * 8;
            #pragma unroll
            for (int j = 0; j < 8; j++)
                BsT[(kk0 + j) * 68 + n] = B[(size_t)n * ldb + k0 + kk0 + j];
        }
        __syncthreads();
        #pragma unroll 4
        for (int kk = 0; kk < 32; kk++) {
            float a[4];
            #pragma unroll
            for (int i = 0; i < 4; i++) a[i] = As[(ty * 4 + i) * 36 + kk];
            ull b0 = *(const ull*)&BsT[kk * 68 + tx * 4];
            ull b1 = *(const ull*)&BsT[kk * 68 + tx * 4 + 2];
            #pragma unroll
            for (int i = 0; i < 4; i++) {
                ull ad = dup2(a[i]);
                acc[i][0] = ffma2(ad, b0, acc[i][0]);
                acc[i][1] = ffma2(ad, b1, acc[i][1]);
            }
        }
    }
    #pragma unroll
    for (int i = 0; i < 4; i++) {
        size_t row = blockIdx.x * 64 + ty * 4 + i;
        *(float2*)&C[row * 64 + tx * 4]     = unpack2(acc[i][0]);
        *(float2*)&C[row * 64 + tx * 4 + 2] = unpack2(acc[i][1]);
    }
}

// resonances: grid (64, 2, 3); split-K halves of K=2048
__global__ __launch_bounds__(256) void k_res_part(const float* __restrict__ X,
                                                  const float* __restrict__ b0,
                                                  const float* __restrict__ b1,
                                                  const float* __restrict__ b2)
{
    const int z = blockIdx.z, ks = blockIdx.y;
    const float* B = (z == 0) ? b0 : (z == 1) ? b1 : b2;
    gemm64F2(X + ks * 1024, B + ks * 1024, g_resP[z][ks], 1024, HID, HID);
}
__global__ void k_res_combine()
{
    int i = blockIdx.x * blockDim.x + threadIdx.x;  // float4 index
    const int N4 = NROWS * HARM / 4;
    if (i < 3 * N4) {
        int z = i / N4, r = i - z * N4;
        float4 a = ((const float4*)g_resP[z][0])[r];
        float4 b = ((const float4*)g_resP[z][1])[r];
        ((float4*)g_res[z])[r] = make_float4(a.x + b.x, a.y + b.y, a.z + b.z, a.w + b.w);
    }
}

// res_o partials: grid (64, 4); K=1024 split 4 ways
__global__ __launch_bounds__(256) void k_resO_part()
{
    const int ks = blockIdx.y;
    gemm64F2(g_U + ks * 256, g_Nt + ks * 256, g_resoP[ks], 256, NHEAD * HARM, NHEAD * HARM);
}
__global__ void k_resO_combine()
{
    int i = blockIdx.x * blockDim.x + threadIdx.x;
    const int N4 = NROWS * HARM / 4;
    if (i < N4) {
        float4 a = ((const float4*)g_resoP[0])[i];
        float4 b = ((const float4*)g_resoP[1])[i];
        float4 c = ((const float4*)g_resoP[2])[i];
        float4 d = ((const float4*)g_resoP[3])[i];
        ((float4*)g_reso)[i] = make_float4(a.x + b.x + c.x + d.x, a.y + b.y + c.y + d.y,
                                           a.z + b.z + c.z + d.z, a.w + b.w + c.w + d.w);
    }
}

// ---------------- 128x64-tile f32x2 GEMM (final output) ----------------
__device__ __forceinline__ void gemmF2(const float* __restrict__ A,
                                       const float* __restrict__ B,
                                       float* __restrict__ C,
                                       int K, int lda, int ldb, int ldc)
{
    __shared__ float As[128 * 36];
    __shared__ float BsT[32 * 68];
    const int tid = threadIdx.x;
    const int tx = tid & 15;
    const int ty = tid >> 4;
    const float* Ab = A + (size_t)blockIdx.x * 128 * lda;
    const float* Bb = B + (size_t)blockIdx.y * 64 * ldb;

    ull acc[8][2] = {};
    for (int k0 = 0; k0 < K; k0 += 32) {
        __syncthreads();
        {
            int c = (tid & 7) * 4;
            #pragma unroll
            for (int p = 0; p < 4; p++) {
                int r = (tid >> 3) + p * 32;
                *(float4*)&As[r * 36 + c] = *(const float4*)&Ab[(size_t)r * lda + k0 + c];
            }
            int n = tid >> 2, kk0 = (tid & 3) * 8;
            #pragma unroll
            for (int j = 0; j < 8; j++)
                BsT[(kk0 + j) * 68 + n] = Bb[(size_t)n * ldb + k0 + kk0 + j];
        }
        __syncthreads();
        #pragma unroll 4
        for (int kk = 0; kk < 32; kk++) {
            float a[8];
            #pragma unroll
            for (int i = 0; i < 8; i++) a[i] = As[(ty * 8 + i) * 36 + kk];
            ull b0 = *(const ull*)&BsT[kk * 68 + tx * 4];
            ull b1 = *(const ull*)&BsT[kk * 68 + tx * 4 + 2];
            #pragma unroll
            for (int i = 0; i < 8; i++) {
                ull ad = dup2(a[i]);
                acc[i][0] = ffma2(ad, b0, acc[i][0]);
                acc[i][1] = ffma2(ad, b1, acc[i][1]);
            }
        }
    }
    #pragma unroll
    for (int i = 0; i < 8; i++) {
        size_t row = blockIdx.x * 128 + ty * 8 + i;
        *(float2*)&C[row * ldc + blockIdx.y * 64 + tx * 4]     = unpack2(acc[i][0]);
        *(float2*)&C[row * ldc + blockIdx.y * 64 + tx * 4 + 2] = unpack2(acc[i][1]);
    }
}

__global__ __launch_bounds__(256) void k_out(float* __restrict__ out)
{
    gemmF2(g_reso, g_w[3], out, HARM, HARM, HARM, HID);
}

// ---------------- attention: rank-64, online softmax, packed-row S-GEMM ----------------
// smem: TsT[a][row] 64x132 (T transposed: A-operand loads as packed row-pairs),
//       KsT[a][kk]  64x68, Vs[kk][c] 64x68, Ps[row][kk] 128x68.
#define TS_LD 132
#define KS_LD 68
#define VS_LD 68
#define PS_LD 68
#define ATTN_SMEM_FLOATS (64*TS_LD + 64*KS_LD + 64*VS_LD + 128*PS_LD)
#define ATTN_SMEM_BYTES  (ATTN_SMEM_FLOATS * 4)

__global__ __launch_bounds__(256, 2) void k_attn4()
{
    extern __shared__ float sm[];
    float* TsT = sm;                    // [64][132]  T transposed (feature-major)
    float* KsT = TsT + 64 * TS_LD;      // [64][68]   keys feature-major [a][kk] (also M in phase0)
    float* Vs  = KsT + 64 * KS_LD;      // [64][68]   values [kk][c]
    float* Ps  = Vs + 64 * VS_LD;       // [128][68]  P row-major (also RqT staging in phase0)

    const int tid = threadIdx.x;
    const int tx = tid & 15;
    const int ty = tid >> 4;
    const int lane = tid & 31;
    const int wrp = tid >> 5;
    const int qt = blockIdx.x;
    const int h  = blockIdx.y;
    const int b  = blockIdx.z;
    const int qrow0 = b * SEQ + qt * 128;

    // K staging mapping (lane-contiguous kk -> conflict-free STS)
    const int kkL = lane + (wrp & 1) * 32;  // 0..63
    const int f0  = (wrp >> 1) * 16;        // 0,16,32,48

    // ---- phase 0: stage Rq transposed into Ps region, M_h into KsT ----
    {
        const float* Rq = g_res[0] + (size_t)qrow0 * HARM;
        int r = tid >> 1;              // 0..127
        int a0 = (tid & 1) * 32;       // 0 or 32
        #pragma unroll
        for (int t = 0; t < 8; t++) {
            float4 v = *(const float4*)&Rq[r * 64 + a0 + t * 4];
            Ps[(a0 + t * 4 + 0) * TS_LD + r] = v.x;   // reuse TS_LD stride (fits: 64*132 <= 128*68)
            Ps[(a0 + t * 4 + 1) * TS_LD + r] = v.y;
            Ps[(a0 + t * 4 + 2) * TS_LD + r] = v.z;
            Ps[(a0 + t * 4 + 3) * TS_LD + r] = v.w;
        }
        const float* Mh = g_M + h * 4096;
        #pragma unroll
        for (int p = 0; p < 4; p++) {
            int a = ty + p * 16;
            *(float4*)&KsT[a * KS_LD + tx * 4] = *(const float4*)&Mh[a * 64 + tx * 4];
        }
    }
    __syncthreads();

    const float* RkB = g_res[1] + (size_t)(b * SEQ) * HARM;
    const float* RvB = g_res[2] + (size_t)(b * SEQ) * HARM;

    // prefetch K/V tile 0 (overlaps T-GEMM)
    float4 pk[4], pv[4];
    #pragma unroll
    for (int t = 0; t < 4; t++) pk[t] = *(const float4*)&RkB[kkL * 64 + f0 + t * 4];
    #pragma unroll
    for (int p = 0; p < 4; p++) pv[p] = *(const float4*)&RvB[(ty + p * 16) * 64 + tx * 4];

    // ---- T = Rq @ M_h, packed-row accumulators ----
    {
        ull t2[4][4] = {};   // [row-pair p][col j]
        #pragma unroll 8
        for (int a = 0; a < 64; a++) {
            ulonglong2 q01 = *(const ulonglong2*)&Ps[a * TS_LD + ty * 8];
            ulonglong2 q23 = *(const ulonglong2*)&Ps[a * TS_LD + ty * 8 + 4];
            float4 mv = *(const float4*)&KsT[a * KS_LD + tx * 4];
            ull m0 = dup2(mv.x), m1 = dup2(mv.y), m2 = dup2(mv.z), m3 = dup2(mv.w);
            t2[0][0] = ffma2(q01.x, m0, t2[0][0]); t2[0][1] = ffma2(q01.x, m1, t2[0][1]);
            t2[0][2] = ffma2(q01.x, m2, t2[0][2]); t2[0][3] = ffma2(q01.x, m3, t2[0][3]);
            t2[1][0] = ffma2(q01.y, m0, t2[1][0]); t2[1][1] = ffma2(q01.y, m1, t2[1][1]);
            t2[1][2] = ffma2(q01.y, m2, t2[1][2]); t2[1][3] = ffma2(q01.y, m3, t2[1][3]);
            t2[2][0] = ffma2(q23.x, m0, t2[2][0]); t2[2][1] = ffma2(q23.x, m1, t2[2][1]);
            t2[2][2] = ffma2(q23.x, m2, t2[2][2]); t2[2][3] = ffma2(q23.x, m3, t2[2][3]);
            t2[3][0] = ffma2(q23.y, m0, t2[3][0]); t2[3][1] = ffma2(q23.y, m1, t2[3][1]);
            t2[3][2] = ffma2(q23.y, m2, t2[3][2]); t2[3][3] = ffma2(q23.y, m3, t2[3][3]);
        }
        // store T transposed: TsT[col][row], rows contiguous
        #pragma unroll
        for (int j = 0; j < 4; j++) {
            ulonglong2 w0; w0.x = t2[0][j]; w0.y = t2[1][j];
            ulonglong2 w1; w1.x = t2[2][j]; w1.y = t2[3][j];
            *(ulonglong2*)&TsT[(tx * 4 + j) * TS_LD + ty * 8]     = w0;
            *(ulonglong2*)&TsT[(tx * 4 + j) * TS_LD + ty * 8 + 4] = w1;
        }
    }

    float m_i[8], l_i[8];
    ull u2[8][2] = {};   // col-packed: row i, col pairs (tx*4+0,1) and (tx*4+2,3)
    #pragma unroll
    for (int i = 0; i < 8; i++) { m_i[i] = -1e30f; l_i[i] = 0.0f; }

    for (int kt = 0; kt < SEQ / 64; kt++) {
        __syncthreads();  // prior tile readers of KsT/Vs/Ps done (phase0: T reads of KsT/Ps done)
        // ---- stage K (feature-major) and V from prefetch registers ----
        #pragma unroll
        for (int t = 0; t < 4; t++) {
            KsT[(f0 + t * 4 + 0) * KS_LD + kkL] = pk[t].x;
            KsT[(f0 + t * 4 + 1) * KS_LD + kkL] = pk[t].y;
            KsT[(f0 + t * 4 + 2) * KS_LD + kkL] = pk[t].z;
            KsT[(f0 + t * 4 + 3) * KS_LD + kkL] = pk[t].w;
        }
        #pragma unroll
        for (int p = 0; p < 4; p++)
            *(float4*)&Vs[(ty + p * 16) * VS_LD + tx * 4] = pv[p];
        __syncthreads();

        // ---- S = T @ Rk^T, packed-row accumulators ----
        ull s2[4][4] = {};   // [row-pair p][col j]
        #pragma unroll 8
        for (int a = 0; a < 64; a++) {
            ulonglong2 t01 = *(const ulonglong2*)&TsT[a * TS_LD + ty * 8];
            ulonglong2 t23 = *(const ulonglong2*)&TsT[a * TS_LD + ty * 8 + 4];
            float4 kv = *(const float4*)&KsT[a * KS_LD + tx * 4];
            ull k0 = dup2(kv.x), k1 = dup2(kv.y), k2 = dup2(kv.z), k3 = dup2(kv.w);
            s2[0][0] = ffma2(t01.x, k0, s2[0][0]); s2[0][1] = ffma2(t01.x, k1, s2[0][1]);
            s2[0][2] = ffma2(t01.x, k2, s2[0][2]); s2[0][3] = ffma2(t01.x, k3, s2[0][3]);
            s2[1][0] = ffma2(t01.y, k0, s2[1][0]); s2[1][1] = ffma2(t01.y, k1, s2[1][1]);
            s2[1][2] = ffma2(t01.y, k2, s2[1][2]); s2[1][3] = ffma2(t01.y, k3, s2[1][3]);
            s2[2][0] = ffma2(t23.x, k0, s2[2][0]); s2[2][1] = ffma2(t23.x, k1, s2[2][1]);
            s2[2][2] = ffma2(t23.x, k2, s2[2][2]); s2[2][3] = ffma2(t23.x, k3, s2[2][3]);
            s2[3][0] = ffma2(t23.y, k0, s2[3][0]); s2[3][1] = ffma2(t23.y, k1, s2[3][1]);
            s2[3][2] = ffma2(t23.y, k2, s2[3][2]); s2[3][3] = ffma2(t23.y, k3, s2[3][3]);
        }

        // ---- online softmax (log2 domain), P stored row-major float4 ----
        #pragma unroll
        for (int p = 0; p < 4; p++) {
            float2 c0 = unpack2(s2[p][0]);
            float2 c1 = unpack2(s2[p][1]);
            float2 c2 = unpack2(s2[p][2]);
            float2 c3 = unpack2(s2[p][3]);
            #pragma unroll
            for (int hl = 0; hl < 2; hl++) {
                int r = 2 * p + hl;
                float s0 = hl ? c0.y : c0.x;
                float s1 = hl ? c1.y : c1.x;
                float s2v = hl ? c2.y : c2.x;
                float s3 = hl ? c3.y : c3.x;
                float rm = fmaxf(fmaxf(s0, s1), fmaxf(s2v, s3));
                rm = fmaxf(rm, __shfl_xor_sync(0xffffffffu, rm, 1));
                rm = fmaxf(rm, __shfl_xor_sync(0xffffffffu, rm, 2));
                rm = fmaxf(rm, __shfl_xor_sync(0xffffffffu, rm, 4));
                rm = fmaxf(rm, __shfl_xor_sync(0xffffffffu, rm, 8));
                float mn   = fmaxf(m_i[r], rm);
                float corr = ex2(m_i[r] - mn);
                m_i[r] = mn;
                float e0 = ex2(s0 - mn);
                float e1 = ex2(s1 - mn);
                float e2 = ex2(s2v - mn);
                float e3 = ex2(s3 - mn);
                *(float4*)&Ps[(ty * 8 + r) * PS_LD + tx * 4] = make_float4(e0, e1, e2, e3);
                l_i[r] = l_i[r] * corr + ((e0 + e1) + (e2 + e3));
                ull cc = dup2(corr);
                u2[r][0] = mul2(u2[r][0], cc);
                u2[r][1] = mul2(u2[r][1], cc);
            }
        }
        __syncthreads();  // Ps complete before PV

        // ---- prefetch next K/V tile (overlaps PV) ----
        if (kt + 1 < SEQ / 64) {
            const float* Rk = RkB + (size_t)((kt + 1) * 64) * HARM;
            const float* Rv = RvB + (size_t)((kt + 1) * 64) * HARM;
            #pragma unroll
            for (int t = 0; t < 4; t++) pk[t] = *(const float4*)&Rk[kkL * 64 + f0 + t * 4];
            #pragma unroll
            for (int p = 0; p < 4; p++) pv[p] = *(const float4*)&Rv[(ty + p * 16) * 64 + tx * 4];
        }

        // ---- U += P @ Rv (col-packed accumulators) ----
        #pragma unroll 8
        for (int kk = 0; kk < 64; kk++) {
            float pvv[8];
            #pragma unroll
            for (int i = 0; i < 8; i++) pvv[i] = Ps[(ty * 8 + i) * PS_LD + kk];
            ulonglong2 vv = *(const ulonglong2*)&Vs[kk * VS_LD + tx * 4];
            #pragma unroll
            for (int i = 0; i < 8; i++) {
                ull pd = dup2(pvv[i]);
                u2[i][0] = ffma2(pd, vv.x, u2[i][0]);
                u2[i][1] = ffma2(pd, vv.y, u2[i][1]);
            }
        }
    }

    // ---- epilogue: reduce l across 16 lanes, normalize, store ----
    float* Ug = g_U + (size_t)qrow0 * (NHEAD * HARM) + h * HARM;
    #pragma unroll
    for (int i = 0; i < 8; i++) {
        float lv = l_i[i];
        lv += __shfl_xor_sync(0xffffffffu, lv, 1);
        lv += __shfl_xor_sync(0xffffffffu, lv, 2);
        lv += __shfl_xor_sync(0xffffffffu, lv, 4);
        lv += __shfl_xor_sync(0xffffffffu, lv, 8);
        ull iv = dup2(1.0f / lv);
        size_t row = (size_t)(ty * 8 + i) * (NHEAD * HARM);
        *(float2*)&Ug[row + tx * 4]     = unpack2(mul2(u2[i][0], iv));
        *(float2*)&Ug[row + tx * 4 + 2] = unpack2(mul2(u2[i][1], iv));
    }
}

// ---------------- launch ----------------
extern "C" void kernel_launch(void* const* d_in, const int* in_sizes, int n_in,
                              void* d_out, int out_size)
{
    (void)in_sizes; (void)n_in; (void)out_size;
    const float* hs      = (const float*)d_in[0];
    const float* basis_q = (const float*)d_in[1];
    const float* phase_q = (const float*)d_in[2];
    const float* amp_q   = (const float*)d_in[3];
    const float* basis_k = (const float*)d_in[4];
    const float* phase_k = (const float*)d_in[5];
    const float* amp_k   = (const float*)d_in[6];
    const float* basis_v = (const float*)d_in[7];
    const float* phase_v = (const float*)d_in[8];
    const float* amp_v   = (const float*)d_in[9];
    const float* basis_o = (const float*)d_in[10];
    const float* phase_o = (const float*)d_in[11];
    const float* amp_o   = (const float*)d_in[12];
    float* out = (float*)d_out;

    cudaFuncSetAttribute(k_attn4, cudaFuncAttributeMaxDynamicSharedMemorySize, ATTN_SMEM_BYTES);

    k_compute_w<<<(HID * HARM + 255) / 256, 256>>>(phase_q, amp_q, phase_k, amp_k,
                                                   phase_v, amp_v, phase_o, amp_o);
    k_prep<<<dim3(NHEAD, 2), 256>>>(basis_o);
    k_res_part<<<dim3(NROWS / 64, 2, 3), 256>>>(hs, basis_q, basis_k, basis_v);
    k_res_combine<<<(3 * NROWS * HARM / 4 + 255) / 256, 256>>>();
    k_attn4<<<dim3(SEQ / 128, NHEAD, BATCH), 256, ATTN_SMEM_BYTES>>>();
    k_resO_part<<<dim3(NROWS / 64, 4), 256>>>();
    k_resO_combine<<<(NROWS * HARM / 4 + 255) / 256, 256>>>();
    k_out<<<dim3(NROWS / 128, HID / 64), 256>>>(out);
}

// round 7
// speedup vs baseline: 2.3469x; 1.0573x over previous
#include <cuda_runtime.h>
#include <math.h>

#define HID   2048
#define NHEAD 16
#define DH    128
#define HARM  64
#define BATCH 2
#define SEQ   2048
#define NROWS (BATCH*SEQ)   // 4096

typedef unsigned long long ull;

// ---------------- device scratch ----------------
__device__ float g_w[4][HID*HARM];         // amp*cos(phase) q,k,v,o (2MB)
__device__ float g_res[3][NROWS*HARM];     // resonances q,k,v (3MB)
__device__ float g_resP[3][2][NROWS*HARM]; // split-K partials (6MB)
__device__ float g_M[NHEAD*HARM*HARM];     // M_h = log2e*scale*Wq_h^T Wk_h
__device__ float g_Nt[HARM*NHEAD*HARM];    // Nt[c][h*64+a] = N_h[a][c]
__device__ float g_U[NROWS*NHEAD*HARM];    // attn@res_v, (b,s,h*64+a) (16MB)
__device__ float g_reso[NROWS*HARM];       // res_o (1MB)
__device__ float g_resoP[4][NROWS*HARM];   // split-K partials (4MB)

// ---------------- f32x2 / misc helpers ----------------
__device__ __forceinline__ ull ffma2(ull a, ull b, ull c) {
    ull d; asm("fma.rn.f32x2 %0, %1, %2, %3;" : "=l"(d) : "l"(a), "l"(b), "l"(c)); return d;
}
__device__ __forceinline__ ull mul2(ull a, ull b) {
    ull d; asm("mul.rn.f32x2 %0, %1, %2;" : "=l"(d) : "l"(a), "l"(b)); return d;
}
__device__ __forceinline__ ull dup2(float v) {
    ull r; asm("mov.b64 %0, {%1, %2};" : "=l"(r) : "f"(v), "f"(v)); return r;
}
__device__ __forceinline__ float2 unpack2(ull v) {
    float2 f; asm("mov.b64 {%0, %1}, %2;" : "=f"(f.x), "=f"(f.y) : "l"(v)); return f;
}
__device__ __forceinline__ float ex2(float x) {
    float y; asm("ex2.approx.ftz.f32 %0, %1;" : "=f"(y) : "f"(x)); return y;
}

// ---------------- w = amp * cos(phase) ----------------
__global__ void k_compute_w(const float* __restrict__ pq, const float* __restrict__ aq,
                            const float* __restrict__ pk, const float* __restrict__ ak,
                            const float* __restrict__ pv, const float* __restrict__ av,
                            const float* __restrict__ po, const float* __restrict__ ao)
{
    int i = blockIdx.x * blockDim.x + threadIdx.x;
    if (i < HID * HARM) {
        g_w[0][i] = aq[i] * cosf(pq[i]);
        g_w[1][i] = ak[i] * cosf(pk[i]);
        g_w[2][i] = av[i] * cosf(pv[i]);
        g_w[3][i] = ao[i] * cosf(po[i]);
    }
}

// ---------------- prep: M_h (log2e folded) and Nt ----------------
__global__ __launch_bounds__(256) void k_prep(const float* __restrict__ basis_o)
{
    __shared__ float As[32][65];
    __shared__ float Bs[32][65];
    const int h = blockIdx.x;
    const int z = blockIdx.y;
    const int tid = threadIdx.x;
    const int tx = tid & 15;
    const int ty = tid >> 4;

    float acc[4][4] = {};
    for (int dc = 0; dc < 128; dc += 32) {
        __syncthreads();
        if (z == 0) {
            int d = tid >> 3, a0 = (tid & 7) * 8;
            #pragma unroll
            for (int j = 0; j < 8; j++) {
                As[d][a0 + j] = g_w[0][(h * 128 + dc + d) * 64 + a0 + j];
                Bs[d][a0 + j] = g_w[1][(h * 128 + dc + d) * 64 + a0 + j];
            }
        } else {
            int d = tid >> 3, a0 = (tid & 7) * 8;
            #pragma unroll
            for (int j = 0; j < 8; j++)
                As[d][a0 + j] = g_w[2][(h * 128 + dc + d) * 64 + a0 + j];
            int c = tid >> 2, d0 = (tid & 3) * 8;
            #pragma unroll
            for (int j = 0; j < 8; j++)
                Bs[d0 + j][c] = basis_o[c * 2048 + h * 128 + dc + d0 + j];
        }
        __syncthreads();
        #pragma unroll 8
        for (int d = 0; d < 32; d++) {
            float a[4], b[4];
            #pragma unroll
            for (int i = 0; i < 4; i++) a[i] = As[d][ty * 4 + i];
            #pragma unroll
            for (int j = 0; j < 4; j++) b[j] = Bs[d][tx * 4 + j];
            #pragma unroll
            for (int i = 0; i < 4; i++)
                #pragma unroll
                for (int j = 0; j < 4; j++)
                    acc[i][j] += a[i] * b[j];
        }
    }
    const float scale = 0.08838834764831845f * 1.4426950408889634f; // /sqrt(128) * log2e
    if (z == 0) {
        #pragma unroll
        for (int i = 0; i < 4; i++)
            #pragma unroll
            for (int j = 0; j < 4; j++)
                g_M[h * 4096 + (ty * 4 + i) * 64 + tx * 4 + j] = acc[i][j] * scale;
    } else {
        #pragma unroll
        for (int i = 0; i < 4; i++)
            #pragma unroll
            for (int j = 0; j < 4; j++)
                g_Nt[(tx * 4 + j) * 1024 + h * 64 + ty * 4 + i] = acc[i][j];
    }
}

// ---------------- 64x64-tile f32x2 GEMM partial: C = A @ B^T over Klen ----------------
__device__ __forceinline__ void gemm64F2(const float* __restrict__ A,
                                         const float* __restrict__ B,
                                         float* __restrict__ C,
                                         int Klen, int lda, int ldb)
{
    __shared__ float As[64 * 36];
    __shared__ float BsT[32 * 68];
    const int tid = threadIdx.x;
    const int tx = tid & 15;
    const int ty = tid >> 4;
    const float* Ab = A + (size_t)blockIdx.x * 64 * lda;

    ull acc[4][2] = {};
    for (int k0 = 0; k0 < Klen; k0 += 32) {
        __syncthreads();
        {
            int c = (tid & 7) * 4;
            int r = tid >> 3;
            *(float4*)&As[r * 36 + c]        = *(const float4*)&Ab[(size_t)r * lda + k0 + c];
            *(float4*)&As[(r + 32) * 36 + c] = *(const float4*)&Ab[(size_t)(r + 32) * lda + k0 + c];
            int n = tid >> 2, kk0 = (tid & 3) * 8;
            #pragma unroll
            for (int j = 0; j < 8; j++)
                BsT[(kk0 + j) * 68 + n] = B[(size_t)n * ldb + k0 + kk0 + j];
        }
        __syncthreads();
        #pragma unroll 4
        for (int kk = 0; kk < 32; kk++) {
            float a[4];
            #pragma unroll
            for (int i = 0; i < 4; i++) a[i] = As[(ty * 4 + i) * 36 + kk];
            ull b0 = *(const ull*)&BsT[kk * 68 + tx * 4];
            ull b1 = *(const ull*)&BsT[kk * 68 + tx * 4 + 2];
            #pragma unroll
            for (int i = 0; i < 4; i++) {
                ull ad = dup2(a[i]);
                acc[i][0] = ffma2(ad, b0, acc[i][0]);
                acc[i][1] = ffma2(ad, b1, acc[i][1]);
            }
        }
    }
    #pragma unroll
    for (int i = 0; i < 4; i++) {
        size_t row = blockIdx.x * 64 + ty * 4 + i;
        *(float2*)&C[row * 64 + tx * 4]     = unpack2(acc[i][0]);
        *(float2*)&C[row * 64 + tx * 4 + 2] = unpack2(acc[i][1]);
    }
}

// resonances: grid (64, 2, 3); split-K halves of K=2048
__global__ __launch_bounds__(256) void k_res_part(const float* __restrict__ X,
                                                  const float* __restrict__ b0,
                                                  const float* __restrict__ b1,
                                                  const float* __restrict__ b2)
{
    const int z = blockIdx.z, ks = blockIdx.y;
    const float* B = (z == 0) ? b0 : (z == 1) ? b1 : b2;
    gemm64F2(X + ks * 1024, B + ks * 1024, g_resP[z][ks], 1024, HID, HID);
}
__global__ void k_res_combine()
{
    int i = blockIdx.x * blockDim.x + threadIdx.x;  // float4 index
    const int N4 = NROWS * HARM / 4;
    if (i < 3 * N4) {
        int z = i / N4, r = i - z * N4;
        float4 a = ((const float4*)g_resP[z][0])[r];
        float4 b = ((const float4*)g_resP[z][1])[r];
        ((float4*)g_res[z])[r] = make_float4(a.x + b.x, a.y + b.y, a.z + b.z, a.w + b.w);
    }
}

// res_o partials: grid (64, 4); K=1024 split 4 ways
__global__ __launch_bounds__(256) void k_resO_part()
{
    const int ks = blockIdx.y;
    gemm64F2(g_U + ks * 256, g_Nt + ks * 256, g_resoP[ks], 256, NHEAD * HARM, NHEAD * HARM);
}
__global__ void k_resO_combine()
{
    int i = blockIdx.x * blockDim.x + threadIdx.x;
    const int N4 = NROWS * HARM / 4;
    if (i < N4) {
        float4 a = ((const float4*)g_resoP[0])[i];
        float4 b = ((const float4*)g_resoP[1])[i];
        float4 c = ((const float4*)g_resoP[2])[i];
        float4 d = ((const float4*)g_resoP[3])[i];
        ((float4*)g_reso)[i] = make_float4(a.x + b.x + c.x + d.x, a.y + b.y + c.y + d.y,
                                           a.z + b.z + c.z + d.z, a.w + b.w + c.w + d.w);
    }
}

// ---------------- 128x64-tile f32x2 GEMM (final output) ----------------
__device__ __forceinline__ void gemmF2(const float* __restrict__ A,
                                       const float* __restrict__ B,
                                       float* __restrict__ C,
                                       int K, int lda, int ldb, int ldc)
{
    __shared__ float As[128 * 36];
    __shared__ float BsT[32 * 68];
    const int tid = threadIdx.x;
    const int tx = tid & 15;
    const int ty = tid >> 4;
    const float* Ab = A + (size_t)blockIdx.x * 128 * lda;
    const float* Bb = B + (size_t)blockIdx.y * 64 * ldb;

    ull acc[8][2] = {};
    for (int k0 = 0; k0 < K; k0 += 32) {
        __syncthreads();
        {
            int c = (tid & 7) * 4;
            #pragma unroll
            for (int p = 0; p < 4; p++) {
                int r = (tid >> 3) + p * 32;
                *(float4*)&As[r * 36 + c] = *(const float4*)&Ab[(size_t)r * lda + k0 + c];
            }
            int n = tid >> 2, kk0 = (tid & 3) * 8;
            #pragma unroll
            for (int j = 0; j < 8; j++)
                BsT[(kk0 + j) * 68 + n] = Bb[(size_t)n * ldb + k0 + kk0 + j];
        }
        __syncthreads();
        #pragma unroll 4
        for (int kk = 0; kk < 32; kk++) {
            float a[8];
            #pragma unroll
            for (int i = 0; i < 8; i++) a[i] = As[(ty * 8 + i) * 36 + kk];
            ull b0 = *(const ull*)&BsT[kk * 68 + tx * 4];
            ull b1 = *(const ull*)&BsT[kk * 68 + tx * 4 + 2];
            #pragma unroll
            for (int i = 0; i < 8; i++) {
                ull ad = dup2(a[i]);
                acc[i][0] = ffma2(ad, b0, acc[i][0]);
                acc[i][1] = ffma2(ad, b1, acc[i][1]);
            }
        }
    }
    #pragma unroll
    for (int i = 0; i < 8; i++) {
        size_t row = blockIdx.x * 128 + ty * 8 + i;
        *(float2*)&C[row * ldc + blockIdx.y * 64 + tx * 4]     = unpack2(acc[i][0]);
        *(float2*)&C[row * ldc + blockIdx.y * 64 + tx * 4 + 2] = unpack2(acc[i][1]);
    }
}

__global__ __launch_bounds__(256) void k_out(float* __restrict__ out)
{
    gemmF2(g_reso, g_w[3], out, HARM, HARM, HARM, HID);
}

// ---------------- attention: rank-64, online softmax, packed-row S-GEMM ----------------
// smem: TsT[a][row] 64x132 (T transposed: A-operand loads as packed row-pairs),
//       KsT[a][kk]  64x68, Vs[kk][c] 64x68, Ps[row][kk] 128x68.
#define TS_LD 132
#define KS_LD 68
#define VS_LD 68
#define PS_LD 68
#define ATTN_SMEM_FLOATS (64*TS_LD + 64*KS_LD + 64*VS_LD + 128*PS_LD)
#define ATTN_SMEM_BYTES  (ATTN_SMEM_FLOATS * 4)

__global__ __launch_bounds__(256, 2) void k_attn4()
{
    extern __shared__ float sm[];
    float* TsT = sm;                    // [64][132]  T transposed (feature-major)
    float* KsT = TsT + 64 * TS_LD;      // [64][68]   keys feature-major [a][kk] (also M in phase0)
    float* Vs  = KsT + 64 * KS_LD;      // [64][68]   values [kk][c]
    float* Ps  = Vs + 64 * VS_LD;       // [128][68]  P row-major (also RqT staging in phase0)

    const int tid = threadIdx.x;
    const int tx = tid & 15;
    const int ty = tid >> 4;
    const int lane = tid & 31;
    const int wrp = tid >> 5;
    const int qt = blockIdx.x;
    const int h  = blockIdx.y;
    const int b  = blockIdx.z;
    const int qrow0 = b * SEQ + qt * 128;

    // K staging mapping (lane-contiguous kk -> conflict-free STS)
    const int kkL = lane + (wrp & 1) * 32;  // 0..63
    const int f0  = (wrp >> 1) * 16;        // 0,16,32,48

    // ---- phase 0: stage Rq transposed into Ps region, M_h into KsT ----
    {
        const float* Rq = g_res[0] + (size_t)qrow0 * HARM;
        int r = tid >> 1;              // 0..127
        int a0 = (tid & 1) * 32;       // 0 or 32
        #pragma unroll
        for (int t = 0; t < 8; t++) {
            float4 v = *(const float4*)&Rq[r * 64 + a0 + t * 4];
            Ps[(a0 + t * 4 + 0) * TS_LD + r] = v.x;   // reuse TS_LD stride (fits: 64*132 <= 128*68)
            Ps[(a0 + t * 4 + 1) * TS_LD + r] = v.y;
            Ps[(a0 + t * 4 + 2) * TS_LD + r] = v.z;
            Ps[(a0 + t * 4 + 3) * TS_LD + r] = v.w;
        }
        const float* Mh = g_M + h * 4096;
        #pragma unroll
        for (int p = 0; p < 4; p++) {
            int a = ty + p * 16;
            *(float4*)&KsT[a * KS_LD + tx * 4] = *(const float4*)&Mh[a * 64 + tx * 4];
        }
    }
    __syncthreads();

    const float* RkB = g_res[1] + (size_t)(b * SEQ) * HARM;
    const float* RvB = g_res[2] + (size_t)(b * SEQ) * HARM;

    // prefetch K/V tile 0 (overlaps T-GEMM)
    float4 pk[4], pv[4];
    #pragma unroll
    for (int t = 0; t < 4; t++) pk[t] = *(const float4*)&RkB[kkL * 64 + f0 + t * 4];
    #pragma unroll
    for (int p = 0; p < 4; p++) pv[p] = *(const float4*)&RvB[(ty + p * 16) * 64 + tx * 4];

    // ---- T = Rq @ M_h, packed-row accumulators ----
    {
        ull t2[4][4] = {};   // [row-pair p][col j]
        #pragma unroll 8
        for (int a = 0; a < 64; a++) {
            ulonglong2 q01 = *(const ulonglong2*)&Ps[a * TS_LD + ty * 8];
            ulonglong2 q23 = *(const ulonglong2*)&Ps[a * TS_LD + ty * 8 + 4];
            float4 mv = *(const float4*)&KsT[a * KS_LD + tx * 4];
            ull m0 = dup2(mv.x), m1 = dup2(mv.y), m2 = dup2(mv.z), m3 = dup2(mv.w);
            t2[0][0] = ffma2(q01.x, m0, t2[0][0]); t2[0][1] = ffma2(q01.x, m1, t2[0][1]);
            t2[0][2] = ffma2(q01.x, m2, t2[0][2]); t2[0][3] = ffma2(q01.x, m3, t2[0][3]);
            t2[1][0] = ffma2(q01.y, m0, t2[1][0]); t2[1][1] = ffma2(q01.y, m1, t2[1][1]);
            t2[1][2] = ffma2(q01.y, m2, t2[1][2]); t2[1][3] = ffma2(q01.y, m3, t2[1][3]);
            t2[2][0] = ffma2(q23.x, m0, t2[2][0]); t2[2][1] = ffma2(q23.x, m1, t2[2][1]);
            t2[2][2] = ffma2(q23.x, m2, t2[2][2]); t2[2][3] = ffma2(q23.x, m3, t2[2][3]);
            t2[3][0] = ffma2(q23.y, m0, t2[3][0]); t2[3][1] = ffma2(q23.y, m1, t2[3][1]);
            t2[3][2] = ffma2(q23.y, m2, t2[3][2]); t2[3][3] = ffma2(q23.y, m3, t2[3][3]);
        }
        // store T transposed: TsT[col][row], rows contiguous
        #pragma unroll
        for (int j = 0; j < 4; j++) {
            ulonglong2 w0; w0.x = t2[0][j]; w0.y = t2[1][j];
            ulonglong2 w1; w1.x = t2[2][j]; w1.y = t2[3][j];
            *(ulonglong2*)&TsT[(tx * 4 + j) * TS_LD + ty * 8]     = w0;
            *(ulonglong2*)&TsT[(tx * 4 + j) * TS_LD + ty * 8 + 4] = w1;
        }
    }

    float m_i[8], l_i[8];
    ull u2[8][2] = {};   // col-packed: row i, col pairs (tx*4+0,1) and (tx*4+2,3)
    #pragma unroll
    for (int i = 0; i < 8; i++) { m_i[i] = -1e30f; l_i[i] = 0.0f; }

    for (int kt = 0; kt < SEQ / 64; kt++) {
        __syncthreads();  // prior tile readers of KsT/Vs/Ps done (phase0: T reads of KsT/Ps done)
        // ---- stage K (feature-major) and V from prefetch registers ----
        #pragma unroll
        for (int t = 0; t < 4; t++) {
            KsT[(f0 + t * 4 + 0) * KS_LD + kkL] = pk[t].x;
            KsT[(f0 + t * 4 + 1) * KS_LD + kkL] = pk[t].y;
            KsT[(f0 + t * 4 + 2) * KS_LD + kkL] = pk[t].z;
            KsT[(f0 + t * 4 + 3) * KS_LD + kkL] = pk[t].w;
        }
        #pragma unroll
        for (int p = 0; p < 4; p++)
            *(float4*)&Vs[(ty + p * 16) * VS_LD + tx * 4] = pv[p];
        __syncthreads();

        // ---- S = T @ Rk^T, packed-row accumulators ----
        ull s2[4][4] = {};   // [row-pair p][col j]
        #pragma unroll 8
        for (int a = 0; a < 64; a++) {
            ulonglong2 t01 = *(const ulonglong2*)&TsT[a * TS_LD + ty * 8];
            ulonglong2 t23 = *(const ulonglong2*)&TsT[a * TS_LD + ty * 8 + 4];
            float4 kv = *(const float4*)&KsT[a * KS_LD + tx * 4];
            ull k0 = dup2(kv.x), k1 = dup2(kv.y), k2 = dup2(kv.z), k3 = dup2(kv.w);
            s2[0][0] = ffma2(t01.x, k0, s2[0][0]); s2[0][1] = ffma2(t01.x, k1, s2[0][1]);
            s2[0][2] = ffma2(t01.x, k2, s2[0][2]); s2[0][3] = ffma2(t01.x, k3, s2[0][3]);
            s2[1][0] = ffma2(t01.y, k0, s2[1][0]); s2[1][1] = ffma2(t01.y, k1, s2[1][1]);
            s2[1][2] = ffma2(t01.y, k2, s2[1][2]); s2[1][3] = ffma2(t01.y, k3, s2[1][3]);
            s2[2][0] = ffma2(t23.x, k0, s2[2][0]); s2[2][1] = ffma2(t23.x, k1, s2[2][1]);
            s2[2][2] = ffma2(t23.x, k2, s2[2][2]); s2[2][3] = ffma2(t23.x, k3, s2[2][3]);
            s2[3][0] = ffma2(t23.y, k0, s2[3][0]); s2[3][1] = ffma2(t23.y, k1, s2[3][1]);
            s2[3][2] = ffma2(t23.y, k2, s2[3][2]); s2[3][3] = ffma2(t23.y, k3, s2[3][3]);
        }

        // ---- online softmax (log2 domain), P stored row-major float4 ----
        #pragma unroll
        for (int p = 0; p < 4; p++) {
            float2 c0 = unpack2(s2[p][0]);
            float2 c1 = unpack2(s2[p][1]);
            float2 c2 = unpack2(s2[p][2]);
            float2 c3 = unpack2(s2[p][3]);
            #pragma unroll
            for (int hl = 0; hl < 2; hl++) {
                int r = 2 * p + hl;
                float s0 = hl ? c0.y : c0.x;
                float s1 = hl ? c1.y : c1.x;
                float s2v = hl ? c2.y : c2.x;
                float s3 = hl ? c3.y : c3.x;
                float rm = fmaxf(fmaxf(s0, s1), fmaxf(s2v, s3));
                rm = fmaxf(rm, __shfl_xor_sync(0xffffffffu, rm, 1));
                rm = fmaxf(rm, __shfl_xor_sync(0xffffffffu, rm, 2));
                rm = fmaxf(rm, __shfl_xor_sync(0xffffffffu, rm, 4));
                rm = fmaxf(rm, __shfl_xor_sync(0xffffffffu, rm, 8));
                float mn   = fmaxf(m_i[r], rm);
                float corr = ex2(m_i[r] - mn);
                m_i[r] = mn;
                float e0 = ex2(s0 - mn);
                float e1 = ex2(s1 - mn);
                float e2 = ex2(s2v - mn);
                float e3 = ex2(s3 - mn);
                *(float4*)&Ps[(ty * 8 + r) * PS_LD + tx * 4] = make_float4(e0, e1, e2, e3);
                l_i[r] = l_i[r] * corr + ((e0 + e1) + (e2 + e3));
                ull cc = dup2(corr);
                u2[r][0] = mul2(u2[r][0], cc);
                u2[r][1] = mul2(u2[r][1], cc);
            }
        }
        __syncthreads();  // Ps complete before PV

        // ---- prefetch next K/V tile (overlaps PV) ----
        if (kt + 1 < SEQ / 64) {
            const float* Rk = RkB + (size_t)((kt + 1) * 64) * HARM;
            const float* Rv = RvB + (size_t)((kt + 1) * 64) * HARM;
            #pragma unroll
            for (int t = 0; t < 4; t++) pk[t] = *(const float4*)&Rk[kkL * 64 + f0 + t * 4];
            #pragma unroll
            for (int p = 0; p < 4; p++) pv[p] = *(const float4*)&Rv[(ty + p * 16) * 64 + tx * 4];
        }

        // ---- U += P @ Rv (col-packed accumulators) ----
        #pragma unroll 8
        for (int kk = 0; kk < 64; kk++) {
            float pvv[8];
            #pragma unroll
            for (int i = 0; i < 8; i++) pvv[i] = Ps[(ty * 8 + i) * PS_LD + kk];
            ulonglong2 vv = *(const ulonglong2*)&Vs[kk * VS_LD + tx * 4];
            #pragma unroll
            for (int i = 0; i < 8; i++) {
                ull pd = dup2(pvv[i]);
                u2[i][0] = ffma2(pd, vv.x, u2[i][0]);
                u2[i][1] = ffma2(pd, vv.y, u2[i][1]);
            }
        }
    }

    // ---- epilogue: reduce l across 16 lanes, normalize, store ----
    float* Ug = g_U + (size_t)qrow0 * (NHEAD * HARM) + h * HARM;
    #pragma unroll
    for (int i = 0; i < 8; i++) {
        float lv = l_i[i];
        lv += __shfl_xor_sync(0xffffffffu, lv, 1);
        lv += __shfl_xor_sync(0xffffffffu, lv, 2);
        lv += __shfl_xor_sync(0xffffffffu, lv, 4);
        lv += __shfl_xor_sync(0xffffffffu, lv, 8);
        ull iv = dup2(1.0f / lv);
        size_t row = (size_t)(ty * 8 + i) * (NHEAD * HARM);
        *(float2*)&Ug[row + tx * 4]     = unpack2(mul2(u2[i][0], iv));
        *(float2*)&Ug[row + tx * 4 + 2] = unpack2(mul2(u2[i][1], iv));
    }
}

// ---------------- launch ----------------
extern "C" void kernel_launch(void* const* d_in, const int* in_sizes, int n_in,
                              void* d_out, int out_size)
{
    (void)in_sizes; (void)n_in; (void)out_size;
    const float* hs      = (const float*)d_in[0];
    const float* basis_q = (const float*)d_in[1];
    const float* phase_q = (const float*)d_in[2];
    const float* amp_q   = (const float*)d_in[3];
    const float* basis_k = (const float*)d_in[4];
    const float* phase_k = (const float*)d_in[5];
    const float* amp_k   = (const float*)d_in[6];
    const float* basis_v = (const float*)d_in[7];
    const float* phase_v = (const float*)d_in[8];
    const float* amp_v   = (const float*)d_in[9];
    const float* basis_o = (const float*)d_in[10];
    const float* phase_o = (const float*)d_in[11];
    const float* amp_o   = (const float*)d_in[12];
    float* out = (float*)d_out;

    cudaFuncSetAttribute(k_attn4, cudaFuncAttributeMaxDynamicSharedMemorySize, ATTN_SMEM_BYTES);

    k_compute_w<<<(HID * HARM + 255) / 256, 256>>>(phase_q, amp_q, phase_k, amp_k,
                                                   phase_v, amp_v, phase_o, amp_o);
    k_prep<<<dim3(NHEAD, 2), 256>>>(basis_o);
    k_res_part<<<dim3(NROWS / 64, 2, 3), 256>>>(hs, basis_q, basis_k, basis_v);
    k_res_combine<<<(3 * NROWS * HARM / 4 + 255) / 256, 256>>>();
    k_attn4<<<dim3(SEQ / 128, NHEAD, BATCH), 256, ATTN_SMEM_BYTES>>>();
    k_resO_part<<<dim3(NROWS / 64, 4), 256>>>();
    k_resO_combine<<<(NROWS * HARM / 4 + 255) / 256, 256>>>();
    k_out<<<dim3(NROWS / 128, HID / 64), 256>>>(out);
}

// round 12
// speedup vs baseline: 3.6841x; 1.5698x over previous
#include <cuda_runtime.h>
#include <cuda_bf16.h>
#include <cstdint>
#include <stdint.h>
#include <math.h>

#define HID   2048
#define NHEAD 16
#define DH    128
#define HARM  64
#define BATCH 2
#define SEQ   2048
#define NROWS (BATCH*SEQ)   // 4096
#define NTILE (SEQ/64)      // 32

typedef unsigned long long ull;

// ---------------- device scratch ----------------
__device__ float g_w[4][HID*HARM];
__device__ float g_res[3][NROWS*HARM];
__device__ float g_resP[3][2][NROWS*HARM];
__device__ float g_Mt[NHEAD*HARM*HARM];    // Mt[h][c][a] = log2e*scale*M[a][c]
__device__ float g_Nt[HARM*NHEAD*HARM];
__device__ float g_U[NROWS*NHEAD*HARM];
__device__ float g_reso[NROWS*HARM];
__device__ float g_resoP[4][NROWS*HARM];
// bf16 operands for tensor-core attention
__device__ __nv_bfloat16 g_Thi[(size_t)NHEAD*NROWS*HARM];  // [h][row][c]
__device__ __nv_bfloat16 g_Tlo[(size_t)NHEAD*NROWS*HARM];
__device__ __nv_bfloat16 g_Khi[NROWS*HARM];                // [row][a]
__device__ __nv_bfloat16 g_Klo[NROWS*HARM];
__device__ __nv_bfloat16 g_VThi[(size_t)HARM*NROWS];       // [c][row]
__device__ __nv_bfloat16 g_VTlo[(size_t)HARM*NROWS];       // [c][row]

// ---------------- f32x2 / misc helpers ----------------
__device__ __forceinline__ ull ffma2(ull a, ull b, ull c) {
    ull d; asm("fma.rn.f32x2 %0, %1, %2, %3;" : "=l"(d) : "l"(a), "l"(b), "l"(c)); return d;
}
__device__ __forceinline__ ull dup2(float v) {
    ull r; asm("mov.b64 %0, {%1, %2};" : "=l"(r) : "f"(v), "f"(v)); return r;
}
__device__ __forceinline__ float2 unpack2(ull v) {
    float2 f; asm("mov.b64 {%0, %1}, %2;" : "=f"(f.x), "=f"(f.y) : "l"(v)); return f;
}
__device__ __forceinline__ float ex2(float x) {
    float y; asm("ex2.approx.ftz.f32 %0, %1;" : "=f"(y) : "f"(x)); return y;
}
__device__ __forceinline__ unsigned bfbits(__nv_bfloat16 h) {
    return (unsigned)*reinterpret_cast<unsigned short*>(&h);
}
__device__ __forceinline__ uint32_t packbf(float x, float y) {
    // lo element = x (even col / even k), hi = y
    return bfbits(__float2bfloat16(x)) | (bfbits(__float2bfloat16(y)) << 16);
}
__device__ __forceinline__ uint32_t packres(float x, float y) {
    __nv_bfloat16 hx = __float2bfloat16(x), hy = __float2bfloat16(y);
    return bfbits(__float2bfloat16(x - __bfloat162float(hx))) |
           (bfbits(__float2bfloat16(y - __bfloat162float(hy))) << 16);
}
__device__ __forceinline__ uint32_t s2u(const void* p) {
    uint32_t a; asm("{ .reg .u64 t; cvta.to.shared.u64 t, %1; cvt.u32.u64 %0, t; }" : "=r"(a) : "l"(p)); return a;
}

// mma.sync m16n8k16 bf16 (base PTX, works on plain sm_103 target)
#define MMA16816(D, A, b0_, b1_) \
    asm volatile("mma.sync.aligned.m16n8k16.row.col.f32.bf16.bf16.f32 " \
        "{%0,%1,%2,%3}, {%4,%5,%6,%7}, {%8,%9}, {%0,%1,%2,%3};" \
        : "+f"((D)[0]), "+f"((D)[1]), "+f"((D)[2]), "+f"((D)[3]) \
        : "r"((A)[0]), "r"((A)[1]), "r"((A)[2]), "r"((A)[3]), "r"(b0_), "r"(b1_))

__device__ __forceinline__ void cpasync16(uint32_t sdst, const void* gsrc) {
    asm volatile("cp.async.cg.shared.global [%0], [%1], 16;" :: "r"(sdst), "l"(gsrc) : "memory");
}
#define CP_COMMIT() asm volatile("cp.async.commit_group;" ::: "memory")
#define CP_WAIT(n)  asm volatile("cp.async.wait_group %0;" :: "n"(n) : "memory")

// ---------------- w = amp * cos(phase) ----------------
__global__ void k_compute_w(const float* __restrict__ pq, const float* __restrict__ aq,
                            const float* __restrict__ pk, const float* __restrict__ ak,
                            const float* __restrict__ pv, const float* __restrict__ av,
                            const float* __restrict__ po, const float* __restrict__ ao)
{
    int i = blockIdx.x * blockDim.x + threadIdx.x;
    if (i < HID * HARM) {
        g_w[0][i] = aq[i] * cosf(pq[i]);
        g_w[1][i] = ak[i] * cosf(pk[i]);
        g_w[2][i] = av[i] * cosf(pv[i]);
        g_w[3][i] = ao[i] * cosf(po[i]);
    }
}

// ---------------- prep: Mt (log2e*scale, transposed) and Nt ----------------
__global__ __launch_bounds__(256) void k_prep(const float* __restrict__ basis_o)
{
    __shared__ float As[32][65];
    __shared__ float Bs[32][65];
    const int h = blockIdx.x;
    const int z = blockIdx.y;
    const int tid = threadIdx.x;
    const int tx = tid & 15;
    const int ty = tid >> 4;

    float acc[4][4] = {};
    for (int dc = 0; dc < 128; dc += 32) {
        __syncthreads();
        if (z == 0) {
            int d = tid >> 3, a0 = (tid & 7) * 8;
            #pragma unroll
            for (int j = 0; j < 8; j++) {
                As[d][a0 + j] = g_w[0][(h * 128 + dc + d) * 64 + a0 + j];
                Bs[d][a0 + j] = g_w[1][(h * 128 + dc + d) * 64 + a0 + j];
            }
        } else {
            int d = tid >> 3, a0 = (tid & 7) * 8;
            #pragma unroll
            for (int j = 0; j < 8; j++)
                As[d][a0 + j] = g_w[2][(h * 128 + dc + d) * 64 + a0 + j];
            int c = tid >> 2, d0 = (tid & 3) * 8;
            #pragma unroll
            for (int j = 0; j < 8; j++)
                Bs[d0 + j][c] = basis_o[c * 2048 + h * 128 + dc + d0 + j];
        }
        __syncthreads();
        #pragma unroll 8
        for (int d = 0; d < 32; d++) {
            float a[4], b[4];
            #pragma unroll
            for (int i = 0; i < 4; i++) a[i] = As[d][ty * 4 + i];
            #pragma unroll
            for (int j = 0; j < 4; j++) b[j] = Bs[d][tx * 4 + j];
            #pragma unroll
            for (int i = 0; i < 4; i++)
                #pragma unroll
                for (int j = 0; j < 4; j++)
                    acc[i][j] += a[i] * b[j];
        }
    }
    const float scale = 0.08838834764831845f * 1.4426950408889634f;
    if (z == 0) {
        #pragma unroll
        for (int i = 0; i < 4; i++)
            #pragma unroll
            for (int j = 0; j < 4; j++)
                g_Mt[h * 4096 + (tx * 4 + j) * 64 + (ty * 4 + i)] = acc[i][j] * scale;
    } else {
        #pragma unroll
        for (int i = 0; i < 4; i++)
            #pragma unroll
            for (int j = 0; j < 4; j++)
                g_Nt[(tx * 4 + j) * 1024 + h * 64 + ty * 4 + i] = acc[i][j];
    }
}

// ---------------- 64x64-tile f32x2 GEMM partial ----------------
__device__ __forceinline__ void gemm64F2(const float* __restrict__ A,
                                         const float* __restrict__ B,
                                         float* __restrict__ C,
                                         int Klen, int lda, int ldb)
{
    __shared__ float As[64 * 36];
    __shared__ float BsT[32 * 68];
    const int tid = threadIdx.x;
    const int tx = tid & 15;
    const int ty = tid >> 4;
    const float* Ab = A + (size_t)blockIdx.x * 64 * lda;

    ull acc[4][2] = {};
    for (int k0 = 0; k0 < Klen; k0 += 32) {
        __syncthreads();
        {
            int c = (tid & 7) * 4;
            int r = tid >> 3;
            *(float4*)&As[r * 36 + c]        = *(const float4*)&Ab[(size_t)r * lda + k0 + c];
            *(float4*)&As[(r + 32) * 36 + c] = *(const float4*)&Ab[(size_t)(r + 32) * lda + k0 + c];
            int n = tid >> 2, kk0 = (tid & 3) * 8;
            #pragma unroll
            for (int j = 0; j < 8; j++)
                BsT[(kk0 + j) * 68 + n] = B[(size_t)n * ldb + k0 + kk0 + j];
        }
        __syncthreads();
        #pragma unroll 4
        for (int kk = 0; kk < 32; kk++) {
            float a[4];
            #pragma unroll
            for (int i = 0; i < 4; i++) a[i] = As[(ty * 4 + i) * 36 + kk];
            ull b0 = *(const ull*)&BsT[kk * 68 + tx * 4];
            ull b1 = *(const ull*)&BsT[kk * 68 + tx * 4 + 2];
            #pragma unroll
            for (int i = 0; i < 4; i++) {
                ull ad = dup2(a[i]);
                acc[i][0] = ffma2(ad, b0, acc[i][0]);
                acc[i][1] = ffma2(ad, b1, acc[i][1]);
            }
        }
    }
    #pragma unroll
    for (int i = 0; i < 4; i++) {
        size_t row = blockIdx.x * 64 + ty * 4 + i;
        *(float2*)&C[row * 64 + tx * 4]     = unpack2(acc[i][0]);
        *(float2*)&C[row * 64 + tx * 4 + 2] = unpack2(acc[i][1]);
    }
}

__global__ __launch_bounds__(256) void k_res_part(const float* __restrict__ X,
                                                  const float* __restrict__ b0,
                                                  const float* __restrict__ b1,
                                                  const float* __restrict__ b2)
{
    const int z = blockIdx.z, ks = blockIdx.y;
    const float* B = (z == 0) ? b0 : (z == 1) ? b1 : b2;
    gemm64F2(X + ks * 1024, B + ks * 1024, g_resP[z][ks], 1024, HID, HID);
}
__global__ void k_res_combine()
{
    int i = blockIdx.x * blockDim.x + threadIdx.x;
    const int N4 = NROWS * HARM / 4;
    if (i < 3 * N4) {
        int z = i / N4, r = i - z * N4;
        float4 a = ((const float4*)g_resP[z][0])[r];
        float4 b = ((const float4*)g_resP[z][1])[r];
        ((float4*)g_res[z])[r] = make_float4(a.x + b.x, a.y + b.y, a.z + b.z, a.w + b.w);
    }
}

__global__ __launch_bounds__(256) void k_resO_part()
{
    const int ks = blockIdx.y;
    gemm64F2(g_U + ks * 256, g_Nt + ks * 256, g_resoP[ks], 256, NHEAD * HARM, NHEAD * HARM);
}
__global__ void k_resO_combine()
{
    int i = blockIdx.x * blockDim.x + threadIdx.x;
    const int N4 = NROWS * HARM / 4;
    if (i < N4) {
        float4 a = ((const float4*)g_resoP[0])[i];
        float4 b = ((const float4*)g_resoP[1])[i];
        float4 c = ((const float4*)g_resoP[2])[i];
        float4 d = ((const float4*)g_resoP[3])[i];
        ((float4*)g_reso)[i] = make_float4(a.x + b.x + c.x + d.x, a.y + b.y + c.y + d.y,
                                           a.z + b.z + c.z + d.z, a.w + b.w + c.w + d.w);
    }
}

// ---------------- 128x64-tile f32x2 GEMM (final output) ----------------
__device__ __forceinline__ void gemmF2(const float* __restrict__ A,
                                       const float* __restrict__ B,
                                       float* __restrict__ C,
                                       int K, int lda, int ldb, int ldc)
{
    __shared__ float As[128 * 36];
    __shared__ float BsT[32 * 68];
    const int tid = threadIdx.x;
    const int tx = tid & 15;
    const int ty = tid >> 4;
    const float* Ab = A + (size_t)blockIdx.x * 128 * lda;
    const float* Bb = B + (size_t)blockIdx.y * 64 * ldb;

    ull acc[8][2] = {};
    for (int k0 = 0; k0 < K; k0 += 32) {
        __syncthreads();
        {
            int c = (tid & 7) * 4;
            #pragma unroll
            for (int p = 0; p < 4; p++) {
                int r = (tid >> 3) + p * 32;
                *(float4*)&As[r * 36 + c] = *(const float4*)&Ab[(size_t)r * lda + k0 + c];
            }
            int n = tid >> 2, kk0 = (tid & 3) * 8;
            #pragma unroll
            for (int j = 0; j < 8; j++)
                BsT[(kk0 + j) * 68 + n] = Bb[(size_t)n * ldb + k0 + kk0 + j];
        }
        __syncthreads();
        #pragma unroll 4
        for (int kk = 0; kk < 32; kk++) {
            float a[8];
            #pragma unroll
            for (int i = 0; i < 8; i++) a[i] = As[(ty * 8 + i) * 36 + kk];
            ull b0 = *(const ull*)&BsT[kk * 68 + tx * 4];
            ull b1 = *(const ull*)&BsT[kk * 68 + tx * 4 + 2];
            #pragma unroll
            for (int i = 0; i < 8; i++) {
                ull ad = dup2(a[i]);
                acc[i][0] = ffma2(ad, b0, acc[i][0]);
                acc[i][1] = ffma2(ad, b1, acc[i][1]);
            }
        }
    }
    #pragma unroll
    for (int i = 0; i < 8; i++) {
        size_t row = blockIdx.x * 128 + ty * 8 + i;
        *(float2*)&C[row * ldc + blockIdx.y * 64 + tx * 4]     = unpack2(acc[i][0]);
        *(float2*)&C[row * ldc + blockIdx.y * 64 + tx * 4 + 2] = unpack2(acc[i][1]);
    }
}

__global__ __launch_bounds__(256) void k_out(float* __restrict__ out)
{
    gemmF2(g_reso, g_w[3], out, HARM, HARM, HARM, HID);
}

// ---------------- bf16 split prep kernels ----------------
__global__ __launch_bounds__(256) void k_splitT()
{
    __shared__ float As[64 * 68];
    __shared__ float Bs[64 * 68];
    const int bx = blockIdx.x, h = blockIdx.y;
    const int tid = threadIdx.x;
    const int tx = tid & 15;
    const int ty = tid >> 4;
    {
        int r = tid >> 2, a0 = (tid & 3) * 16;
        const float* Aq = g_res[0] + (size_t)(bx * 64) * 64;
        const float* Bm = g_Mt + h * 4096;
        #pragma unroll
        for (int q = 0; q < 4; q++) {
            *(float4*)&As[r * 68 + a0 + q * 4] = *(const float4*)&Aq[r * 64 + a0 + q * 4];
            *(float4*)&Bs[r * 68 + a0 + q * 4] = *(const float4*)&Bm[r * 64 + a0 + q * 4];
        }
    }
    __syncthreads();
    float acc[4][4] = {};
    #pragma unroll 8
    for (int a = 0; a < 64; a++) {
        float av[4], bv[4];
        #pragma unroll
        for (int i = 0; i < 4; i++) av[i] = As[(ty * 4 + i) * 68 + a];
        #pragma unroll
        for (int j = 0; j < 4; j++) bv[j] = Bs[(tx * 4 + j) * 68 + a];
        #pragma unroll
        for (int i = 0; i < 4; i++)
            #pragma unroll
            for (int j = 0; j < 4; j++)
                acc[i][j] += av[i] * bv[j];
    }
    #pragma unroll
    for (int i = 0; i < 4; i++)
        #pragma unroll
        for (int j = 0; j < 4; j++) {
            float x = acc[i][j];
            size_t o = (size_t)h * NROWS * 64 + (size_t)(bx * 64 + ty * 4 + i) * 64 + tx * 4 + j;
            __nv_bfloat16 hi = __float2bfloat16(x);
            g_Thi[o] = hi;
            g_Tlo[o] = __float2bfloat16(x - __bfloat162float(hi));
        }
}

__global__ void k_splitK()
{
    int i = blockIdx.x * blockDim.x + threadIdx.x;
    if (i < NROWS * HARM / 4) {
        float4 v = ((const float4*)g_res[1])[i];
        __nv_bfloat16 h0 = __float2bfloat16(v.x), h1 = __float2bfloat16(v.y);
        __nv_bfloat16 h2 = __float2bfloat16(v.z), h3 = __float2bfloat16(v.w);
        uint2 hh, ll;
        hh.x = bfbits(h0) | (bfbits(h1) << 16);
        hh.y = bfbits(h2) | (bfbits(h3) << 16);
        ll.x = bfbits(__float2bfloat16(v.x - __bfloat162float(h0))) |
               (bfbits(__float2bfloat16(v.y - __bfloat162float(h1))) << 16);
        ll.y = bfbits(__float2bfloat16(v.z - __bfloat162float(h2))) |
               (bfbits(__float2bfloat16(v.w - __bfloat162float(h3))) << 16);
        *(uint2*)&g_Khi[i * 4] = hh;
        *(uint2*)&g_Klo[i * 4] = ll;
    }
}

__global__ __launch_bounds__(256) void k_splitV()
{
    __shared__ float t[64][65];
    const int r0 = blockIdx.x * 64;
    const int tid = threadIdx.x;
    #pragma unroll
    for (int q = 0; q < 16; q++) {
        int idx = q * 256 + tid;
        int r = idx >> 6, c = idx & 63;
        t[r][c] = g_res[2][(size_t)(r0 + r) * 64 + c];
    }
    __syncthreads();
    #pragma unroll
    for (int q = 0; q < 16; q++) {
        int idx = q * 256 + tid;
        int c = idx >> 6, r = idx & 63;
        float v = t[r][c];
        __nv_bfloat16 hi = __float2bfloat16(v);
        g_VThi[(size_t)c * NROWS + r0 + r] = hi;
        g_VTlo[(size_t)c * NROWS + r0 + r] = __float2bfloat16(v - __bfloat162float(hi));
    }
}

// ---------------- FA2-style mma.sync attention ----------------
// CTA: 256 thr / 8 warps / 128 q-rows. Warp w owns q-rows w*16..w*16+15.
// Key tiles of 64, double-buffered cp.async staging.
// smem per stage: Khi,Klo [64 key][72 feat] + Vhi,Vlo [64 c][72 key] bf16.
#define STRIDE 72
#define ARRB   (64 * STRIDE)              // elements per array
#define STAGEB (4 * ARRB)                 // elements per stage
#define ATTN_SMEM (2 * STAGEB * 2)        // bytes = 73728

__global__ __launch_bounds__(256, 1) void k_attn6()
{
    extern __shared__ __nv_bfloat16 smb[];
    const int tid = threadIdx.x;
    const int lane = tid & 31, w = tid >> 5;
    const int qt = blockIdx.x, h = blockIdx.y, b = blockIdx.z;
    const int qrow0 = b * SEQ + qt * 128;
    const size_t bSEQ = (size_t)b * SEQ;
    const int qr = lane >> 2;        // 0..7
    const int qk = (lane & 3) * 2;   // 0,2,4,6

    // ---- T a-fragments into registers (hi+lo), once ----
    uint32_t tahi[4][4], talo[4][4];
    {
        const __nv_bfloat16* Th = g_Thi + ((size_t)h * NROWS + qrow0 + w * 16 + qr) * 64;
        const __nv_bfloat16* Tl = g_Tlo + ((size_t)h * NROWS + qrow0 + w * 16 + qr) * 64;
        #pragma unroll
        for (int kc = 0; kc < 4; kc++) {
            tahi[kc][0] = *(const uint32_t*)&Th[16 * kc + qk];
            tahi[kc][1] = *(const uint32_t*)&Th[8 * 64 + 16 * kc + qk];
            tahi[kc][2] = *(const uint32_t*)&Th[16 * kc + qk + 8];
            tahi[kc][3] = *(const uint32_t*)&Th[8 * 64 + 16 * kc + qk + 8];
            talo[kc][0] = *(const uint32_t*)&Tl[16 * kc + qk];
            talo[kc][1] = *(const uint32_t*)&Tl[8 * 64 + 16 * kc + qk];
            talo[kc][2] = *(const uint32_t*)&Tl[16 * kc + qk + 8];
            talo[kc][3] = *(const uint32_t*)&Tl[8 * 64 + 16 * kc + qk + 8];
        }
    }

    // staging: thread -> (array, row); 8 x 16B per thread per tile
    const int sarr = tid >> 6;        // 0..3
    const int srow = tid & 63;
    const uint32_t sdstBase[2] = {
        s2u(smb + 0 * STAGEB + sarr * ARRB + srow * STRIDE),
        s2u(smb + 1 * STAGEB + sarr * ARRB + srow * STRIDE)
    };
    auto stage = [&](int t, int s) {
        const char* src;
        if (sarr == 0)      src = (const char*)(g_Khi  + (bSEQ + t * 64 + srow) * 64);
        else if (sarr == 1) src = (const char*)(g_Klo  + (bSEQ + t * 64 + srow) * 64);
        else if (sarr == 2) src = (const char*)(g_VThi + (size_t)srow * NROWS + bSEQ + t * 64);
        else                src = (const char*)(g_VTlo + (size_t)srow * NROWS + bSEQ + t * 64);
        uint32_t d = sdstBase[s];
        #pragma unroll
        for (int j = 0; j < 8; j++)
            cpasync16(d + j * 16, src + j * 16);
    };

    float U[8][4];
    #pragma unroll
    for (int n = 0; n < 8; n++)
        #pragma unroll
        for (int e = 0; e < 4; e++) U[n][e] = 0.0f;
    float mA = -1e30f, mB = -1e30f, lA = 0.0f, lB = 0.0f;

    stage(0, 0); CP_COMMIT();

    for (int t = 0; t < NTILE; t++) {
        if (t + 1 < NTILE) { stage(t + 1, (t + 1) & 1); CP_COMMIT(); CP_WAIT(1); }
        else               { CP_WAIT(0); }
        __syncthreads();

        const __nv_bfloat16* Kh = smb + (t & 1) * STAGEB;
        const __nv_bfloat16* Kl = Kh + ARRB;
        const __nv_bfloat16* Vh = Kh + 2 * ARRB;
        const __nv_bfloat16* Vl = Kh + 3 * ARRB;

        // ---- S = Thi*Khi + Tlo*Khi + Thi*Klo ----
        float S[8][4];
        #pragma unroll
        for (int n = 0; n < 8; n++)
            #pragma unroll
            for (int e = 0; e < 4; e++) S[n][e] = 0.0f;
        #pragma unroll
        for (int n = 0; n < 8; n++) {
            #pragma unroll
            for (int kc = 0; kc < 4; kc++) {
                const __nv_bfloat16* kp = Kh + (n * 8 + qr) * STRIDE + 16 * kc + qk;
                uint32_t b0 = *(const uint32_t*)kp;
                uint32_t b1 = *(const uint32_t*)(kp + 8);
                MMA16816(S[n], tahi[kc], b0, b1);
                MMA16816(S[n], talo[kc], b0, b1);
                const __nv_bfloat16* kp2 = Kl + (n * 8 + qr) * STRIDE + 16 * kc + qk;
                uint32_t c0 = *(const uint32_t*)kp2;
                uint32_t c1 = *(const uint32_t*)(kp2 + 8);
                MMA16816(S[n], tahi[kc], c0, c1);
            }
        }

        // ---- online softmax (log2 domain; rows: A = qr, B = qr+8) ----
        float rmA = -1e30f, rmB = -1e30f;
        #pragma unroll
        for (int n = 0; n < 8; n++) {
            rmA = fmaxf(rmA, fmaxf(S[n][0], S[n][1]));
            rmB = fmaxf(rmB, fmaxf(S[n][2], S[n][3]));
        }
        rmA = fmaxf(rmA, __shfl_xor_sync(0xffffffffu, rmA, 1));
        rmA = fmaxf(rmA, __shfl_xor_sync(0xffffffffu, rmA, 2));
        rmB = fmaxf(rmB, __shfl_xor_sync(0xffffffffu, rmB, 1));
        rmB = fmaxf(rmB, __shfl_xor_sync(0xffffffffu, rmB, 2));
        float mnA = fmaxf(mA, rmA), mnB = fmaxf(mB, rmB);
        float cA = ex2(mA - mnA), cB = ex2(mB - mnB);
        mA = mnA; mB = mnB;

        uint32_t pahi[4][4], palo[4][4];
        float sA = 0.0f, sB = 0.0f;
        #pragma unroll
        for (int kc2 = 0; kc2 < 4; kc2++) {
            int n0 = 2 * kc2, n1 = 2 * kc2 + 1;
            float p00 = ex2(S[n0][0] - mnA), p01 = ex2(S[n0][1] - mnA);
            float p10 = ex2(S[n0][2] - mnB), p11 = ex2(S[n0][3] - mnB);
            float p20 = ex2(S[n1][0] - mnA), p21 = ex2(S[n1][1] - mnA);
            float p30 = ex2(S[n1][2] - mnB), p31 = ex2(S[n1][3] - mnB);
            sA += (p00 + p01) + (p20 + p21);
            sB += (p10 + p11) + (p30 + p31);
            pahi[kc2][0] = packbf(p00, p01);  palo[kc2][0] = packres(p00, p01);
            pahi[kc2][1] = packbf(p10, p11);  palo[kc2][1] = packres(p10, p11);
            pahi[kc2][2] = packbf(p20, p21);  palo[kc2][2] = packres(p20, p21);
            pahi[kc2][3] = packbf(p30, p31);  palo[kc2][3] = packres(p30, p31);
        }
        lA = lA * cA + sA;
        lB = lB * cB + sB;
        #pragma unroll
        for (int n = 0; n < 8; n++) {
            U[n][0] *= cA; U[n][1] *= cA;
            U[n][2] *= cB; U[n][3] *= cB;
        }

        // ---- U += Phi*Vhi + Plo*Vhi + Phi*Vlo ----
        #pragma unroll
        for (int n2 = 0; n2 < 8; n2++) {
            #pragma unroll
            for (int kc2 = 0; kc2 < 4; kc2++) {
                const __nv_bfloat16* vp = Vh + (n2 * 8 + qr) * STRIDE + 16 * kc2 + qk;
                uint32_t b0 = *(const uint32_t*)vp;
                uint32_t b1 = *(const uint32_t*)(vp + 8);
                MMA16816(U[n2], pahi[kc2], b0, b1);
                MMA16816(U[n2], palo[kc2], b0, b1);
                const __nv_bfloat16* vp2 = Vl + (n2 * 8 + qr) * STRIDE + 16 * kc2 + qk;
                uint32_t c0 = *(const uint32_t*)vp2;
                uint32_t c1 = *(const uint32_t*)(vp2 + 8);
                MMA16816(U[n2], pahi[kc2], c0, c1);
            }
        }
        __syncthreads();   // consumers done before next stage overwrites buf
    }

    // ---- epilogue: reduce l over quad, normalize, store ----
    lA += __shfl_xor_sync(0xffffffffu, lA, 1);
    lA += __shfl_xor_sync(0xffffffffu, lA, 2);
    lB += __shfl_xor_sync(0xffffffffu, lB, 1);
    lB += __shfl_xor_sync(0xffffffffu, lB, 2);
    float iA = 1.0f / lA, iB = 1.0f / lB;
    float* UgA = g_U + (size_t)(qrow0 + w * 16 + qr) * (NHEAD * HARM) + h * 64;
    float* UgB = UgA + (size_t)8 * (NHEAD * HARM);
    #pragma unroll
    for (int n2 = 0; n2 < 8; n2++) {
        *(float2*)&UgA[n2 * 8 + qk] = make_float2(U[n2][0] * iA, U[n2][1] * iA);
        *(float2*)&UgB[n2 * 8 + qk] = make_float2(U[n2][2] * iB, U[n2][3] * iB);
    }
}

// ---------------- launch ----------------
extern "C" void kernel_launch(void* const* d_in, const int* in_sizes, int n_in,
                              void* d_out, int out_size)
{
    (void)in_sizes; (void)n_in; (void)out_size;
    const float* hs      = (const float*)d_in[0];
    const float* basis_q = (const float*)d_in[1];
    const float* phase_q = (const float*)d_in[2];
    const float* amp_q   = (const float*)d_in[3];
    const float* basis_k = (const float*)d_in[4];
    const float* phase_k = (const float*)d_in[5];
    const float* amp_k   = (const float*)d_in[6];
    const float* basis_v = (const float*)d_in[7];
    const float* phase_v = (const float*)d_in[8];
    const float* amp_v   = (const float*)d_in[9];
    const float* basis_o = (const float*)d_in[10];
    const float* phase_o = (const float*)d_in[11];
    const float* amp_o   = (const float*)d_in[12];
    float* out = (float*)d_out;

    cudaFuncSetAttribute(k_attn6, cudaFuncAttributeMaxDynamicSharedMemorySize, ATTN_SMEM);

    k_compute_w<<<(HID * HARM + 255) / 256, 256>>>(phase_q, amp_q, phase_k, amp_k,
                                                   phase_v, amp_v, phase_o, amp_o);
    k_prep<<<dim3(NHEAD, 2), 256>>>(basis_o);
    k_res_part<<<dim3(NROWS / 64, 2, 3), 256>>>(hs, basis_q, basis_k, basis_v);
    k_res_combine<<<(3 * NROWS * HARM / 4 + 255) / 256, 256>>>();
    k_splitT<<<dim3(NROWS / 64, NHEAD), 256>>>();
    k_splitK<<<(NROWS * HARM / 4 + 255) / 256, 256>>>();
    k_splitV<<<NROWS / 64, 256>>>();
    k_attn6<<<dim3(SEQ / 128, NHEAD, BATCH), 256, ATTN_SMEM>>>();
    k_resO_part<<<dim3(NROWS / 64, 4), 256>>>();
    k_resO_combine<<<(NROWS * HARM / 4 + 255) / 256, 256>>>();
    k_out<<<dim3(NROWS / 128, HID / 64), 256>>>(out);
}

// round 13
// speedup vs baseline: 3.7955x; 1.0302x over previous
#include <cuda_runtime.h>
#include <cuda_bf16.h>
#include <cstdint>
#include <stdint.h>
#include <math.h>

#define HID   2048
#define NHEAD 16
#define DH    128
#define HARM  64
#define BATCH 2
#define SEQ   2048
#define NROWS (BATCH*SEQ)   // 4096
#define NTILE (SEQ/64)      // 32

typedef unsigned long long ull;

// ---------------- device scratch ----------------
__device__ float g_w[4][HID*HARM];
__device__ float g_res[3][NROWS*HARM];     // only [0] (Rq) used now
__device__ float g_Mt[NHEAD*HARM*HARM];    // Mt[h][c][a] = log2e*scale*M[a][c]
__device__ float g_Nt[HARM*NHEAD*HARM];
__device__ float g_U[NROWS*NHEAD*HARM];
__device__ float g_reso[NROWS*HARM];
__device__ float g_resoP[4][NROWS*HARM];
// bf16 operands
__device__ __nv_bfloat16 g_Xhi[(size_t)NROWS*HID];         // hidden_states split
__device__ __nv_bfloat16 g_Xlo[(size_t)NROWS*HID];
__device__ __nv_bfloat16 g_Bhi[3][HARM*HID];               // basis q,k,v split
__device__ __nv_bfloat16 g_Blo[3][HARM*HID];
__device__ __nv_bfloat16 g_Thi[(size_t)NHEAD*NROWS*HARM];  // [h][row][c]
__device__ __nv_bfloat16 g_Tlo[(size_t)NHEAD*NROWS*HARM];
__device__ __nv_bfloat16 g_Khi[NROWS*HARM];                // [row][a]
__device__ __nv_bfloat16 g_Klo[NROWS*HARM];
__device__ __nv_bfloat16 g_VThi[(size_t)HARM*NROWS];       // [c][row]
__device__ __nv_bfloat16 g_VTlo[(size_t)HARM*NROWS];       // [c][row]

// ---------------- f32x2 / misc helpers ----------------
__device__ __forceinline__ ull ffma2(ull a, ull b, ull c) {
    ull d; asm("fma.rn.f32x2 %0, %1, %2, %3;" : "=l"(d) : "l"(a), "l"(b), "l"(c)); return d;
}
__device__ __forceinline__ ull dup2(float v) {
    ull r; asm("mov.b64 %0, {%1, %2};" : "=l"(r) : "f"(v), "f"(v)); return r;
}
__device__ __forceinline__ float2 unpack2(ull v) {
    float2 f; asm("mov.b64 {%0, %1}, %2;" : "=f"(f.x), "=f"(f.y) : "l"(v)); return f;
}
__device__ __forceinline__ float ex2(float x) {
    float y; asm("ex2.approx.ftz.f32 %0, %1;" : "=f"(y) : "f"(x)); return y;
}
__device__ __forceinline__ unsigned bfbits(__nv_bfloat16 h) {
    return (unsigned)*reinterpret_cast<unsigned short*>(&h);
}
__device__ __forceinline__ uint32_t packbf(float x, float y) {
    return bfbits(__float2bfloat16(x)) | (bfbits(__float2bfloat16(y)) << 16);
}
__device__ __forceinline__ uint32_t packres(float x, float y) {
    __nv_bfloat16 hx = __float2bfloat16(x), hy = __float2bfloat16(y);
    return bfbits(__float2bfloat16(x - __bfloat162float(hx))) |
           (bfbits(__float2bfloat16(y - __bfloat162float(hy))) << 16);
}
__device__ __forceinline__ uint32_t s2u(const void* p) {
    uint32_t a; asm("{ .reg .u64 t; cvta.to.shared.u64 t, %1; cvt.u32.u64 %0, t; }" : "=r"(a) : "l"(p)); return a;
}

// mma.sync m16n8k16 bf16 (base PTX)
#define MMA16816(D, A, b0_, b1_) \
    asm volatile("mma.sync.aligned.m16n8k16.row.col.f32.bf16.bf16.f32 " \
        "{%0,%1,%2,%3}, {%4,%5,%6,%7}, {%8,%9}, {%0,%1,%2,%3};" \
        : "+f"((D)[0]), "+f"((D)[1]), "+f"((D)[2]), "+f"((D)[3]) \
        : "r"((A)[0]), "r"((A)[1]), "r"((A)[2]), "r"((A)[3]), "r"(b0_), "r"(b1_))

__device__ __forceinline__ void cpasync16(uint32_t sdst, const void* gsrc) {
    asm volatile("cp.async.cg.shared.global [%0], [%1], 16;" :: "r"(sdst), "l"(gsrc) : "memory");
}
#define CP_COMMIT() asm volatile("cp.async.commit_group;" ::: "memory")
#define CP_WAIT(n)  asm volatile("cp.async.wait_group %0;" :: "n"(n) : "memory")

// ---------------- w = amp * cos(phase) ----------------
__global__ void k_compute_w(const float* __restrict__ pq, const float* __restrict__ aq,
                            const float* __restrict__ pk, const float* __restrict__ ak,
                            const float* __restrict__ pv, const float* __restrict__ av,
                            const float* __restrict__ po, const float* __restrict__ ao)
{
    int i = blockIdx.x * blockDim.x + threadIdx.x;
    if (i < HID * HARM) {
        g_w[0][i] = aq[i] * cosf(pq[i]);
        g_w[1][i] = ak[i] * cosf(pk[i]);
        g_w[2][i] = av[i] * cosf(pv[i]);
        g_w[3][i] = ao[i] * cosf(po[i]);
    }
}

// ---------------- prep: Mt (log2e*scale, transposed) and Nt ----------------
__global__ __launch_bounds__(256) void k_prep(const float* __restrict__ basis_o)
{
    __shared__ float As[32][65];
    __shared__ float Bs[32][65];
    const int h = blockIdx.x;
    const int z = blockIdx.y;
    const int tid = threadIdx.x;
    const int tx = tid & 15;
    const int ty = tid >> 4;

    float acc[4][4] = {};
    for (int dc = 0; dc < 128; dc += 32) {
        __syncthreads();
        if (z == 0) {
            int d = tid >> 3, a0 = (tid & 7) * 8;
            #pragma unroll
            for (int j = 0; j < 8; j++) {
                As[d][a0 + j] = g_w[0][(h * 128 + dc + d) * 64 + a0 + j];
                Bs[d][a0 + j] = g_w[1][(h * 128 + dc + d) * 64 + a0 + j];
            }
        } else {
            int d = tid >> 3, a0 = (tid & 7) * 8;
            #pragma unroll
            for (int j = 0; j < 8; j++)
                As[d][a0 + j] = g_w[2][(h * 128 + dc + d) * 64 + a0 + j];
            int c = tid >> 2, d0 = (tid & 3) * 8;
            #pragma unroll
            for (int j = 0; j < 8; j++)
                Bs[d0 + j][c] = basis_o[c * 2048 + h * 128 + dc + d0 + j];
        }
        __syncthreads();
        #pragma unroll 8
        for (int d = 0; d < 32; d++) {
            float a[4], b[4];
            #pragma unroll
            for (int i = 0; i < 4; i++) a[i] = As[d][ty * 4 + i];
            #pragma unroll
            for (int j = 0; j < 4; j++) b[j] = Bs[d][tx * 4 + j];
            #pragma unroll
            for (int i = 0; i < 4; i++)
                #pragma unroll
                for (int j = 0; j < 4; j++)
                    acc[i][j] += a[i] * b[j];
        }
    }
    const float scale = 0.08838834764831845f * 1.4426950408889634f;
    if (z == 0) {
        #pragma unroll
        for (int i = 0; i < 4; i++)
            #pragma unroll
            for (int j = 0; j < 4; j++)
                g_Mt[h * 4096 + (tx * 4 + j) * 64 + (ty * 4 + i)] = acc[i][j] * scale;
    } else {
        #pragma unroll
        for (int i = 0; i < 4; i++)
            #pragma unroll
            for (int j = 0; j < 4; j++)
                g_Nt[(tx * 4 + j) * 1024 + h * 64 + ty * 4 + i] = acc[i][j];
    }
}

// ---------------- input splits ----------------
__global__ void k_splitX(const float* __restrict__ hs)
{
    int i = blockIdx.x * blockDim.x + threadIdx.x;
    if (i < NROWS * HID / 4) {
        float4 v = ((const float4*)hs)[i];
        uint2 hh, ll;
        hh.x = packbf(v.x, v.y);  hh.y = packbf(v.z, v.w);
        ll.x = packres(v.x, v.y); ll.y = packres(v.z, v.w);
        *(uint2*)&g_Xhi[(size_t)i * 4] = hh;
        *(uint2*)&g_Xlo[(size_t)i * 4] = ll;
    }
}
__global__ void k_splitB(const float* __restrict__ b0,
                         const float* __restrict__ b1,
                         const float* __restrict__ b2)
{
    int i = blockIdx.x * blockDim.x + threadIdx.x;
    int z = blockIdx.y;
    const float* B = (z == 0) ? b0 : (z == 1) ? b1 : b2;
    if (i < HARM * HID / 4) {
        float4 v = ((const float4*)B)[i];
        uint2 hh, ll;
        hh.x = packbf(v.x, v.y);  hh.y = packbf(v.z, v.w);
        ll.x = packres(v.x, v.y); ll.y = packres(v.z, v.w);
        *(uint2*)&g_Bhi[z][i * 4] = hh;
        *(uint2*)&g_Blo[z][i * 4] = ll;
    }
}

// ---------------- resonance via mma.sync: res_z = X @ basis_z^T ----------------
// grid (NROWS/64, 3), 256 thr / 8 warps. Warp: rows (w&3)*16, cols (w>>2)*32.
// Fused epilogue: z=0 -> g_res[0] fp32; z=1 -> Khi/Klo; z=2 -> VThi/VTlo (transposed).
#define RSTRIDE 72
#define RARR (64*RSTRIDE)
#define RSTAGE (4*RARR)
#define RES_SMEM (2*RSTAGE*2)   // 73728 bytes

__global__ __launch_bounds__(256) void k_res_mma()
{
    extern __shared__ __nv_bfloat16 rsm[];
    const int tid = threadIdx.x;
    const int lane = tid & 31, w = tid >> 5;
    const int rt = blockIdx.x, z = blockIdx.y;
    const int r0 = rt * 64;
    const int qr = lane >> 2, qk = (lane & 3) * 2;
    const int wr = (w & 3) * 16;
    const int wn = (w >> 2) * 32;

    const __nv_bfloat16* Bh = g_Bhi[z];
    const __nv_bfloat16* Bl = g_Blo[z];

    const int sarr = tid >> 6, srow = tid & 63;
    const uint32_t sbase[2] = { s2u(rsm + 0 * RSTAGE + sarr * RARR + srow * RSTRIDE),
                                s2u(rsm + 1 * RSTAGE + sarr * RARR + srow * RSTRIDE) };
    auto stage = [&](int kc64, int s) {
        size_t k0 = (size_t)kc64 * 64;
        const char* src;
        if (sarr == 0)      src = (const char*)(g_Xhi + (size_t)(r0 + srow) * HID + k0);
        else if (sarr == 1) src = (const char*)(g_Xlo + (size_t)(r0 + srow) * HID + k0);
        else if (sarr == 2) src = (const char*)(Bh + (size_t)srow * HID + k0);
        else                src = (const char*)(Bl + (size_t)srow * HID + k0);
        uint32_t d = sbase[s];
        #pragma unroll
        for (int j = 0; j < 8; j++)
            cpasync16(d + j * 16, src + j * 16);
    };

    float acc[4][4] = {};
    stage(0, 0); CP_COMMIT();
    for (int kc64 = 0; kc64 < HID / 64; kc64++) {
        if (kc64 + 1 < HID / 64) { stage(kc64 + 1, (kc64 + 1) & 1); CP_COMMIT(); CP_WAIT(1); }
        else                     { CP_WAIT(0); }
        __syncthreads();
        const __nv_bfloat16* Xh = rsm + (kc64 & 1) * RSTAGE;
        const __nv_bfloat16* Xl = Xh + RARR;
        const __nv_bfloat16* Bsh = Xh + 2 * RARR;
        const __nv_bfloat16* Bsl = Xh + 3 * RARR;
        #pragma unroll
        for (int kc = 0; kc < 4; kc++) {
            uint32_t ahi[4], alo[4];
            const __nv_bfloat16* xp = Xh + (wr + qr) * RSTRIDE + 16 * kc + qk;
            const __nv_bfloat16* xp2 = Xl + (wr + qr) * RSTRIDE + 16 * kc + qk;
            ahi[0] = *(const uint32_t*)xp;
            ahi[1] = *(const uint32_t*)(xp + 8 * RSTRIDE);
            ahi[2] = *(const uint32_t*)(xp + 8);
            ahi[3] = *(const uint32_t*)(xp + 8 * RSTRIDE + 8);
            alo[0] = *(const uint32_t*)xp2;
            alo[1] = *(const uint32_t*)(xp2 + 8 * RSTRIDE);
            alo[2] = *(const uint32_t*)(xp2 + 8);
            alo[3] = *(const uint32_t*)(xp2 + 8 * RSTRIDE + 8);
            #pragma unroll
            for (int n = 0; n < 4; n++) {
                const __nv_bfloat16* bp = Bsh + (wn + n * 8 + qr) * RSTRIDE + 16 * kc + qk;
                uint32_t b0 = *(const uint32_t*)bp;
                uint32_t b1 = *(const uint32_t*)(bp + 8);
                MMA16816(acc[n], ahi, b0, b1);
                MMA16816(acc[n], alo, b0, b1);
                const __nv_bfloat16* bp2 = Bsl + (wn + n * 8 + qr) * RSTRIDE + 16 * kc + qk;
                uint32_t c0 = *(const uint32_t*)bp2;
                uint32_t c1 = *(const uint32_t*)(bp2 + 8);
                MMA16816(acc[n], ahi, c0, c1);
            }
        }
        __syncthreads();
    }

    if (z == 0) {
        float* C  = g_res[0] + (size_t)(r0 + wr + qr) * 64 + wn;
        float* C2 = C + (size_t)8 * 64;
        #pragma unroll
        for (int n = 0; n < 4; n++) {
            *(float2*)&C[n * 8 + qk]  = make_float2(acc[n][0], acc[n][1]);
            *(float2*)&C2[n * 8 + qk] = make_float2(acc[n][2], acc[n][3]);
        }
    } else if (z == 1) {
        int row = r0 + wr + qr;
        #pragma unroll
        for (int n = 0; n < 4; n++) {
            *(uint32_t*)&g_Khi[row * 64 + wn + n * 8 + qk]       = packbf(acc[n][0], acc[n][1]);
            *(uint32_t*)&g_Klo[row * 64 + wn + n * 8 + qk]       = packres(acc[n][0], acc[n][1]);
            *(uint32_t*)&g_Khi[(row + 8) * 64 + wn + n * 8 + qk] = packbf(acc[n][2], acc[n][3]);
            *(uint32_t*)&g_Klo[(row + 8) * 64 + wn + n * 8 + qk] = packres(acc[n][2], acc[n][3]);
        }
    } else {
        float* F = (float*)rsm;   // [64][68] fp32, fits in stage smem
        #pragma unroll
        for (int n = 0; n < 4; n++) {
            F[(wr + qr) * 68 + wn + n * 8 + qk]       = acc[n][0];
            F[(wr + qr) * 68 + wn + n * 8 + qk + 1]   = acc[n][1];
            F[(wr + qr + 8) * 68 + wn + n * 8 + qk]     = acc[n][2];
            F[(wr + qr + 8) * 68 + wn + n * 8 + qk + 1] = acc[n][3];
        }
        __syncthreads();
        int r = tid & 63;
        int c0 = (tid >> 6) * 16;
        #pragma unroll
        for (int cc = 0; cc < 16; cc++) {
            int c = c0 + cc;
            float v = F[r * 68 + c];
            __nv_bfloat16 hi = __float2bfloat16(v);
            g_VThi[(size_t)c * NROWS + r0 + r] = hi;
            g_VTlo[(size_t)c * NROWS + r0 + r] = __float2bfloat16(v - __bfloat162float(hi));
        }
    }
}

// ---------------- 64x64-tile f32x2 GEMM partial (resO) ----------------
__device__ __forceinline__ void gemm64F2(const float* __restrict__ A,
                                         const float* __restrict__ B,
                                         float* __restrict__ C,
                                         int Klen, int lda, int ldb)
{
    __shared__ float As[64 * 36];
    __shared__ float BsT[32 * 68];
    const int tid = threadIdx.x;
    const int tx = tid & 15;
    const int ty = tid >> 4;
    const float* Ab = A + (size_t)blockIdx.x * 64 * lda;

    ull acc[4][2] = {};
    for (int k0 = 0; k0 < Klen; k0 += 32) {
        __syncthreads();
        {
            int c = (tid & 7) * 4;
            int r = tid >> 3;
            *(float4*)&As[r * 36 + c]        = *(const float4*)&Ab[(size_t)r * lda + k0 + c];
            *(float4*)&As[(r + 32) * 36 + c] = *(const float4*)&Ab[(size_t)(r + 32) * lda + k0 + c];
            int n = tid >> 2, kk0 = (tid & 3) * 8;
            #pragma unroll
            for (int j = 0; j < 8; j++)
                BsT[(kk0 + j) * 68 + n] = B[(size_t)n * ldb + k0 + kk0 + j];
        }
        __syncthreads();
        #pragma unroll 4
        for (int kk = 0; kk < 32; kk++) {
            float a[4];
            #pragma unroll
            for (int i = 0; i < 4; i++) a[i] = As[(ty * 4 + i) * 36 + kk];
            ull b0 = *(const ull*)&BsT[kk * 68 + tx * 4];
            ull b1 = *(const ull*)&BsT[kk * 68 + tx * 4 + 2];
            #pragma unroll
            for (int i = 0; i < 4; i++) {
                ull ad = dup2(a[i]);
                acc[i][0] = ffma2(ad, b0, acc[i][0]);
                acc[i][1] = ffma2(ad, b1, acc[i][1]);
            }
        }
    }
    #pragma unroll
    for (int i = 0; i < 4; i++) {
        size_t row = blockIdx.x * 64 + ty * 4 + i;
        *(float2*)&C[row * 64 + tx * 4]     = unpack2(acc[i][0]);
        *(float2*)&C[row * 64 + tx * 4 + 2] = unpack2(acc[i][1]);
    }
}

__global__ __launch_bounds__(256) void k_resO_part()
{
    const int ks = blockIdx.y;
    gemm64F2(g_U + ks * 256, g_Nt + ks * 256, g_resoP[ks], 256, NHEAD * HARM, NHEAD * HARM);
}
__global__ void k_resO_combine()
{
    int i = blockIdx.x * blockDim.x + threadIdx.x;
    const int N4 = NROWS * HARM / 4;
    if (i < N4) {
        float4 a = ((const float4*)g_resoP[0])[i];
        float4 b = ((const float4*)g_resoP[1])[i];
        float4 c = ((const float4*)g_resoP[2])[i];
        float4 d = ((const float4*)g_resoP[3])[i];
        ((float4*)g_reso)[i] = make_float4(a.x + b.x + c.x + d.x, a.y + b.y + c.y + d.y,
                                           a.z + b.z + c.z + d.z, a.w + b.w + c.w + d.w);
    }
}

// ---------------- 128x64-tile f32x2 GEMM (final output) ----------------
__device__ __forceinline__ void gemmF2(const float* __restrict__ A,
                                       const float* __restrict__ B,
                                       float* __restrict__ C,
                                       int K, int lda, int ldb, int ldc)
{
    __shared__ float As[128 * 36];
    __shared__ float BsT[32 * 68];
    const int tid = threadIdx.x;
    const int tx = tid & 15;
    const int ty = tid >> 4;
    const float* Ab = A + (size_t)blockIdx.x * 128 * lda;
    const float* Bb = B + (size_t)blockIdx.y * 64 * ldb;

    ull acc[8][2] = {};
    for (int k0 = 0; k0 < K; k0 += 32) {
        __syncthreads();
        {
            int c = (tid & 7) * 4;
            #pragma unroll
            for (int p = 0; p < 4; p++) {
                int r = (tid >> 3) + p * 32;
                *(float4*)&As[r * 36 + c] = *(const float4*)&Ab[(size_t)r * lda + k0 + c];
            }
            int n = tid >> 2, kk0 = (tid & 3) * 8;
            #pragma unroll
            for (int j = 0; j < 8; j++)
                BsT[(kk0 + j) * 68 + n] = Bb[(size_t)n * ldb + k0 + kk0 + j];
        }
        __syncthreads();
        #pragma unroll 4
        for (int kk = 0; kk < 32; kk++) {
            float a[8];
            #pragma unroll
            for (int i = 0; i < 8; i++) a[i] = As[(ty * 8 + i) * 36 + kk];
            ull b0 = *(const ull*)&BsT[kk * 68 + tx * 4];
            ull b1 = *(const ull*)&BsT[kk * 68 + tx * 4 + 2];
            #pragma unroll
            for (int i = 0; i < 8; i++) {
                ull ad = dup2(a[i]);
                acc[i][0] = ffma2(ad, b0, acc[i][0]);
                acc[i][1] = ffma2(ad, b1, acc[i][1]);
            }
        }
    }
    #pragma unroll
    for (int i = 0; i < 8; i++) {
        size_t row = blockIdx.x * 128 + ty * 8 + i;
        *(float2*)&C[row * ldc + blockIdx.y * 64 + tx * 4]     = unpack2(acc[i][0]);
        *(float2*)&C[row * ldc + blockIdx.y * 64 + tx * 4 + 2] = unpack2(acc[i][1]);
    }
}

__global__ __launch_bounds__(256) void k_out(float* __restrict__ out)
{
    gemmF2(g_reso, g_w[3], out, HARM, HARM, HARM, HID);
}

// ---------------- T split prep ----------------
__global__ __launch_bounds__(256) void k_splitT()
{
    __shared__ float As[64 * 68];
    __shared__ float Bs[64 * 68];
    const int bx = blockIdx.x, h = blockIdx.y;
    const int tid = threadIdx.x;
    const int tx = tid & 15;
    const int ty = tid >> 4;
    {
        int r = tid >> 2, a0 = (tid & 3) * 16;
        const float* Aq = g_res[0] + (size_t)(bx * 64) * 64;
        const float* Bm = g_Mt + h * 4096;
        #pragma unroll
        for (int q = 0; q < 4; q++) {
            *(float4*)&As[r * 68 + a0 + q * 4] = *(const float4*)&Aq[r * 64 + a0 + q * 4];
            *(float4*)&Bs[r * 68 + a0 + q * 4] = *(const float4*)&Bm[r * 64 + a0 + q * 4];
        }
    }
    __syncthreads();
    float acc[4][4] = {};
    #pragma unroll 8
    for (int a = 0; a < 64; a++) {
        float av[4], bv[4];
        #pragma unroll
        for (int i = 0; i < 4; i++) av[i] = As[(ty * 4 + i) * 68 + a];
        #pragma unroll
        for (int j = 0; j < 4; j++) bv[j] = Bs[(tx * 4 + j) * 68 + a];
        #pragma unroll
        for (int i = 0; i < 4; i++)
            #pragma unroll
            for (int j = 0; j < 4; j++)
                acc[i][j] += av[i] * bv[j];
    }
    #pragma unroll
    for (int i = 0; i < 4; i++)
        #pragma unroll
        for (int j = 0; j < 4; j++) {
            float x = acc[i][j];
            size_t o = (size_t)h * NROWS * 64 + (size_t)(bx * 64 + ty * 4 + i) * 64 + tx * 4 + j;
            __nv_bfloat16 hi = __float2bfloat16(x);
            g_Thi[o] = hi;
            g_Tlo[o] = __float2bfloat16(x - __bfloat162float(hi));
        }
}

// ---------------- FA2-style mma.sync attention (unchanged from R12) ----------------
#define STRIDE 72
#define ARRB   (64 * STRIDE)
#define STAGEB (4 * ARRB)
#define ATTN_SMEM (2 * STAGEB * 2)

__global__ __launch_bounds__(256, 1) void k_attn6()
{
    extern __shared__ __nv_bfloat16 smb[];
    const int tid = threadIdx.x;
    const int lane = tid & 31, w = tid >> 5;
    const int qt = blockIdx.x, h = blockIdx.y, b = blockIdx.z;
    const int qrow0 = b * SEQ + qt * 128;
    const size_t bSEQ = (size_t)b * SEQ;
    const int qr = lane >> 2;
    const int qk = (lane & 3) * 2;

    uint32_t tahi[4][4], talo[4][4];
    {
        const __nv_bfloat16* Th = g_Thi + ((size_t)h * NROWS + qrow0 + w * 16 + qr) * 64;
        const __nv_bfloat16* Tl = g_Tlo + ((size_t)h * NROWS + qrow0 + w * 16 + qr) * 64;
        #pragma unroll
        for (int kc = 0; kc < 4; kc++) {
            tahi[kc][0] = *(const uint32_t*)&Th[16 * kc + qk];
            tahi[kc][1] = *(const uint32_t*)&Th[8 * 64 + 16 * kc + qk];
            tahi[kc][2] = *(const uint32_t*)&Th[16 * kc + qk + 8];
            tahi[kc][3] = *(const uint32_t*)&Th[8 * 64 + 16 * kc + qk + 8];
            talo[kc][0] = *(const uint32_t*)&Tl[16 * kc + qk];
            talo[kc][1] = *(const uint32_t*)&Tl[8 * 64 + 16 * kc + qk];
            talo[kc][2] = *(const uint32_t*)&Tl[16 * kc + qk + 8];
            talo[kc][3] = *(const uint32_t*)&Tl[8 * 64 + 16 * kc + qk + 8];
        }
    }

    const int sarr = tid >> 6;
    const int srow = tid & 63;
    const uint32_t sdstBase[2] = {
        s2u(smb + 0 * STAGEB + sarr * ARRB + srow * STRIDE),
        s2u(smb + 1 * STAGEB + sarr * ARRB + srow * STRIDE)
    };
    auto stage = [&](int t, int s) {
        const char* src;
        if (sarr == 0)      src = (const char*)(g_Khi  + (bSEQ + t * 64 + srow) * 64);
        else if (sarr == 1) src = (const char*)(g_Klo  + (bSEQ + t * 64 + srow) * 64);
        else if (sarr == 2) src = (const char*)(g_VThi + (size_t)srow * NROWS + bSEQ + t * 64);
        else                src = (const char*)(g_VTlo + (size_t)srow * NROWS + bSEQ + t * 64);
        uint32_t d = sdstBase[s];
        #pragma unroll
        for (int j = 0; j < 8; j++)
            cpasync16(d + j * 16, src + j * 16);
    };

    float U[8][4];
    #pragma unroll
    for (int n = 0; n < 8; n++)
        #pragma unroll
        for (int e = 0; e < 4; e++) U[n][e] = 0.0f;
    float mA = -1e30f, mB = -1e30f, lA = 0.0f, lB = 0.0f;

    stage(0, 0); CP_COMMIT();

    for (int t = 0; t < NTILE; t++) {
        if (t + 1 < NTILE) { stage(t + 1, (t + 1) & 1); CP_COMMIT(); CP_WAIT(1); }
        else               { CP_WAIT(0); }
        __syncthreads();

        const __nv_bfloat16* Kh = smb + (t & 1) * STAGEB;
        const __nv_bfloat16* Kl = Kh + ARRB;
        const __nv_bfloat16* Vh = Kh + 2 * ARRB;
        const __nv_bfloat16* Vl = Kh + 3 * ARRB;

        float S[8][4];
        #pragma unroll
        for (int n = 0; n < 8; n++)
            #pragma unroll
            for (int e = 0; e < 4; e++) S[n][e] = 0.0f;
        #pragma unroll
        for (int n = 0; n < 8; n++) {
            #pragma unroll
            for (int kc = 0; kc < 4; kc++) {
                const __nv_bfloat16* kp = Kh + (n * 8 + qr) * STRIDE + 16 * kc + qk;
                uint32_t b0 = *(const uint32_t*)kp;
                uint32_t b1 = *(const uint32_t*)(kp + 8);
                MMA16816(S[n], tahi[kc], b0, b1);
                MMA16816(S[n], talo[kc], b0, b1);
                const __nv_bfloat16* kp2 = Kl + (n * 8 + qr) * STRIDE + 16 * kc + qk;
                uint32_t c0 = *(const uint32_t*)kp2;
                uint32_t c1 = *(const uint32_t*)(kp2 + 8);
                MMA16816(S[n], tahi[kc], c0, c1);
            }
        }

        float rmA = -1e30f, rmB = -1e30f;
        #pragma unroll
        for (int n = 0; n < 8; n++) {
            rmA = fmaxf(rmA, fmaxf(S[n][0], S[n][1]));
            rmB = fmaxf(rmB, fmaxf(S[n][2], S[n][3]));
        }
        rmA = fmaxf(rmA, __shfl_xor_sync(0xffffffffu, rmA, 1));
        rmA = fmaxf(rmA, __shfl_xor_sync(0xffffffffu, rmA, 2));
        rmB = fmaxf(rmB, __shfl_xor_sync(0xffffffffu, rmB, 1));
        rmB = fmaxf(rmB, __shfl_xor_sync(0xffffffffu, rmB, 2));
        float mnA = fmaxf(mA, rmA), mnB = fmaxf(mB, rmB);
        float cA = ex2(mA - mnA), cB = ex2(mB - mnB);
        mA = mnA; mB = mnB;

        uint32_t pahi[4][4], palo[4][4];
        float sA = 0.0f, sB = 0.0f;
        #pragma unroll
        for (int kc2 = 0; kc2 < 4; kc2++) {
            int n0 = 2 * kc2, n1 = 2 * kc2 + 1;
            float p00 = ex2(S[n0][0] - mnA), p01 = ex2(S[n0][1] - mnA);
            float p10 = ex2(S[n0][2] - mnB), p11 = ex2(S[n0][3] - mnB);
            float p20 = ex2(S[n1][0] - mnA), p21 = ex2(S[n1][1] - mnA);
            float p30 = ex2(S[n1][2] - mnB), p31 = ex2(S[n1][3] - mnB);
            sA += (p00 + p01) + (p20 + p21);
            sB += (p10 + p11) + (p30 + p31);
            pahi[kc2][0] = packbf(p00, p01);  palo[kc2][0] = packres(p00, p01);
            pahi[kc2][1] = packbf(p10, p11);  palo[kc2][1] = packres(p10, p11);
            pahi[kc2][2] = packbf(p20, p21);  palo[kc2][2] = packres(p20, p21);
            pahi[kc2][3] = packbf(p30, p31);  palo[kc2][3] = packres(p30, p31);
        }
        lA = lA * cA + sA;
        lB = lB * cB + sB;
        #pragma unroll
        for (int n = 0; n < 8; n++) {
            U[n][0] *= cA; U[n][1] *= cA;
            U[n][2] *= cB; U[n][3] *= cB;
        }

        #pragma unroll
        for (int n2 = 0; n2 < 8; n2++) {
            #pragma unroll
            for (int kc2 = 0; kc2 < 4; kc2++) {
                const __nv_bfloat16* vp = Vh + (n2 * 8 + qr) * STRIDE + 16 * kc2 + qk;
                uint32_t b0 = *(const uint32_t*)vp;
                uint32_t b1 = *(const uint32_t*)(vp + 8);
                MMA16816(U[n2], pahi[kc2], b0, b1);
                MMA16816(U[n2], palo[kc2], b0, b1);
                const __nv_bfloat16* vp2 = Vl + (n2 * 8 + qr) * STRIDE + 16 * kc2 + qk;
                uint32_t c0 = *(const uint32_t*)vp2;
                uint32_t c1 = *(const uint32_t*)(vp2 + 8);
                MMA16816(U[n2], pahi[kc2], c0, c1);
            }
        }
        __syncthreads();
    }

    lA += __shfl_xor_sync(0xffffffffu, lA, 1);
    lA += __shfl_xor_sync(0xffffffffu, lA, 2);
    lB += __shfl_xor_sync(0xffffffffu, lB, 1);
    lB += __shfl_xor_sync(0xffffffffu, lB, 2);
    float iA = 1.0f / lA, iB = 1.0f / lB;
    float* UgA = g_U + (size_t)(qrow0 + w * 16 + qr) * (NHEAD * HARM) + h * 64;
    float* UgB = UgA + (size_t)8 * (NHEAD * HARM);
    #pragma unroll
    for (int n2 = 0; n2 < 8; n2++) {
        *(float2*)&UgA[n2 * 8 + qk] = make_float2(U[n2][0] * iA, U[n2][1] * iA);
        *(float2*)&UgB[n2 * 8 + qk] = make_float2(U[n2][2] * iB, U[n2][3] * iB);
    }
}

// ---------------- launch ----------------
extern "C" void kernel_launch(void* const* d_in, const int* in_sizes, int n_in,
                              void* d_out, int out_size)
{
    (void)in_sizes; (void)n_in; (void)out_size;
    const float* hs      = (const float*)d_in[0];
    const float* basis_q = (const float*)d_in[1];
    const float* phase_q = (const float*)d_in[2];
    const float* amp_q   = (const float*)d_in[3];
    const float* basis_k = (const float*)d_in[4];
    const float* phase_k = (const float*)d_in[5];
    const float* amp_k   = (const float*)d_in[6];
    const float* basis_v = (const float*)d_in[7];
    const float* phase_v = (const float*)d_in[8];
    const float* amp_v   = (const float*)d_in[9];
    const float* basis_o = (const float*)d_in[10];
    const float* phase_o = (const float*)d_in[11];
    const float* amp_o   = (const float*)d_in[12];
    float* out = (float*)d_out;

    cudaFuncSetAttribute(k_attn6, cudaFuncAttributeMaxDynamicSharedMemorySize, ATTN_SMEM);
    cudaFuncSetAttribute(k_res_mma, cudaFuncAttributeMaxDynamicSharedMemorySize, RES_SMEM);

    k_compute_w<<<(HID * HARM + 255) / 256, 256>>>(phase_q, amp_q, phase_k, amp_k,
                                                   phase_v, amp_v, phase_o, amp_o);
    k_prep<<<dim3(NHEAD, 2), 256>>>(basis_o);
    k_splitX<<<(NROWS * HID / 4 + 255) / 256, 256>>>(hs);
    k_splitB<<<dim3((HARM * HID / 4 + 255) / 256, 3), 256>>>(basis_q, basis_k, basis_v);
    k_res_mma<<<dim3(NROWS / 64, 3), 256, RES_SMEM>>>();
    k_splitT<<<dim3(NROWS / 64, NHEAD), 256>>>();
    k_attn6<<<dim3(SEQ / 128, NHEAD, BATCH), 256, ATTN_SMEM>>>();
    k_resO_part<<<dim3(NROWS / 64, 4), 256>>>();
    k_resO_combine<<<(NROWS * HARM / 4 + 255) / 256, 256>>>();
    k_out<<<dim3(NROWS / 128, HID / 64), 256>>>(out);
}

// round 15
// speedup vs baseline: 4.7800x; 1.2594x over previous
#include <cuda_runtime.h>
#include <cuda_fp16.h>
#include <cstdint>
#include <stdint.h>
#include <math.h>

#define HID   2048
#define NHEAD 16
#define DH    128
#define HARM  64
#define BATCH 2
#define SEQ   2048
#define NROWS (BATCH*SEQ)   // 4096
#define NTILE (SEQ/64)      // 32

typedef unsigned long long ull;

// ---------------- device scratch ----------------
__device__ float g_w[4][HID*HARM];
__device__ float g_res[NROWS*HARM];        // Rq fp32
__device__ float g_Mt[NHEAD*HARM*HARM];    // Mt[h][c][a] = log2e*scale*M[a][c]
__device__ float g_Nt[HARM*NHEAD*HARM];
__device__ float g_U[NROWS*NHEAD*HARM];
__device__ float g_reso[NROWS*HARM];
__device__ float g_resoP[4][NROWS*HARM];
// fp16 operands
__device__ __half g_Xhi[(size_t)NROWS*HID];
__device__ __half g_Xlo[(size_t)NROWS*HID];
__device__ __half g_Bhi[3][HARM*HID];
__device__ __half g_Blo[3][HARM*HID];
__device__ __half g_Thi[(size_t)NHEAD*NROWS*HARM];  // [h][row][c]
__device__ __half g_Tlo[(size_t)NHEAD*NROWS*HARM];
__device__ __half g_Khi[NROWS*HARM];                // [row][a]
__device__ __half g_Klo[NROWS*HARM];
__device__ __half g_VT[(size_t)HARM*NROWS];         // [c][row]

// ---------------- helpers ----------------
__device__ __forceinline__ ull ffma2(ull a, ull b, ull c) {
    ull d; asm("fma.rn.f32x2 %0, %1, %2, %3;" : "=l"(d) : "l"(a), "l"(b), "l"(c)); return d;
}
__device__ __forceinline__ ull dup2(float v) {
    ull r; asm("mov.b64 %0, {%1, %2};" : "=l"(r) : "f"(v), "f"(v)); return r;
}
__device__ __forceinline__ float2 unpack2(ull v) {
    float2 f; asm("mov.b64 {%0, %1}, %2;" : "=f"(f.x), "=f"(f.y) : "l"(v)); return f;
}
__device__ __forceinline__ float ex2(float x) {
    float y; asm("ex2.approx.ftz.f32 %0, %1;" : "=f"(y) : "f"(x)); return y;
}
__device__ __forceinline__ unsigned hbits(__half h) {
    return (unsigned)*reinterpret_cast<unsigned short*>(&h);
}
__device__ __forceinline__ uint32_t packh(float x, float y) {
    return hbits(__float2half(x)) | (hbits(__float2half(y)) << 16);
}
__device__ __forceinline__ uint32_t packhres(float x, float y) {
    __half hx = __float2half(x), hy = __float2half(y);
    return hbits(__float2half(x - __half2float(hx))) |
           (hbits(__float2half(y - __half2float(hy))) << 16);
}
__device__ __forceinline__ uint32_t s2u(const void* p) {
    uint32_t a; asm("{ .reg .u64 t; cvta.to.shared.u64 t, %1; cvt.u32.u64 %0, t; }" : "=r"(a) : "l"(p)); return a;
}

// mma.sync m16n8k16 fp16 in / fp32 accum (base PTX)
#define MMA16816(D, A, b0_, b1_) \
    asm volatile("mma.sync.aligned.m16n8k16.row.col.f32.f16.f16.f32 " \
        "{%0,%1,%2,%3}, {%4,%5,%6,%7}, {%8,%9}, {%0,%1,%2,%3};" \
        : "+f"((D)[0]), "+f"((D)[1]), "+f"((D)[2]), "+f"((D)[3]) \
        : "r"((A)[0]), "r"((A)[1]), "r"((A)[2]), "r"((A)[3]), "r"(b0_), "r"(b1_))

__device__ __forceinline__ void cpasync16(uint32_t sdst, const void* gsrc) {
    asm volatile("cp.async.cg.shared.global [%0], [%1], 16;" :: "r"(sdst), "l"(gsrc) : "memory");
}
#define CP_COMMIT() asm volatile("cp.async.commit_group;" ::: "memory")
#define CP_WAIT(n)  asm volatile("cp.async.wait_group %0;" :: "n"(n) : "memory")

// ---------------- w = amp * cos(phase) ----------------
__global__ void k_compute_w(const float* __restrict__ pq, const float* __restrict__ aq,
                            const float* __restrict__ pk, const float* __restrict__ ak,
                            const float* __restrict__ pv, const float* __restrict__ av,
                            const float* __restrict__ po, const float* __restrict__ ao)
{
    int i = blockIdx.x * blockDim.x + threadIdx.x;
    if (i < HID * HARM) {
        g_w[0][i] = aq[i] * cosf(pq[i]);
        g_w[1][i] = ak[i] * cosf(pk[i]);
        g_w[2][i] = av[i] * cosf(pv[i]);
        g_w[3][i] = ao[i] * cosf(po[i]);
    }
}

// ---------------- prep: Mt (log2e*scale, transposed) and Nt ----------------
__global__ __launch_bounds__(256) void k_prep(const float* __restrict__ basis_o)
{
    __shared__ float As[32][65];
    __shared__ float Bs[32][65];
    const int h = blockIdx.x;
    const int z = blockIdx.y;
    const int tid = threadIdx.x;
    const int tx = tid & 15;
    const int ty = tid >> 4;

    float acc[4][4] = {};
    for (int dc = 0; dc < 128; dc += 32) {
        __syncthreads();
        if (z == 0) {
            int d = tid >> 3, a0 = (tid & 7) * 8;
            #pragma unroll
            for (int j = 0; j < 8; j++) {
                As[d][a0 + j] = g_w[0][(h * 128 + dc + d) * 64 + a0 + j];
                Bs[d][a0 + j] = g_w[1][(h * 128 + dc + d) * 64 + a0 + j];
            }
        } else {
            int d = tid >> 3, a0 = (tid & 7) * 8;
            #pragma unroll
            for (int j = 0; j < 8; j++)
                As[d][a0 + j] = g_w[2][(h * 128 + dc + d) * 64 + a0 + j];
            int c = tid >> 2, d0 = (tid & 3) * 8;
            #pragma unroll
            for (int j = 0; j < 8; j++)
                Bs[d0 + j][c] = basis_o[c * 2048 + h * 128 + dc + d0 + j];
        }
        __syncthreads();
        #pragma unroll 8
        for (int d = 0; d < 32; d++) {
            float a[4], b[4];
            #pragma unroll
            for (int i = 0; i < 4; i++) a[i] = As[d][ty * 4 + i];
            #pragma unroll
            for (int j = 0; j < 4; j++) b[j] = Bs[d][tx * 4 + j];
            #pragma unroll
            for (int i = 0; i < 4; i++)
                #pragma unroll
                for (int j = 0; j < 4; j++)
                    acc[i][j] += a[i] * b[j];
        }
    }
    const float scale = 0.08838834764831845f * 1.4426950408889634f;
    if (z == 0) {
        #pragma unroll
        for (int i = 0; i < 4; i++)
            #pragma unroll
            for (int j = 0; j < 4; j++)
                g_Mt[h * 4096 + (tx * 4 + j) * 64 + (ty * 4 + i)] = acc[i][j] * scale;
    } else {
        #pragma unroll
        for (int i = 0; i < 4; i++)
            #pragma unroll
            for (int j = 0; j < 4; j++)
                g_Nt[(tx * 4 + j) * 1024 + h * 64 + ty * 4 + i] = acc[i][j];
    }
}

// ---------------- input splits (fp16) ----------------
__global__ void k_splitX(const float* __restrict__ hs)
{
    int i = blockIdx.x * blockDim.x + threadIdx.x;
    if (i < NROWS * HID / 4) {
        float4 v = ((const float4*)hs)[i];
        uint2 hh, ll;
        hh.x = packh(v.x, v.y);   hh.y = packh(v.z, v.w);
        ll.x = packhres(v.x, v.y); ll.y = packhres(v.z, v.w);
        *(uint2*)&g_Xhi[(size_t)i * 4] = hh;
        *(uint2*)&g_Xlo[(size_t)i * 4] = ll;
    }
}
__global__ void k_splitB(const float* __restrict__ b0,
                         const float* __restrict__ b1,
                         const float* __restrict__ b2)
{
    int i = blockIdx.x * blockDim.x + threadIdx.x;
    int z = blockIdx.y;
    const float* B = (z == 0) ? b0 : (z == 1) ? b1 : b2;
    if (i < HARM * HID / 4) {
        float4 v = ((const float4*)B)[i];
        uint2 hh, ll;
        hh.x = packh(v.x, v.y);   hh.y = packh(v.z, v.w);
        ll.x = packhres(v.x, v.y); ll.y = packhres(v.z, v.w);
        *(uint2*)&g_Bhi[z][i * 4] = hh;
        *(uint2*)&g_Blo[z][i * 4] = ll;
    }
}

// ---------------- resonance via mma.sync (fp16): res_z = X @ basis_z^T ----------------
// grid (NROWS/64, 3), 256 thr / 8 warps.
// Epilogue: z=0 -> g_res fp32 (Rq); z=1 -> Khi/Klo fp16; z=2 -> VT fp16 (transposed).
#define RSTRIDE 72
#define RARR (64*RSTRIDE)
#define RSTAGE (4*RARR)
#define RES_SMEM (2*RSTAGE*2)   // 73728 bytes

__global__ __launch_bounds__(256) void k_res_mma()
{
    extern __shared__ __half rsm[];
    const int tid = threadIdx.x;
    const int lane = tid & 31, w = tid >> 5;
    const int rt = blockIdx.x, z = blockIdx.y;
    const int r0 = rt * 64;
    const int qr = lane >> 2, qk = (lane & 3) * 2;
    const int wr = (w & 3) * 16;
    const int wn = (w >> 2) * 32;

    const __half* Bh = g_Bhi[z];
    const __half* Bl = g_Blo[z];

    const int sarr = tid >> 6, srow = tid & 63;
    const uint32_t sbase[2] = { s2u(rsm + 0 * RSTAGE + sarr * RARR + srow * RSTRIDE),
                                s2u(rsm + 1 * RSTAGE + sarr * RARR + srow * RSTRIDE) };
    auto stage = [&](int kc64, int s) {
        size_t k0 = (size_t)kc64 * 64;
        const char* src;
        if (sarr == 0)      src = (const char*)(g_Xhi + (size_t)(r0 + srow) * HID + k0);
        else if (sarr == 1) src = (const char*)(g_Xlo + (size_t)(r0 + srow) * HID + k0);
        else if (sarr == 2) src = (const char*)(Bh + (size_t)srow * HID + k0);
        else                src = (const char*)(Bl + (size_t)srow * HID + k0);
        uint32_t d = sbase[s];
        #pragma unroll
        for (int j = 0; j < 8; j++)
            cpasync16(d + j * 16, src + j * 16);
    };

    float acc[4][4] = {};
    stage(0, 0); CP_COMMIT();
    for (int kc64 = 0; kc64 < HID / 64; kc64++) {
        if (kc64 + 1 < HID / 64) { stage(kc64 + 1, (kc64 + 1) & 1); CP_COMMIT(); CP_WAIT(1); }
        else                     { CP_WAIT(0); }
        __syncthreads();
        const __half* Xh = rsm + (kc64 & 1) * RSTAGE;
        const __half* Xl = Xh + RARR;
        const __half* Bsh = Xh + 2 * RARR;
        const __half* Bsl = Xh + 3 * RARR;
        #pragma unroll
        for (int kc = 0; kc < 4; kc++) {
            uint32_t ahi[4], alo[4];
            const __half* xp = Xh + (wr + qr) * RSTRIDE + 16 * kc + qk;
            const __half* xp2 = Xl + (wr + qr) * RSTRIDE + 16 * kc + qk;
            ahi[0] = *(const uint32_t*)xp;
            ahi[1] = *(const uint32_t*)(xp + 8 * RSTRIDE);
            ahi[2] = *(const uint32_t*)(xp + 8);
            ahi[3] = *(const uint32_t*)(xp + 8 * RSTRIDE + 8);
            alo[0] = *(const uint32_t*)xp2;
            alo[1] = *(const uint32_t*)(xp2 + 8 * RSTRIDE);
            alo[2] = *(const uint32_t*)(xp2 + 8);
            alo[3] = *(const uint32_t*)(xp2 + 8 * RSTRIDE + 8);
            #pragma unroll
            for (int n = 0; n < 4; n++) {
                const __half* bp = Bsh + (wn + n * 8 + qr) * RSTRIDE + 16 * kc + qk;
                uint32_t b0 = *(const uint32_t*)bp;
                uint32_t b1 = *(const uint32_t*)(bp + 8);
                MMA16816(acc[n], ahi, b0, b1);
                MMA16816(acc[n], alo, b0, b1);
                const __half* bp2 = Bsl + (wn + n * 8 + qr) * RSTRIDE + 16 * kc + qk;
                uint32_t c0 = *(const uint32_t*)bp2;
                uint32_t c1 = *(const uint32_t*)(bp2 + 8);
                MMA16816(acc[n], ahi, c0, c1);
            }
        }
        __syncthreads();
    }

    if (z == 0) {
        float* C  = g_res + (size_t)(r0 + wr + qr) * 64 + wn;
        float* C2 = C + (size_t)8 * 64;
        #pragma unroll
        for (int n = 0; n < 4; n++) {
            *(float2*)&C[n * 8 + qk]  = make_float2(acc[n][0], acc[n][1]);
            *(float2*)&C2[n * 8 + qk] = make_float2(acc[n][2], acc[n][3]);
        }
    } else if (z == 1) {
        int row = r0 + wr + qr;
        #pragma unroll
        for (int n = 0; n < 4; n++) {
            *(uint32_t*)&g_Khi[row * 64 + wn + n * 8 + qk]       = packh(acc[n][0], acc[n][1]);
            *(uint32_t*)&g_Klo[row * 64 + wn + n * 8 + qk]       = packhres(acc[n][0], acc[n][1]);
            *(uint32_t*)&g_Khi[(row + 8) * 64 + wn + n * 8 + qk] = packh(acc[n][2], acc[n][3]);
            *(uint32_t*)&g_Klo[(row + 8) * 64 + wn + n * 8 + qk] = packhres(acc[n][2], acc[n][3]);
        }
    } else {
        float* F = (float*)rsm;   // [64][68] fp32 scratch
        #pragma unroll
        for (int n = 0; n < 4; n++) {
            F[(wr + qr) * 68 + wn + n * 8 + qk]         = acc[n][0];
            F[(wr + qr) * 68 + wn + n * 8 + qk + 1]     = acc[n][1];
            F[(wr + qr + 8) * 68 + wn + n * 8 + qk]     = acc[n][2];
            F[(wr + qr + 8) * 68 + wn + n * 8 + qk + 1] = acc[n][3];
        }
        __syncthreads();
        int r = tid & 63;
        int c0 = (tid >> 6) * 16;
        #pragma unroll
        for (int cc = 0; cc < 16; cc++) {
            int c = c0 + cc;
            g_VT[(size_t)c * NROWS + r0 + r] = __float2half(F[r * 68 + c]);
        }
    }
}

// ---------------- 64x64-tile f32x2 GEMM partial (resO) ----------------
__device__ __forceinline__ void gemm64F2(const float* __restrict__ A,
                                         const float* __restrict__ B,
                                         float* __restrict__ C,
                                         int Klen, int lda, int ldb)
{
    __shared__ float As[64 * 36];
    __shared__ float BsT[32 * 68];
    const int tid = threadIdx.x;
    const int tx = tid & 15;
    const int ty = tid >> 4;
    const float* Ab = A + (size_t)blockIdx.x * 64 * lda;

    ull acc[4][2] = {};
    for (int k0 = 0; k0 < Klen; k0 += 32) {
        __syncthreads();
        {
            int c = (tid & 7) * 4;
            int r = tid >> 3;
            *(float4*)&As[r * 36 + c]        = *(const float4*)&Ab[(size_t)r * lda + k0 + c];
            *(float4*)&As[(r + 32) * 36 + c] = *(const float4*)&Ab[(size_t)(r + 32) * lda + k0 + c];
            int n = tid >> 2, kk0 = (tid & 3) * 8;
            #pragma unroll
            for (int j = 0; j < 8; j++)
                BsT[(kk0 + j) * 68 + n] = B[(size_t)n * ldb + k0 + kk0 + j];
        }
        __syncthreads();
        #pragma unroll 4
        for (int kk = 0; kk < 32; kk++) {
            float a[4];
            #pragma unroll
            for (int i = 0; i < 4; i++) a[i] = As[(ty * 4 + i) * 36 + kk];
            ull b0 = *(const ull*)&BsT[kk * 68 + tx * 4];
            ull b1 = *(const ull*)&BsT[kk * 68 + tx * 4 + 2];
            #pragma unroll
            for (int i = 0; i < 4; i++) {
                ull ad = dup2(a[i]);
                acc[i][0] = ffma2(ad, b0, acc[i][0]);
                acc[i][1] = ffma2(ad, b1, acc[i][1]);
            }
        }
    }
    #pragma unroll
    for (int i = 0; i < 4; i++) {
        size_t row = blockIdx.x * 64 + ty * 4 + i;
        *(float2*)&C[row * 64 + tx * 4]     = unpack2(acc[i][0]);
        *(float2*)&C[row * 64 + tx * 4 + 2] = unpack2(acc[i][1]);
    }
}

__global__ __launch_bounds__(256) void k_resO_part()
{
    const int ks = blockIdx.y;
    gemm64F2(g_U + ks * 256, g_Nt + ks * 256, g_resoP[ks], 256, NHEAD * HARM, NHEAD * HARM);
}
__global__ void k_resO_combine()
{
    int i = blockIdx.x * blockDim.x + threadIdx.x;
    const int N4 = NROWS * HARM / 4;
    if (i < N4) {
        float4 a = ((const float4*)g_resoP[0])[i];
        float4 b = ((const float4*)g_resoP[1])[i];
        float4 c = ((const float4*)g_resoP[2])[i];
        float4 d = ((const float4*)g_resoP[3])[i];
        ((float4*)g_reso)[i] = make_float4(a.x + b.x + c.x + d.x, a.y + b.y + c.y + d.y,
                                           a.z + b.z + c.z + d.z, a.w + b.w + c.w + d.w);
    }
}

// ---------------- 128x64-tile f32x2 GEMM (final output) ----------------
__device__ __forceinline__ void gemmF2(const float* __restrict__ A,
                                       const float* __restrict__ B,
                                       float* __restrict__ C,
                                       int K, int lda, int ldb, int ldc)
{
    __shared__ float As[128 * 36];
    __shared__ float BsT[32 * 68];
    const int tid = threadIdx.x;
    const int tx = tid & 15;
    const int ty = tid >> 4;
    const float* Ab = A + (size_t)blockIdx.x * 128 * lda;
    const float* Bb = B + (size_t)blockIdx.y * 64 * ldb;

    ull acc[8][2] = {};
    for (int k0 = 0; k0 < K; k0 += 32) {
        __syncthreads();
        {
            int c = (tid & 7) * 4;
            #pragma unroll
            for (int p = 0; p < 4; p++) {
                int r = (tid >> 3) + p * 32;
                *(float4*)&As[r * 36 + c] = *(const float4*)&Ab[(size_t)r * lda + k0 + c];
            }
            int n = tid >> 2, kk0 = (tid & 3) * 8;
            #pragma unroll
            for (int j = 0; j < 8; j++)
                BsT[(kk0 + j) * 68 + n] = Bb[(size_t)n * ldb + k0 + kk0 + j];
        }
        __syncthreads();
        #pragma unroll 4
        for (int kk = 0; kk < 32; kk++) {
            float a[8];
            #pragma unroll
            for (int i = 0; i < 8; i++) a[i] = As[(ty * 8 + i) * 36 + kk];
            ull b0 = *(const ull*)&BsT[kk * 68 + tx * 4];
            ull b1 = *(const ull*)&BsT[kk * 68 + tx * 4 + 2];
            #pragma unroll
            for (int i = 0; i < 8; i++) {
                ull ad = dup2(a[i]);
                acc[i][0] = ffma2(ad, b0, acc[i][0]);
                acc[i][1] = ffma2(ad, b1, acc[i][1]);
            }
        }
    }
    #pragma unroll
    for (int i = 0; i < 8; i++) {
        size_t row = blockIdx.x * 128 + ty * 8 + i;
        *(float2*)&C[row * ldc + blockIdx.y * 64 + tx * 4]     = unpack2(acc[i][0]);
        *(float2*)&C[row * ldc + blockIdx.y * 64 + tx * 4 + 2] = unpack2(acc[i][1]);
    }
}

__global__ __launch_bounds__(256) void k_out(float* __restrict__ out)
{
    gemmF2(g_reso, g_w[3], out, HARM, HARM, HARM, HID);
}

// ---------------- T split prep (fp16 out) ----------------
__global__ __launch_bounds__(256) void k_splitT()
{
    __shared__ float As[64 * 68];
    __shared__ float Bs[64 * 68];
    const int bx = blockIdx.x, h = blockIdx.y;
    const int tid = threadIdx.x;
    const int tx = tid & 15;
    const int ty = tid >> 4;
    {
        int r = tid >> 2, a0 = (tid & 3) * 16;
        const float* Aq = g_res + (size_t)(bx * 64) * 64;
        const float* Bm = g_Mt + h * 4096;
        #pragma unroll
        for (int q = 0; q < 4; q++) {
            *(float4*)&As[r * 68 + a0 + q * 4] = *(const float4*)&Aq[r * 64 + a0 + q * 4];
            *(float4*)&Bs[r * 68 + a0 + q * 4] = *(const float4*)&Bm[r * 64 + a0 + q * 4];
        }
    }
    __syncthreads();
    float acc[4][4] = {};
    #pragma unroll 8
    for (int a = 0; a < 64; a++) {
        float av[4], bv[4];
        #pragma unroll
        for (int i = 0; i < 4; i++) av[i] = As[(ty * 4 + i) * 68 + a];
        #pragma unroll
        for (int j = 0; j < 4; j++) bv[j] = Bs[(tx * 4 + j) * 68 + a];
        #pragma unroll
        for (int i = 0; i < 4; i++)
            #pragma unroll
            for (int j = 0; j < 4; j++)
                acc[i][j] += av[i] * bv[j];
    }
    #pragma unroll
    for (int i = 0; i < 4; i++)
        #pragma unroll
        for (int j = 0; j < 4; j++) {
            float x = acc[i][j];
            size_t o = (size_t)h * NROWS * 64 + (size_t)(bx * 64 + ty * 4 + i) * 64 + tx * 4 + j;
            __half hi = __float2half(x);
            g_Thi[o] = hi;
            g_Tlo[o] = __float2half(x - __half2float(hi));
        }
}

// ---------------- FA2-style mma.sync attention (fp16, 4 MMA terms) ----------------
// smem per stage: Khi,Klo [64 key][72 feat] + V [64 c][72 key], fp16.
#define STRIDE 72
#define ARRB   (64 * STRIDE)
#define STAGEB (3 * ARRB)
#define ATTN_SMEM (2 * STAGEB * 2)   // 55296 bytes

__global__ __launch_bounds__(256, 1) void k_attn7()
{
    extern __shared__ __half smb[];
    const int tid = threadIdx.x;
    const int lane = tid & 31, w = tid >> 5;
    const int qt = blockIdx.x, h = blockIdx.y, b = blockIdx.z;
    const int qrow0 = b * SEQ + qt * 128;
    const size_t bSEQ = (size_t)b * SEQ;
    const int qr = lane >> 2;
    const int qk = (lane & 3) * 2;

    uint32_t tahi[4][4], talo[4][4];
    {
        const __half* Th = g_Thi + ((size_t)h * NROWS + qrow0 + w * 16 + qr) * 64;
        const __half* Tl = g_Tlo + ((size_t)h * NROWS + qrow0 + w * 16 + qr) * 64;
        #pragma unroll
        for (int kc = 0; kc < 4; kc++) {
            tahi[kc][0] = *(const uint32_t*)&Th[16 * kc + qk];
            tahi[kc][1] = *(const uint32_t*)&Th[8 * 64 + 16 * kc + qk];
            tahi[kc][2] = *(const uint32_t*)&Th[16 * kc + qk + 8];
            tahi[kc][3] = *(const uint32_t*)&Th[8 * 64 + 16 * kc + qk + 8];
            talo[kc][0] = *(const uint32_t*)&Tl[16 * kc + qk];
            talo[kc][1] = *(const uint32_t*)&Tl[8 * 64 + 16 * kc + qk];
            talo[kc][2] = *(const uint32_t*)&Tl[16 * kc + qk + 8];
            talo[kc][3] = *(const uint32_t*)&Tl[8 * 64 + 16 * kc + qk + 8];
        }
    }

    const int sarr = tid >> 6;        // 0..3 (3 = idle)
    const int srow = tid & 63;
    const uint32_t sdstBase[2] = {
        s2u(smb + 0 * STAGEB + (sarr < 3 ? sarr : 0) * ARRB + srow * STRIDE),
        s2u(smb + 1 * STAGEB + (sarr < 3 ? sarr : 0) * ARRB + srow * STRIDE)
    };
    auto stage = [&](int t, int s) {
        if (sarr >= 3) return;
        const char* src;
        if (sarr == 0)      src = (const char*)(g_Khi + (bSEQ + t * 64 + srow) * 64);
        else if (sarr == 1) src = (const char*)(g_Klo + (bSEQ + t * 64 + srow) * 64);
        else                src = (const char*)(g_VT + (size_t)srow * NROWS + bSEQ + t * 64);
        uint32_t d = sdstBase[s];
        #pragma unroll
        for (int j = 0; j < 8; j++)
            cpasync16(d + j * 16, src + j * 16);
    };

    float U[8][4];
    #pragma unroll
    for (int n = 0; n < 8; n++)
        #pragma unroll
        for (int e = 0; e < 4; e++) U[n][e] = 0.0f;
    float mA = -1e30f, mB = -1e30f, lA = 0.0f, lB = 0.0f;

    stage(0, 0); CP_COMMIT();

    for (int t = 0; t < NTILE; t++) {
        if (t + 1 < NTILE) { stage(t + 1, (t + 1) & 1); CP_COMMIT(); CP_WAIT(1); }
        else               { CP_WAIT(0); }
        __syncthreads();

        const __half* Kh = smb + (t & 1) * STAGEB;
        const __half* Kl = Kh + ARRB;
        const __half* Vh = Kh + 2 * ARRB;

        // ---- S = Thi*Khi + Tlo*Khi + Thi*Klo ----
        float S[8][4];
        #pragma unroll
        for (int n = 0; n < 8; n++)
            #pragma unroll
            for (int e = 0; e < 4; e++) S[n][e] = 0.0f;
        #pragma unroll
        for (int n = 0; n < 8; n++) {
            #pragma unroll
            for (int kc = 0; kc < 4; kc++) {
                const __half* kp = Kh + (n * 8 + qr) * STRIDE + 16 * kc + qk;
                uint32_t b0 = *(const uint32_t*)kp;
                uint32_t b1 = *(const uint32_t*)(kp + 8);
                MMA16816(S[n], tahi[kc], b0, b1);
                MMA16816(S[n], talo[kc], b0, b1);
                const __half* kp2 = Kl + (n * 8 + qr) * STRIDE + 16 * kc + qk;
                uint32_t c0 = *(const uint32_t*)kp2;
                uint32_t c1 = *(const uint32_t*)(kp2 + 8);
                MMA16816(S[n], tahi[kc], c0, c1);
            }
        }

        // ---- online softmax (log2 domain) ----
        float rmA = -1e30f, rmB = -1e30f;
        #pragma unroll
        for (int n = 0; n < 8; n++) {
            rmA = fmaxf(rmA, fmaxf(S[n][0], S[n][1]));
            rmB = fmaxf(rmB, fmaxf(S[n][2], S[n][3]));
        }
        rmA = fmaxf(rmA, __shfl_xor_sync(0xffffffffu, rmA, 1));
        rmA = fmaxf(rmA, __shfl_xor_sync(0xffffffffu, rmA, 2));
        rmB = fmaxf(rmB, __shfl_xor_sync(0xffffffffu, rmB, 1));
        rmB = fmaxf(rmB, __shfl_xor_sync(0xffffffffu, rmB, 2));
        float mnA = fmaxf(mA, rmA), mnB = fmaxf(mB, rmB);
        float cA = ex2(mA - mnA), cB = ex2(mB - mnB);
        mA = mnA; mB = mnB;

        uint32_t pa[4][4];
        float sA = 0.0f, sB = 0.0f;
        #pragma unroll
        for (int kc2 = 0; kc2 < 4; kc2++) {
            int n0 = 2 * kc2, n1 = 2 * kc2 + 1;
            float p00 = ex2(S[n0][0] - mnA), p01 = ex2(S[n0][1] - mnA);
            float p10 = ex2(S[n0][2] - mnB), p11 = ex2(S[n0][3] - mnB);
            float p20 = ex2(S[n1][0] - mnA), p21 = ex2(S[n1][1] - mnA);
            float p30 = ex2(S[n1][2] - mnB), p31 = ex2(S[n1][3] - mnB);
            sA += (p00 + p01) + (p20 + p21);
            sB += (p10 + p11) + (p30 + p31);
            pa[kc2][0] = packh(p00, p01);
            pa[kc2][1] = packh(p10, p11);
            pa[kc2][2] = packh(p20, p21);
            pa[kc2][3] = packh(p30, p31);
        }
        lA = lA * cA + sA;
        lB = lB * cB + sB;
        #pragma unroll
        for (int n = 0; n < 8; n++) {
            U[n][0] *= cA; U[n][1] *= cA;
            U[n][2] *= cB; U[n][3] *= cB;
        }

        // ---- U += P * V (single fp16 term) ----
        #pragma unroll
        for (int n2 = 0; n2 < 8; n2++) {
            #pragma unroll
            for (int kc2 = 0; kc2 < 4; kc2++) {
                const __half* vp = Vh + (n2 * 8 + qr) * STRIDE + 16 * kc2 + qk;
                uint32_t b0 = *(const uint32_t*)vp;
                uint32_t b1 = *(const uint32_t*)(vp + 8);
                MMA16816(U[n2], pa[kc2], b0, b1);
            }
        }
        __syncthreads();
    }

    lA += __shfl_xor_sync(0xffffffffu, lA, 1);
    lA += __shfl_xor_sync(0xffffffffu, lA, 2);
    lB += __shfl_xor_sync(0xffffffffu, lB, 1);
    lB += __shfl_xor_sync(0xffffffffu, lB, 2);
    float iA = 1.0f / lA, iB = 1.0f / lB;
    float* UgA = g_U + (size_t)(qrow0 + w * 16 + qr) * (NHEAD * HARM) + h * 64;
    float* UgB = UgA + (size_t)8 * (NHEAD * HARM);
    #pragma unroll
    for (int n2 = 0; n2 < 8; n2++) {
        *(float2*)&UgA[n2 * 8 + qk] = make_float2(U[n2][0] * iA, U[n2][1] * iA);
        *(float2*)&UgB[n2 * 8 + qk] = make_float2(U[n2][2] * iB, U[n2][3] * iB);
    }
}

// ---------------- launch ----------------
extern "C" void kernel_launch(void* const* d_in, const int* in_sizes, int n_in,
                              void* d_out, int out_size)
{
    (void)in_sizes; (void)n_in; (void)out_size;
    const float* hs      = (const float*)d_in[0];
    const float* basis_q = (const float*)d_in[1];
    const float* phase_q = (const float*)d_in[2];
    const float* amp_q   = (const float*)d_in[3];
    const float* basis_k = (const float*)d_in[4];
    const float* phase_k = (const float*)d_in[5];
    const float* amp_k   = (const float*)d_in[6];
    const float* basis_v = (const float*)d_in[7];
    const float* phase_v = (const float*)d_in[8];
    const float* amp_v   = (const float*)d_in[9];
    const float* basis_o = (const float*)d_in[10];
    const float* phase_o = (const float*)d_in[11];
    const float* amp_o   = (const float*)d_in[12];
    float* out = (float*)d_out;

    cudaFuncSetAttribute(k_attn7, cudaFuncAttributeMaxDynamicSharedMemorySize, ATTN_SMEM);
    cudaFuncSetAttribute(k_res_mma, cudaFuncAttributeMaxDynamicSharedMemorySize, RES_SMEM);

    k_compute_w<<<(HID * HARM + 255) / 256, 256>>>(phase_q, amp_q, phase_k, amp_k,
                                                   phase_v, amp_v, phase_o, amp_o);
    k_prep<<<dim3(NHEAD, 2), 256>>>(basis_o);
    k_splitX<<<(NROWS * HID / 4 + 255) / 256, 256>>>(hs);
    k_splitB<<<dim3((HARM * HID / 4 + 255) / 256, 3), 256>>>(basis_q, basis_k, basis_v);
    k_res_mma<<<dim3(NROWS / 64, 3), 256, RES_SMEM>>>();
    k_splitT<<<dim3(NROWS / 64, NHEAD), 256>>>();
    k_attn7<<<dim3(SEQ / 128, NHEAD, BATCH), 256, ATTN_SMEM>>>();
    k_resO_part<<<dim3(NROWS / 64, 4), 256>>>();
    k_resO_combine<<<(NROWS * HARM / 4 + 255) / 256, 256>>>();
    k_out<<<dim3(NROWS / 128, HID / 64), 256>>>(out);
}

// round 16
// speedup vs baseline: 5.7970x; 1.2128x over previous
#include <cuda_runtime.h>
#include <cuda_fp16.h>
#include <cstdint>
#include <stdint.h>
#include <math.h>

#define HID   2048
#define NHEAD 16
#define DH    128
#define HARM  64
#define BATCH 2
#define SEQ   2048
#define NROWS (BATCH*SEQ)   // 4096
#define NTILE (SEQ/64)      // 32

typedef unsigned long long ull;

// ---------------- device scratch ----------------
__device__ float g_w[4][HID*HARM];
__device__ float g_res[NROWS*HARM];        // Rq fp32
__device__ float g_Mt[NHEAD*HARM*HARM];    // Mt[h][c][a] = log2e*scale*M[a][c]
__device__ float g_mbar[NHEAD];            // mean of Mt entries per head
__device__ float g_Nt[HARM*NHEAD*HARM];
__device__ float g_U[NROWS*NHEAD*HARM];
__device__ float g_reso[NROWS*HARM];
__device__ float g_resoP[4][NROWS*HARM];
__device__ float g_sq[NROWS];              // row sums of Rq (fp32)
__device__ float g_sigk[NROWS];            // row sums of Rk (fp32, pre-quantization)
// fp16 operands
__device__ __half g_Xhi[(size_t)NROWS*HID];
__device__ __half g_Xlo[(size_t)NROWS*HID];
__device__ __half g_Bhi[3][HARM*HID];
__device__ __half g_Blo[3][HARM*HID];
__device__ __half g_Td[(size_t)NHEAD*NROWS*HARM];   // deltaT [h][row][c]
__device__ __half g_Kd[NROWS*HARM];                 // K fp16 [row][a]
__device__ __half g_VT[(size_t)HARM*NROWS];         // [c][row]

// ---------------- helpers ----------------
__device__ __forceinline__ ull ffma2(ull a, ull b, ull c) {
    ull d; asm("fma.rn.f32x2 %0, %1, %2, %3;" : "=l"(d) : "l"(a), "l"(b), "l"(c)); return d;
}
__device__ __forceinline__ ull dup2(float v) {
    ull r; asm("mov.b64 %0, {%1, %2};" : "=l"(r) : "f"(v), "f"(v)); return r;
}
__device__ __forceinline__ float2 unpack2(ull v) {
    float2 f; asm("mov.b64 {%0, %1}, %2;" : "=f"(f.x), "=f"(f.y) : "l"(v)); return f;
}
__device__ __forceinline__ float ex2(float x) {
    float y; asm("ex2.approx.ftz.f32 %0, %1;" : "=f"(y) : "f"(x)); return y;
}
__device__ __forceinline__ unsigned hbits(__half h) {
    return (unsigned)*reinterpret_cast<unsigned short*>(&h);
}
__device__ __forceinline__ uint32_t packh(float x, float y) {
    return hbits(__float2half(x)) | (hbits(__float2half(y)) << 16);
}
__device__ __forceinline__ uint32_t packhres(float x, float y) {
    __half hx = __float2half(x), hy = __float2half(y);
    return hbits(__float2half(x - __half2float(hx))) |
           (hbits(__float2half(y - __half2float(hy))) << 16);
}
__device__ __forceinline__ uint32_t s2u(const void* p) {
    uint32_t a; asm("{ .reg .u64 t; cvta.to.shared.u64 t, %1; cvt.u32.u64 %0, t; }" : "=r"(a) : "l"(p)); return a;
}

#define MMA16816(D, A, b0_, b1_) \
    asm volatile("mma.sync.aligned.m16n8k16.row.col.f32.f16.f16.f32 " \
        "{%0,%1,%2,%3}, {%4,%5,%6,%7}, {%8,%9}, {%0,%1,%2,%3};" \
        : "+f"((D)[0]), "+f"((D)[1]), "+f"((D)[2]), "+f"((D)[3]) \
        : "r"((A)[0]), "r"((A)[1]), "r"((A)[2]), "r"((A)[3]), "r"(b0_), "r"(b1_))

__device__ __forceinline__ void cpasync16(uint32_t sdst, const void* gsrc) {
    asm volatile("cp.async.cg.shared.global [%0], [%1], 16;" :: "r"(sdst), "l"(gsrc) : "memory");
}
#define CP_COMMIT() asm volatile("cp.async.commit_group;" ::: "memory")
#define CP_WAIT(n)  asm volatile("cp.async.wait_group %0;" :: "n"(n) : "memory")

// ---------------- w = amp * cos(phase) ----------------
__global__ void k_compute_w(const float* __restrict__ pq, const float* __restrict__ aq,
                            const float* __restrict__ pk, const float* __restrict__ ak,
                            const float* __restrict__ pv, const float* __restrict__ av,
                            const float* __restrict__ po, const float* __restrict__ ao)
{
    int i = blockIdx.x * blockDim.x + threadIdx.x;
    if (i < HID * HARM) {
        g_w[0][i] = aq[i] * cosf(pq[i]);
        g_w[1][i] = ak[i] * cosf(pk[i]);
        g_w[2][i] = av[i] * cosf(pv[i]);
        g_w[3][i] = ao[i] * cosf(po[i]);
    }
}

// ---------------- prep: Mt (+mbar reduce) and Nt ----------------
__global__ __launch_bounds__(256) void k_prep(const float* __restrict__ basis_o)
{
    __shared__ float As[32][65];
    __shared__ float Bs[32][65];
    __shared__ float red[256];
    const int h = blockIdx.x;
    const int z = blockIdx.y;
    const int tid = threadIdx.x;
    const int tx = tid & 15;
    const int ty = tid >> 4;

    float acc[4][4] = {};
    for (int dc = 0; dc < 128; dc += 32) {
        __syncthreads();
        if (z == 0) {
            int d = tid >> 3, a0 = (tid & 7) * 8;
            #pragma unroll
            for (int j = 0; j < 8; j++) {
                As[d][a0 + j] = g_w[0][(h * 128 + dc + d) * 64 + a0 + j];
                Bs[d][a0 + j] = g_w[1][(h * 128 + dc + d) * 64 + a0 + j];
            }
        } else {
            int d = tid >> 3, a0 = (tid & 7) * 8;
            #pragma unroll
            for (int j = 0; j < 8; j++)
                As[d][a0 + j] = g_w[2][(h * 128 + dc + d) * 64 + a0 + j];
            int c = tid >> 2, d0 = (tid & 3) * 8;
            #pragma unroll
            for (int j = 0; j < 8; j++)
                Bs[d0 + j][c] = basis_o[c * 2048 + h * 128 + dc + d0 + j];
        }
        __syncthreads();
        #pragma unroll 8
        for (int d = 0; d < 32; d++) {
            float a[4], b[4];
            #pragma unroll
            for (int i = 0; i < 4; i++) a[i] = As[d][ty * 4 + i];
            #pragma unroll
            for (int j = 0; j < 4; j++) b[j] = Bs[d][tx * 4 + j];
            #pragma unroll
            for (int i = 0; i < 4; i++)
                #pragma unroll
                for (int j = 0; j < 4; j++)
                    acc[i][j] += a[i] * b[j];
        }
    }
    const float scale = 0.08838834764831845f * 1.4426950408889634f;
    if (z == 0) {
        float s = 0.0f;
        #pragma unroll
        for (int i = 0; i < 4; i++)
            #pragma unroll
            for (int j = 0; j < 4; j++) {
                g_Mt[h * 4096 + (tx * 4 + j) * 64 + (ty * 4 + i)] = acc[i][j] * scale;
                s += acc[i][j];
            }
        red[tid] = s;
        __syncthreads();
        for (int st = 128; st > 0; st >>= 1) {
            if (tid < st) red[tid] += red[tid + st];
            __syncthreads();
        }
        if (tid == 0) g_mbar[h] = red[0] * scale / 4096.0f;
    } else {
        #pragma unroll
        for (int i = 0; i < 4; i++)
            #pragma unroll
            for (int j = 0; j < 4; j++)
                g_Nt[(tx * 4 + j) * 1024 + h * 64 + ty * 4 + i] = acc[i][j];
    }
}

// ---------------- input splits (fp16) ----------------
__global__ void k_splitX(const float* __restrict__ hs)
{
    int i = blockIdx.x * blockDim.x + threadIdx.x;
    if (i < NROWS * HID / 4) {
        float4 v = ((const float4*)hs)[i];
        uint2 hh, ll;
        hh.x = packh(v.x, v.y);   hh.y = packh(v.z, v.w);
        ll.x = packhres(v.x, v.y); ll.y = packhres(v.z, v.w);
        *(uint2*)&g_Xhi[(size_t)i * 4] = hh;
        *(uint2*)&g_Xlo[(size_t)i * 4] = ll;
    }
}
__global__ void k_splitB(const float* __restrict__ b0,
                         const float* __restrict__ b1,
                         const float* __restrict__ b2)
{
    int i = blockIdx.x * blockDim.x + threadIdx.x;
    int z = blockIdx.y;
    const float* B = (z == 0) ? b0 : (z == 1) ? b1 : b2;
    if (i < HARM * HID / 4) {
        float4 v = ((const float4*)B)[i];
        uint2 hh, ll;
        hh.x = packh(v.x, v.y);   hh.y = packh(v.z, v.w);
        ll.x = packhres(v.x, v.y); ll.y = packhres(v.z, v.w);
        *(uint2*)&g_Bhi[z][i * 4] = hh;
        *(uint2*)&g_Blo[z][i * 4] = ll;
    }
}

// ---------------- resonance via mma.sync (fp16): res_z = X @ basis_z^T ----------------
// z=0 -> g_res fp32 (Rq); z=1 -> g_Kd fp16 + g_sigk fp32; z=2 -> g_VT fp16 (transposed).
#define RSTRIDE 72
#define RARR (64*RSTRIDE)
#define RSTAGE (4*RARR)
#define RES_SMEM (2*RSTAGE*2)

__global__ __launch_bounds__(256) void k_res_mma()
{
    extern __shared__ __half rsm[];
    const int tid = threadIdx.x;
    const int lane = tid & 31, w = tid >> 5;
    const int rt = blockIdx.x, z = blockIdx.y;
    const int r0 = rt * 64;
    const int qr = lane >> 2, qk = (lane & 3) * 2;
    const int wr = (w & 3) * 16;
    const int wn = (w >> 2) * 32;

    const __half* Bh = g_Bhi[z];
    const __half* Bl = g_Blo[z];

    const int sarr = tid >> 6, srow = tid & 63;
    const uint32_t sbase[2] = { s2u(rsm + 0 * RSTAGE + sarr * RARR + srow * RSTRIDE),
                                s2u(rsm + 1 * RSTAGE + sarr * RARR + srow * RSTRIDE) };
    auto stage = [&](int kc64, int s) {
        size_t k0 = (size_t)kc64 * 64;
        const char* src;
        if (sarr == 0)      src = (const char*)(g_Xhi + (size_t)(r0 + srow) * HID + k0);
        else if (sarr == 1) src = (const char*)(g_Xlo + (size_t)(r0 + srow) * HID + k0);
        else if (sarr == 2) src = (const char*)(Bh + (size_t)srow * HID + k0);
        else                src = (const char*)(Bl + (size_t)srow * HID + k0);
        uint32_t d = sbase[s];
        #pragma unroll
        for (int j = 0; j < 8; j++)
            cpasync16(d + j * 16, src + j * 16);
    };

    float acc[4][4] = {};
    stage(0, 0); CP_COMMIT();
    for (int kc64 = 0; kc64 < HID / 64; kc64++) {
        if (kc64 + 1 < HID / 64) { stage(kc64 + 1, (kc64 + 1) & 1); CP_COMMIT(); CP_WAIT(1); }
        else                     { CP_WAIT(0); }
        __syncthreads();
        const __half* Xh = rsm + (kc64 & 1) * RSTAGE;
        const __half* Xl = Xh + RARR;
        const __half* Bsh = Xh + 2 * RARR;
        const __half* Bsl = Xh + 3 * RARR;
        #pragma unroll
        for (int kc = 0; kc < 4; kc++) {
            uint32_t ahi[4], alo[4];
            const __half* xp = Xh + (wr + qr) * RSTRIDE + 16 * kc + qk;
            const __half* xp2 = Xl + (wr + qr) * RSTRIDE + 16 * kc + qk;
            ahi[0] = *(const uint32_t*)xp;
            ahi[1] = *(const uint32_t*)(xp + 8 * RSTRIDE);
            ahi[2] = *(const uint32_t*)(xp + 8);
            ahi[3] = *(const uint32_t*)(xp + 8 * RSTRIDE + 8);
            alo[0] = *(const uint32_t*)xp2;
            alo[1] = *(const uint32_t*)(xp2 + 8 * RSTRIDE);
            alo[2] = *(const uint32_t*)(xp2 + 8);
            alo[3] = *(const uint32_t*)(xp2 + 8 * RSTRIDE + 8);
            #pragma unroll
            for (int n = 0; n < 4; n++) {
                const __half* bp = Bsh + (wn + n * 8 + qr) * RSTRIDE + 16 * kc + qk;
                uint32_t b0 = *(const uint32_t*)bp;
                uint32_t b1 = *(const uint32_t*)(bp + 8);
                MMA16816(acc[n], ahi, b0, b1);
                MMA16816(acc[n], alo, b0, b1);
                const __half* bp2 = Bsl + (wn + n * 8 + qr) * RSTRIDE + 16 * kc + qk;
                uint32_t c0 = *(const uint32_t*)bp2;
                uint32_t c1 = *(const uint32_t*)(bp2 + 8);
                MMA16816(acc[n], ahi, c0, c1);
            }
        }
        __syncthreads();
    }

    if (z == 0) {
        float* C  = g_res + (size_t)(r0 + wr + qr) * 64 + wn;
        float* C2 = C + (size_t)8 * 64;
        #pragma unroll
        for (int n = 0; n < 4; n++) {
            *(float2*)&C[n * 8 + qk]  = make_float2(acc[n][0], acc[n][1]);
            *(float2*)&C2[n * 8 + qk] = make_float2(acc[n][2], acc[n][3]);
        }
    } else if (z == 1) {
        // route through fp32 smem: emit fp16 K and EXACT fp32 row sums (sigk)
        float* F = (float*)rsm;   // [64][68] fp32, in stage-0 region (last tile read stage 1)
        #pragma unroll
        for (int n = 0; n < 4; n++) {
            F[(wr + qr) * 68 + wn + n * 8 + qk]         = acc[n][0];
            F[(wr + qr) * 68 + wn + n * 8 + qk + 1]     = acc[n][1];
            F[(wr + qr + 8) * 68 + wn + n * 8 + qk]     = acc[n][2];
            F[(wr + qr + 8) * 68 + wn + n * 8 + qk + 1] = acc[n][3];
        }
        __syncthreads();
        {
            int r = tid >> 2, c0 = (tid & 3) * 16;
            #pragma unroll
            for (int cc = 0; cc < 16; cc++)
                g_Kd[(r0 + r) * 64 + c0 + cc] = __float2half(F[r * 68 + c0 + cc]);
            if (tid < 64) {
                float s = 0.0f;
                #pragma unroll 8
                for (int c = 0; c < 64; c++) s += F[tid * 68 + c];
                g_sigk[r0 + tid] = s;
            }
        }
    } else {
        float* F = (float*)rsm;
        #pragma unroll
        for (int n = 0; n < 4; n++) {
            F[(wr + qr) * 68 + wn + n * 8 + qk]         = acc[n][0];
            F[(wr + qr) * 68 + wn + n * 8 + qk + 1]     = acc[n][1];
            F[(wr + qr + 8) * 68 + wn + n * 8 + qk]     = acc[n][2];
            F[(wr + qr + 8) * 68 + wn + n * 8 + qk + 1] = acc[n][3];
        }
        __syncthreads();
        int r = tid & 63;
        int c0 = (tid >> 6) * 16;
        #pragma unroll
        for (int cc = 0; cc < 16; cc++) {
            int c = c0 + cc;
            g_VT[(size_t)c * NROWS + r0 + r] = __float2half(F[r * 68 + c]);
        }
    }
}

// ---------------- Rq row sums ----------------
__global__ void k_rowsum()
{
    int row = blockIdx.x * blockDim.x + threadIdx.x;
    if (row < NROWS) {
        const float4* p = (const float4*)(g_res + (size_t)row * 64);
        float s = 0.0f;
        #pragma unroll
        for (int i = 0; i < 16; i++) {
            float4 v = p[i];
            s += (v.x + v.y) + (v.z + v.w);
        }
        g_sq[row] = s;
    }
}

// ---------------- 64x64-tile f32x2 GEMM partial (resO) ----------------
__device__ __forceinline__ void gemm64F2(const float* __restrict__ A,
                                         const float* __restrict__ B,
                                         float* __restrict__ C,
                                         int Klen, int lda, int ldb)
{
    __shared__ float As[64 * 36];
    __shared__ float BsT[32 * 68];
    const int tid = threadIdx.x;
    const int tx = tid & 15;
    const int ty = tid >> 4;
    const float* Ab = A + (size_t)blockIdx.x * 64 * lda;

    ull acc[4][2] = {};
    for (int k0 = 0; k0 < Klen; k0 += 32) {
        __syncthreads();
        {
            int c = (tid & 7) * 4;
            int r = tid >> 3;
            *(float4*)&As[r * 36 + c]        = *(const float4*)&Ab[(size_t)r * lda + k0 + c];
            *(float4*)&As[(r + 32) * 36 + c] = *(const float4*)&Ab[(size_t)(r + 32) * lda + k0 + c];
            int n = tid >> 2, kk0 = (tid & 3) * 8;
            #pragma unroll
            for (int j = 0; j < 8; j++)
                BsT[(kk0 + j) * 68 + n] = B[(size_t)n * ldb + k0 + kk0 + j];
        }
        __syncthreads();
        #pragma unroll 4
        for (int kk = 0; kk < 32; kk++) {
            float a[4];
            #pragma unroll
            for (int i = 0; i < 4; i++) a[i] = As[(ty * 4 + i) * 36 + kk];
            ull b0 = *(const ull*)&BsT[kk * 68 + tx * 4];
            ull b1 = *(const ull*)&BsT[kk * 68 + tx * 4 + 2];
            #pragma unroll
            for (int i = 0; i < 4; i++) {
                ull ad = dup2(a[i]);
                acc[i][0] = ffma2(ad, b0, acc[i][0]);
                acc[i][1] = ffma2(ad, b1, acc[i][1]);
            }
        }
    }
    #pragma unroll
    for (int i = 0; i < 4; i++) {
        size_t row = blockIdx.x * 64 + ty * 4 + i;
        *(float2*)&C[row * 64 + tx * 4]     = unpack2(acc[i][0]);
        *(float2*)&C[row * 64 + tx * 4 + 2] = unpack2(acc[i][1]);
    }
}

__global__ __launch_bounds__(256) void k_resO_part()
{
    const int ks = blockIdx.y;
    gemm64F2(g_U + ks * 256, g_Nt + ks * 256, g_resoP[ks], 256, NHEAD * HARM, NHEAD * HARM);
}
__global__ void k_resO_combine()
{
    int i = blockIdx.x * blockDim.x + threadIdx.x;
    const int N4 = NROWS * HARM / 4;
    if (i < N4) {
        float4 a = ((const float4*)g_resoP[0])[i];
        float4 b = ((const float4*)g_resoP[1])[i];
        float4 c = ((const float4*)g_resoP[2])[i];
        float4 d = ((const float4*)g_resoP[3])[i];
        ((float4*)g_reso)[i] = make_float4(a.x + b.x + c.x + d.x, a.y + b.y + c.y + d.y,
                                           a.z + b.z + c.z + d.z, a.w + b.w + c.w + d.w);
    }
}

// ---------------- 128x64-tile f32x2 GEMM (final output) ----------------
__device__ __forceinline__ void gemmF2(const float* __restrict__ A,
                                       const float* __restrict__ B,
                                       float* __restrict__ C,
                                       int K, int lda, int ldb, int ldc)
{
    __shared__ float As[128 * 36];
    __shared__ float BsT[32 * 68];
    const int tid = threadIdx.x;
    const int tx = tid & 15;
    const int ty = tid >> 4;
    const float* Ab = A + (size_t)blockIdx.x * 128 * lda;
    const float* Bb = B + (size_t)blockIdx.y * 64 * ldb;

    ull acc[8][2] = {};
    for (int k0 = 0; k0 < K; k0 += 32) {
        __syncthreads();
        {
            int c = (tid & 7) * 4;
            #pragma unroll
            for (int p = 0; p < 4; p++) {
                int r = (tid >> 3) + p * 32;
                *(float4*)&As[r * 36 + c] = *(const float4*)&Ab[(size_t)r * lda + k0 + c];
            }
            int n = tid >> 2, kk0 = (tid & 3) * 8;
            #pragma unroll
            for (int j = 0; j < 8; j++)
                BsT[(kk0 + j) * 68 + n] = Bb[(size_t)n * ldb + k0 + kk0 + j];
        }
        __syncthreads();
        #pragma unroll 4
        for (int kk = 0; kk < 32; kk++) {
            float a[8];
            #pragma unroll
            for (int i = 0; i < 8; i++) a[i] = As[(ty * 8 + i) * 36 + kk];
            ull b0 = *(const ull*)&BsT[kk * 68 + tx * 4];
            ull b1 = *(const ull*)&BsT[kk * 68 + tx * 4 + 2];
            #pragma unroll
            for (int i = 0; i < 8; i++) {
                ull ad = dup2(a[i]);
                acc[i][0] = ffma2(ad, b0, acc[i][0]);
                acc[i][1] = ffma2(ad, b1, acc[i][1]);
            }
        }
    }
    #pragma unroll
    for (int i = 0; i < 8; i++) {
        size_t row = blockIdx.x * 128 + ty * 8 + i;
        *(float2*)&C[row * ldc + blockIdx.y * 64 + tx * 4]     = unpack2(acc[i][0]);
        *(float2*)&C[row * ldc + blockIdx.y * 64 + tx * 4 + 2] = unpack2(acc[i][1]);
    }
}

__global__ __launch_bounds__(256) void k_out(float* __restrict__ out)
{
    gemmF2(g_reso, g_w[3], out, HARM, HARM, HARM, HID);
}

// ---------------- T split prep: deltaT = Rq@Mt - mbar*sq (fp16 out) ----------------
__global__ __launch_bounds__(256) void k_splitT()
{
    __shared__ float As[64 * 68];
    __shared__ float Bs[64 * 68];
    const int bx = blockIdx.x, h = blockIdx.y;
    const int tid = threadIdx.x;
    const int tx = tid & 15;
    const int ty = tid >> 4;
    {
        int r = tid >> 2, a0 = (tid & 3) * 16;
        const float* Aq = g_res + (size_t)(bx * 64) * 64;
        const float* Bm = g_Mt + h * 4096;
        #pragma unroll
        for (int q = 0; q < 4; q++) {
            *(float4*)&As[r * 68 + a0 + q * 4] = *(const float4*)&Aq[r * 64 + a0 + q * 4];
            *(float4*)&Bs[r * 68 + a0 + q * 4] = *(const float4*)&Bm[r * 64 + a0 + q * 4];
        }
    }
    float mb = g_mbar[h];
    float sqv[4];
    #pragma unroll
    for (int i = 0; i < 4; i++) sqv[i] = g_sq[bx * 64 + ty * 4 + i];
    __syncthreads();
    float acc[4][4] = {};
    #pragma unroll 8
    for (int a = 0; a < 64; a++) {
        float av[4], bv[4];
        #pragma unroll
        for (int i = 0; i < 4; i++) av[i] = As[(ty * 4 + i) * 68 + a];
        #pragma unroll
        for (int j = 0; j < 4; j++) bv[j] = Bs[(tx * 4 + j) * 68 + a];
        #pragma unroll
        for (int i = 0; i < 4; i++)
            #pragma unroll
            for (int j = 0; j < 4; j++)
                acc[i][j] += av[i] * bv[j];
    }
    #pragma unroll
    for (int i = 0; i < 4; i++)
        #pragma unroll
        for (int j = 0; j < 4; j++) {
            size_t o = (size_t)h * NROWS * 64 + (size_t)(bx * 64 + ty * 4 + i) * 64 + tx * 4 + j;
            g_Td[o] = __float2half(acc[i][j] - mb * sqv[i]);
        }
}

// ---------------- FA2 attention: rank-1 + single-term deltaS, fp16 ----------------
// per-stage smem: Kd [64][72] fp16, VT [64][72] fp16, sigk [64] fp32
#define STRIDE 72
#define ARRB   (64 * STRIDE)                 // halves per array
#define STG_H  (2 * ARRB + 128)              // halves per stage (sigk = 64 floats = 128 halves)
#define ATTN_SMEM (2 * STG_H * 2)            // 37376 bytes

__global__ __launch_bounds__(256, 1) void k_attn8()
{
    extern __shared__ __half smb[];
    const int tid = threadIdx.x;
    const int lane = tid & 31, w = tid >> 5;
    const int qt = blockIdx.x, h = blockIdx.y, b = blockIdx.z;
    const int qrow0 = b * SEQ + qt * 128;
    const size_t bSEQ = (size_t)b * SEQ;
    const int qr = lane >> 2;
    const int qk = (lane & 3) * 2;

    // T (delta) fragments, single fp16
    uint32_t ta[4][4];
    {
        const __half* Th = g_Td + ((size_t)h * NROWS + qrow0 + w * 16 + qr) * 64;
        #pragma unroll
        for (int kc = 0; kc < 4; kc++) {
            ta[kc][0] = *(const uint32_t*)&Th[16 * kc + qk];
            ta[kc][1] = *(const uint32_t*)&Th[8 * 64 + 16 * kc + qk];
            ta[kc][2] = *(const uint32_t*)&Th[16 * kc + qk + 8];
            ta[kc][3] = *(const uint32_t*)&Th[8 * 64 + 16 * kc + qk + 8];
        }
    }
    const float mb = g_mbar[h];
    const float tqA = mb * g_sq[qrow0 + w * 16 + qr];
    const float tqB = mb * g_sq[qrow0 + w * 16 + qr + 8];

    const int sarr = tid >> 6;        // 0: Kd, 1: VT, 2: sigk (srow<16), 3: idle
    const int srow = tid & 63;
    uint32_t sdstBase[2];
    #pragma unroll
    for (int s = 0; s < 2; s++) {
        if (sarr == 0)      sdstBase[s] = s2u(smb + s * STG_H + srow * STRIDE);
        else if (sarr == 1) sdstBase[s] = s2u(smb + s * STG_H + ARRB + srow * STRIDE);
        else                sdstBase[s] = s2u(smb + s * STG_H + 2 * ARRB) + srow * 16;
    }
    auto stage = [&](int t, int s) {
        if (sarr == 0)
            #pragma unroll
            for (int j = 0; j < 8; j++)
                cpasync16(sdstBase[s] + j * 16,
                          (const char*)(g_Kd + (bSEQ + t * 64 + srow) * 64) + j * 16);
        else if (sarr == 1)
            #pragma unroll
            for (int j = 0; j < 8; j++)
                cpasync16(sdstBase[s] + j * 16,
                          (const char*)(g_VT + (size_t)srow * NROWS + bSEQ + t * 64) + j * 16);
        else if (sarr == 2 && srow < 16)
            cpasync16(sdstBase[s], (const char*)(g_sigk + bSEQ + t * 64) + srow * 16);
    };

    float U[8][4];
    #pragma unroll
    for (int n = 0; n < 8; n++)
        #pragma unroll
        for (int e = 0; e < 4; e++) U[n][e] = 0.0f;
    float mA = -1e30f, mB = -1e30f, lA = 0.0f, lB = 0.0f;

    stage(0, 0); CP_COMMIT();

    for (int t = 0; t < NTILE; t++) {
        if (t + 1 < NTILE) { stage(t + 1, (t + 1) & 1); CP_COMMIT(); CP_WAIT(1); }
        else               { CP_WAIT(0); }
        __syncthreads();

        const __half* Kd = smb + (t & 1) * STG_H;
        const __half* Vh = Kd + ARRB;
        const float* sig = (const float*)(Kd + 2 * ARRB);

        // ---- S = rank1 + deltaT * K (single fp16 MMA term) ----
        float S[8][4];
        #pragma unroll
        for (int n = 0; n < 8; n++)
            #pragma unroll
            for (int e = 0; e < 4; e++) S[n][e] = 0.0f;
        #pragma unroll
        for (int n = 0; n < 8; n++) {
            #pragma unroll
            for (int kc = 0; kc < 4; kc++) {
                const __half* kp = Kd + (n * 8 + qr) * STRIDE + 16 * kc + qk;
                uint32_t b0 = *(const uint32_t*)kp;
                uint32_t b1 = *(const uint32_t*)(kp + 8);
                MMA16816(S[n], ta[kc], b0, b1);
            }
            float2 sg = *(const float2*)&sig[n * 8 + qk];
            S[n][0] += tqA * sg.x;  S[n][1] += tqA * sg.y;
            S[n][2] += tqB * sg.x;  S[n][3] += tqB * sg.y;
        }

        // ---- online softmax (log2 domain) ----
        float rmA = -1e30f, rmB = -1e30f;
        #pragma unroll
        for (int n = 0; n < 8; n++) {
            rmA = fmaxf(rmA, fmaxf(S[n][0], S[n][1]));
            rmB = fmaxf(rmB, fmaxf(S[n][2], S[n][3]));
        }
        rmA = fmaxf(rmA, __shfl_xor_sync(0xffffffffu, rmA, 1));
        rmA = fmaxf(rmA, __shfl_xor_sync(0xffffffffu, rmA, 2));
        rmB = fmaxf(rmB, __shfl_xor_sync(0xffffffffu, rmB, 1));
        rmB = fmaxf(rmB, __shfl_xor_sync(0xffffffffu, rmB, 2));
        float mnA = fmaxf(mA, rmA), mnB = fmaxf(mB, rmB);
        float cA = ex2(mA - mnA), cB = ex2(mB - mnB);
        mA = mnA; mB = mnB;

        uint32_t pa[4][4];
        float sA = 0.0f, sB = 0.0f;
        #pragma unroll
        for (int kc2 = 0; kc2 < 4; kc2++) {
            int n0 = 2 * kc2, n1 = 2 * kc2 + 1;
            float p00 = ex2(S[n0][0] - mnA), p01 = ex2(S[n0][1] - mnA);
            float p10 = ex2(S[n0][2] - mnB), p11 = ex2(S[n0][3] - mnB);
            float p20 = ex2(S[n1][0] - mnA), p21 = ex2(S[n1][1] - mnA);
            float p30 = ex2(S[n1][2] - mnB), p31 = ex2(S[n1][3] - mnB);
            sA += (p00 + p01) + (p20 + p21);
            sB += (p10 + p11) + (p30 + p31);
            pa[kc2][0] = packh(p00, p01);
            pa[kc2][1] = packh(p10, p11);
            pa[kc2][2] = packh(p20, p21);
            pa[kc2][3] = packh(p30, p31);
        }
        lA = lA * cA + sA;
        lB = lB * cB + sB;
        #pragma unroll
        for (int n = 0; n < 8; n++) {
            U[n][0] *= cA; U[n][1] *= cA;
            U[n][2] *= cB; U[n][3] *= cB;
        }

        // ---- U += P * V ----
        #pragma unroll
        for (int n2 = 0; n2 < 8; n2++) {
            #pragma unroll
            for (int kc2 = 0; kc2 < 4; kc2++) {
                const __half* vp = Vh + (n2 * 8 + qr) * STRIDE + 16 * kc2 + qk;
                uint32_t b0 = *(const uint32_t*)vp;
                uint32_t b1 = *(const uint32_t*)(vp + 8);
                MMA16816(U[n2], pa[kc2], b0, b1);
            }
        }
        __syncthreads();
    }

    lA += __shfl_xor_sync(0xffffffffu, lA, 1);
    lA += __shfl_xor_sync(0xffffffffu, lA, 2);
    lB += __shfl_xor_sync(0xffffffffu, lB, 1);
    lB += __shfl_xor_sync(0xffffffffu, lB, 2);
    float iA = 1.0f / lA, iB = 1.0f / lB;
    float* UgA = g_U + (size_t)(qrow0 + w * 16 + qr) * (NHEAD * HARM) + h * 64;
    float* UgB = UgA + (size_t)8 * (NHEAD * HARM);
    #pragma unroll
    for (int n2 = 0; n2 < 8; n2++) {
        *(float2*)&UgA[n2 * 8 + qk] = make_float2(U[n2][0] * iA, U[n2][1] * iA);
        *(float2*)&UgB[n2 * 8 + qk] = make_float2(U[n2][2] * iB, U[n2][3] * iB);
    }
}

// ---------------- launch ----------------
extern "C" void kernel_launch(void* const* d_in, const int* in_sizes, int n_in,
                              void* d_out, int out_size)
{
    (void)in_sizes; (void)n_in; (void)out_size;
    const float* hs      = (const float*)d_in[0];
    const float* basis_q = (const float*)d_in[1];
    const float* phase_q = (const float*)d_in[2];
    const float* amp_q   = (const float*)d_in[3];
    const float* basis_k = (const float*)d_in[4];
    const float* phase_k = (const float*)d_in[5];
    const float* amp_k   = (const float*)d_in[6];
    const float* basis_v = (const float*)d_in[7];
    const float* phase_v = (const float*)d_in[8];
    const float* amp_v   = (const float*)d_in[9];
    const float* basis_o = (const float*)d_in[10];
    const float* phase_o = (const float*)d_in[11];
    const float* amp_o   = (const float*)d_in[12];
    float* out = (float*)d_out;

    cudaFuncSetAttribute(k_attn8, cudaFuncAttributeMaxDynamicSharedMemorySize, ATTN_SMEM);
    cudaFuncSetAttribute(k_res_mma, cudaFuncAttributeMaxDynamicSharedMemorySize, RES_SMEM);

    k_compute_w<<<(HID * HARM + 255) / 256, 256>>>(phase_q, amp_q, phase_k, amp_k,
                                                   phase_v, amp_v, phase_o, amp_o);
    k_prep<<<dim3(NHEAD, 2), 256>>>(basis_o);
    k_splitX<<<(NROWS * HID / 4 + 255) / 256, 256>>>(hs);
    k_splitB<<<dim3((HARM * HID / 4 + 255) / 256, 3), 256>>>(basis_q, basis_k, basis_v);
    k_res_mma<<<dim3(NROWS / 64, 3), 256, RES_SMEM>>>();
    k_rowsum<<<(NROWS + 255) / 256, 256>>>();
    k_splitT<<<dim3(NROWS / 64, NHEAD), 256>>>();
    k_attn8<<<dim3(SEQ / 128, NHEAD, BATCH), 256, ATTN_SMEM>>>();
    k_resO_part<<<dim3(NROWS / 64, 4), 256>>>();
    k_resO_combine<<<(NROWS * HARM / 4 + 255) / 256, 256>>>();
    k_out<<<dim3(NROWS / 128, HID / 64), 256>>>(out);
}